// round 2
// baseline (speedup 1.0000x reference)
#include <cuda_runtime.h>
#include <math.h>

#define BB 16
#define CC 512
#define LL 1024       // h*w
#define GG 8
#define CPG 64        // channels per group
#define NH 4
#define HD 128
#define EPS_GN 1e-5f

// Scratch (device globals: no allocation allowed)
__device__ float g_xn[(size_t)BB*CC*LL];        // 32 MB
__device__ float g_qkv[(size_t)BB*3*CC*LL];     // 96 MB
__device__ float g_att[(size_t)BB*CC*LL];       // 32 MB
__device__ float g_mean[BB*GG];
__device__ float g_rstd[BB*GG];

// ---------------------------------------------------------------------------
// GroupNorm statistics: one block per (b, group), reduce over 64*1024 elems
// ---------------------------------------------------------------------------
__global__ void __launch_bounds__(256) gn_stats_kernel(const float* __restrict__ x) {
    int bg = blockIdx.x;               // 0..127
    int b = bg / GG, g = bg % GG;
    const float4* p = (const float4*)(x + ((size_t)b*CC + (size_t)g*CPG) * LL);
    const int n4 = CPG * LL / 4;       // 16384
    float s = 0.f, sq = 0.f;
    for (int i = threadIdx.x; i < n4; i += 256) {
        float4 v = p[i];
        s  += v.x + v.y + v.z + v.w;
        sq += v.x*v.x + v.y*v.y + v.z*v.z + v.w*v.w;
    }
    __shared__ float ss[256], sq_s[256];
    ss[threadIdx.x] = s; sq_s[threadIdx.x] = sq;
    __syncthreads();
    for (int o = 128; o > 0; o >>= 1) {
        if (threadIdx.x < o) { ss[threadIdx.x] += ss[threadIdx.x+o]; sq_s[threadIdx.x] += sq_s[threadIdx.x+o]; }
        __syncthreads();
    }
    if (threadIdx.x == 0) {
        const float invN = 1.0f / (float)(CPG * LL);
        float mean = ss[0] * invN;
        float var  = sq_s[0] * invN - mean * mean;
        g_mean[bg] = mean;
        g_rstd[bg] = rsqrtf(var + EPS_GN);
    }
}

// ---------------------------------------------------------------------------
// GroupNorm apply: one block per (b, c), 1024 elems
// ---------------------------------------------------------------------------
__global__ void __launch_bounds__(256) gn_apply_kernel(const float* __restrict__ x,
                                                       const float* __restrict__ gamma,
                                                       const float* __restrict__ beta) {
    int bc = blockIdx.x;               // 0..8191
    int b = bc / CC, c = bc % CC;
    int gidx = b * GG + c / CPG;
    float rstd = g_rstd[gidx], mean = g_mean[gidx];
    float ga = gamma[c] * rstd;
    float be = beta[c] - mean * ga;
    const float4* px = (const float4*)(x + (size_t)bc * LL);
    float4* po = (float4*)(g_xn + (size_t)bc * LL);
    float4 v = px[threadIdx.x];
    v.x = v.x*ga + be; v.y = v.y*ga + be; v.z = v.z*ga + be; v.w = v.w*ga + be;
    po[threadIdx.x] = v;
}

// ---------------------------------------------------------------------------
// Batched SGEMM: out[b][m][n] = sum_k A[m][k] * Bsrc[b][k][n] + bias[m] (+res)
// Block tile 64x64, K-step 16, 256 threads, 4x4 per thread.
// grid: (N/64, M/64, BB)   N = LL fixed
// ---------------------------------------------------------------------------
template<bool RES>
__global__ void __launch_bounds__(256) gemm64_kernel(const float* __restrict__ A,
                                                     const float* __restrict__ Bsrc,
                                                     const float* __restrict__ bias,
                                                     const float* __restrict__ res,
                                                     float* __restrict__ out,
                                                     int M, int K) {
    const int N = LL;
    const int b  = blockIdx.z;
    const int m0 = blockIdx.y * 64;
    const int n0 = blockIdx.x * 64;
    const float* Bp = Bsrc + (size_t)b * K * N;
    float* Op = out + (size_t)b * M * N;

    __shared__ float As[16][64];
    __shared__ float Bs[16][64];

    const int tid = threadIdx.x;
    const int tx = tid & 15;      // n tile
    const int ty = tid >> 4;      // m tile

    float acc[4][4] = {};

    for (int k0 = 0; k0 < K; k0 += 16) {
        // Load A tile: [64 m][16 k] -> As[k][m]
        {
            int m = tid >> 2;
            int k = (tid & 3) * 4;
            float4 a4 = *(const float4*)(A + (size_t)(m0 + m) * K + k0 + k);
            As[k+0][m] = a4.x; As[k+1][m] = a4.y; As[k+2][m] = a4.z; As[k+3][m] = a4.w;
        }
        // Load B tile: [16 k][64 n]
        {
            int k = tid >> 4;
            int n = (tid & 15) * 4;
            *(float4*)&Bs[k][n] = *(const float4*)(Bp + (size_t)(k0 + k) * N + n0 + n);
        }
        __syncthreads();
        #pragma unroll
        for (int k = 0; k < 16; k++) {
            float4 af = *(const float4*)&As[k][ty*4];
            float4 bf = *(const float4*)&Bs[k][tx*4];
            float a[4] = {af.x, af.y, af.z, af.w};
            float bb[4] = {bf.x, bf.y, bf.z, bf.w};
            #pragma unroll
            for (int i = 0; i < 4; i++)
                #pragma unroll
                for (int j = 0; j < 4; j++)
                    acc[i][j] += a[i] * bb[j];
        }
        __syncthreads();
    }

    #pragma unroll
    for (int i = 0; i < 4; i++) {
        int m = m0 + ty*4 + i;
        float bv = bias[m];
        float4 o;
        o.x = acc[i][0] + bv; o.y = acc[i][1] + bv;
        o.z = acc[i][2] + bv; o.w = acc[i][3] + bv;
        size_t off = (size_t)m * N + n0 + tx*4;
        if (RES) {
            float4 r = *(const float4*)(res + (size_t)b * M * N + off);
            o.x += r.x; o.y += r.y; o.z += r.z; o.w += r.w;
        }
        *(float4*)(Op + off) = o;
    }
}

// ---------------------------------------------------------------------------
// Flash attention: one block per (b, h, q-tile of 64). 256 threads.
// Q/K/V tiles in smem, online softmax, O^T accumulated in registers.
// ---------------------------------------------------------------------------
__global__ void __launch_bounds__(256) attn_kernel() {
    const int lq0 = blockIdx.x * 64;
    const int h   = blockIdx.y;
    const int b   = blockIdx.z;
    const float scale = 0.08838834764831845f;  // 1/sqrt(128)

    extern __shared__ float sm[];
    float* Qs = sm;                    // [128][64]  Qs[d*64+l] (pre-scaled)
    float* Ks = Qs + 128*64;           // [128][64]
    float* Vs = Ks + 128*64;           // [128][64]
    float* Ps = Vs + 128*64;           // [64][64]   Ps[m*64+l]  (S^T, then P^T)
    float* row_max   = Ps + 64*64;     // [64]
    float* row_sum   = row_max + 64;   // [64]
    float* row_alpha = row_sum + 64;   // [64]
    float* part      = row_alpha + 64; // [4][64]

    const int tid = threadIdx.x;
    const int tx = tid & 15;           // l group (l0 = tx*4)
    const int ty = tid >> 4;           // 0..15

    const size_t base = ((size_t)b * 3 * CC + (size_t)h * HD) * LL;
    const float* qg = g_qkv + base;
    const float* kg = g_qkv + base + (size_t)CC * LL;
    const float* vg = g_qkv + base + (size_t)2 * CC * LL;

    // Load Q tile (scaled)
    #pragma unroll
    for (int i = 0; i < 32; i++) {
        int idx = tid + i * 256;
        int d = idx >> 6, l = idx & 63;
        Qs[idx] = qg[(size_t)d * LL + lq0 + l] * scale;
    }
    if (tid < 64) { row_max[tid] = -1e30f; row_sum[tid] = 0.f; }

    float Oacc[8][4];                  // O^T[d0+i][l0+j], d0 = ty*8, l0 = tx*4
    #pragma unroll
    for (int i = 0; i < 8; i++)
        #pragma unroll
        for (int j = 0; j < 4; j++) Oacc[i][j] = 0.f;

    for (int kt = 0; kt < 16; kt++) {
        const int lk0 = kt * 64;
        __syncthreads();   // protect Ks/Vs/Ps reuse + Q/init visibility
        #pragma unroll
        for (int i = 0; i < 32; i++) {
            int idx = tid + i * 256;
            int d = idx >> 6, m = idx & 63;
            Ks[idx] = kg[(size_t)d * LL + lk0 + m];
            Vs[idx] = vg[(size_t)d * LL + lk0 + m];
        }
        __syncthreads();

        // S^T[m][l] = sum_d K[d][m] * Qscaled[d][l]; thread tile m0=ty*4, l0=tx*4
        float acc[4][4] = {};
        #pragma unroll 8
        for (int d = 0; d < 128; d++) {
            float4 kf = *(const float4*)&Ks[d*64 + ty*4];
            float4 qf = *(const float4*)&Qs[d*64 + tx*4];
            float ka[4] = {kf.x, kf.y, kf.z, kf.w};
            float qa[4] = {qf.x, qf.y, qf.z, qf.w};
            #pragma unroll
            for (int i = 0; i < 4; i++)
                #pragma unroll
                for (int j = 0; j < 4; j++)
                    acc[i][j] += ka[i] * qa[j];
        }
        #pragma unroll
        for (int i = 0; i < 4; i++)
            *(float4*)&Ps[(ty*4 + i)*64 + tx*4] =
                make_float4(acc[i][0], acc[i][1], acc[i][2], acc[i][3]);
        __syncthreads();

        // Softmax pass 1: per-column (l) tile max; thread handles 16 m's
        {
            int l = tid & 63, q = tid >> 6;
            float mx = -1e30f;
            #pragma unroll
            for (int m = 0; m < 16; m++) mx = fmaxf(mx, Ps[(q*16 + m)*64 + l]);
            part[q*64 + l] = mx;
        }
        __syncthreads();
        if (tid < 64) {
            float mx = fmaxf(fmaxf(part[tid], part[64+tid]),
                             fmaxf(part[128+tid], part[192+tid]));
            float om = row_max[tid];
            float nm = fmaxf(om, mx);
            row_max[tid] = nm;
            row_alpha[tid] = __expf(om - nm);
        }
        __syncthreads();
        // Pass 2: exponentiate in place, partial sums
        {
            int l = tid & 63, q = tid >> 6;
            float nm = row_max[l];
            float s = 0.f;
            #pragma unroll
            for (int m = 0; m < 16; m++) {
                float p = __expf(Ps[(q*16 + m)*64 + l] - nm);
                Ps[(q*16 + m)*64 + l] = p;
                s += p;
            }
            part[q*64 + l] = s;
        }
        __syncthreads();
        if (tid < 64) {
            float s = part[tid] + part[64+tid] + part[128+tid] + part[192+tid];
            row_sum[tid] = row_sum[tid] * row_alpha[tid] + s;
        }

        // Rescale O and accumulate P*V   (row_alpha/Ps stable after pass-2 sync)
        float al[4];
        #pragma unroll
        for (int j = 0; j < 4; j++) al[j] = row_alpha[tx*4 + j];
        #pragma unroll
        for (int i = 0; i < 8; i++)
            #pragma unroll
            for (int j = 0; j < 4; j++) Oacc[i][j] *= al[j];

        const int d0 = ty * 8;
        #pragma unroll 4
        for (int m4 = 0; m4 < 64; m4 += 4) {
            float4 pv[4];
            #pragma unroll
            for (int mm = 0; mm < 4; mm++)
                pv[mm] = *(const float4*)&Ps[(m4 + mm)*64 + tx*4];
            #pragma unroll
            for (int i = 0; i < 8; i++) {
                float4 vf = *(const float4*)&Vs[(d0 + i)*64 + m4];
                float va[4] = {vf.x, vf.y, vf.z, vf.w};
                #pragma unroll
                for (int mm = 0; mm < 4; mm++) {
                    float pj[4] = {pv[mm].x, pv[mm].y, pv[mm].z, pv[mm].w};
                    #pragma unroll
                    for (int j = 0; j < 4; j++)
                        Oacc[i][j] += va[mm] * pj[j];
                }
            }
        }
    }
    __syncthreads();

    // Normalize and write out: att[b, h*HD+d, l]
    float inv[4];
    #pragma unroll
    for (int j = 0; j < 4; j++) inv[j] = 1.0f / row_sum[tx*4 + j];
    float* og = g_att + ((size_t)b * CC + (size_t)h * HD) * LL;
    const int d0 = ty * 8;
    #pragma unroll
    for (int i = 0; i < 8; i++) {
        float4 o = make_float4(Oacc[i][0]*inv[0], Oacc[i][1]*inv[1],
                               Oacc[i][2]*inv[2], Oacc[i][3]*inv[3]);
        *(float4*)&og[(size_t)(d0 + i) * LL + lq0 + tx*4] = o;
    }
}

// ---------------------------------------------------------------------------
extern "C" void kernel_launch(void* const* d_in, const int* in_sizes, int n_in,
                              void* d_out, int out_size) {
    const float* x      = (const float*)d_in[0];
    const float* gamma  = (const float*)d_in[1];
    const float* beta   = (const float*)d_in[2];
    const float* w_qkv  = (const float*)d_in[3];
    const float* b_qkv  = (const float*)d_in[4];
    const float* w_proj = (const float*)d_in[5];
    const float* b_proj = (const float*)d_in[6];
    float* out = (float*)d_out;

    float *xn_p, *qkv_p, *att_p;
    cudaGetSymbolAddress((void**)&xn_p,  g_xn);
    cudaGetSymbolAddress((void**)&qkv_p, g_qkv);
    cudaGetSymbolAddress((void**)&att_p, g_att);

    // GroupNorm
    gn_stats_kernel<<<BB*GG, 256>>>(x);
    gn_apply_kernel<<<BB*CC, 256>>>(x, gamma, beta);

    // QKV projection: M=1536, K=512
    gemm64_kernel<false><<<dim3(LL/64, (3*CC)/64, BB), 256>>>(
        w_qkv, xn_p, b_qkv, nullptr, qkv_p, 3*CC, CC);

    // Attention
    const int attn_smem = (128*64*3 + 64*64 + 64*3 + 4*64) * (int)sizeof(float);
    cudaFuncSetAttribute(attn_kernel, cudaFuncAttributeMaxDynamicSharedMemorySize, attn_smem);
    attn_kernel<<<dim3(LL/64, NH, BB), 256, attn_smem>>>();

    // Output projection + residual: M=512, K=512
    gemm64_kernel<true><<<dim3(LL/64, CC/64, BB), 256>>>(
        w_proj, att_p, b_proj, x, out, CC, CC);
}

// round 5
// speedup vs baseline: 1.2632x; 1.2632x over previous
#include <cuda_runtime.h>
#include <cuda_bf16.h>
#include <cstdint>
#include <math.h>

#define BB 16
#define CC 512
#define LL 1024       // h*w
#define GG 8
#define CPG 64        // channels per group
#define NH 4
#define HD 128
#define EPS_GN 1e-5f

// ---------------------------------------------------------------------------
// Scratch (device globals: no allocation allowed)
// ---------------------------------------------------------------------------
__device__ float g_qkv[(size_t)BB*3*CC*LL];               // 96 MB fp32
__device__ __nv_bfloat16 g_xnT_h[(size_t)BB*LL*CC];       // xn^T hi  [b][l][c]
__device__ __nv_bfloat16 g_xnT_l[(size_t)BB*LL*CC];       // xn^T lo
__device__ __nv_bfloat16 g_attT_h[(size_t)BB*LL*CC];      // att^T hi [b][l][c]
__device__ __nv_bfloat16 g_attT_l[(size_t)BB*LL*CC];      // att^T lo
__device__ __nv_bfloat16 g_wq_h[(size_t)3*CC*CC], g_wq_l[(size_t)3*CC*CC];
__device__ __nv_bfloat16 g_wp_h[(size_t)CC*CC],   g_wp_l[(size_t)CC*CC];
__device__ float g_mean[BB*GG];
__device__ float g_rstd[BB*GG];

// ---------------------------------------------------------------------------
// mma.sync bf16 (sm_80-era PTX; runs on tensor pipe, valid at compute_103)
// ---------------------------------------------------------------------------
__device__ __forceinline__ void mma16816(float* c, const uint32_t* a, const uint32_t* b) {
    asm volatile(
        "mma.sync.aligned.m16n8k16.row.col.f32.bf16.bf16.f32 "
        "{%0,%1,%2,%3}, {%4,%5,%6,%7}, {%8,%9}, {%0,%1,%2,%3};"
        : "+f"(c[0]), "+f"(c[1]), "+f"(c[2]), "+f"(c[3])
        : "r"(a[0]), "r"(a[1]), "r"(a[2]), "r"(a[3]), "r"(b[0]), "r"(b[1]));
}

// ---------------------------------------------------------------------------
// GroupNorm statistics
// ---------------------------------------------------------------------------
__global__ void __launch_bounds__(256) gn_stats_kernel(const float* __restrict__ x) {
    int bg = blockIdx.x;
    int b = bg / GG, g = bg % GG;
    const float4* p = (const float4*)(x + ((size_t)b*CC + (size_t)g*CPG) * LL);
    const int n4 = CPG * LL / 4;
    float s = 0.f, sq = 0.f;
    for (int i = threadIdx.x; i < n4; i += 256) {
        float4 v = p[i];
        s  += v.x + v.y + v.z + v.w;
        sq += v.x*v.x + v.y*v.y + v.z*v.z + v.w*v.w;
    }
    __shared__ float ss[256], sq_s[256];
    ss[threadIdx.x] = s; sq_s[threadIdx.x] = sq;
    __syncthreads();
    for (int o = 128; o > 0; o >>= 1) {
        if (threadIdx.x < o) { ss[threadIdx.x] += ss[threadIdx.x+o]; sq_s[threadIdx.x] += sq_s[threadIdx.x+o]; }
        __syncthreads();
    }
    if (threadIdx.x == 0) {
        const float invN = 1.0f / (float)(CPG * LL);
        float mean = ss[0] * invN;
        float var  = sq_s[0] * invN - mean * mean;
        g_mean[bg] = mean;
        g_rstd[bg] = rsqrtf(var + EPS_GN);
    }
}

// ---------------------------------------------------------------------------
// GroupNorm apply + transpose + bf16 split: x[b][c][l] -> xnT_{h,l}[b][l][c]
// ---------------------------------------------------------------------------
__global__ void __launch_bounds__(256) gn_norm_t_kernel(const float* __restrict__ x,
                                                        const float* __restrict__ gamma,
                                                        const float* __restrict__ beta) {
    const int b  = blockIdx.z;
    const int c0 = blockIdx.y * 64;
    const int l0 = blockIdx.x * 64;
    const int gidx = b * GG + c0 / CPG;
    const float mean = g_mean[gidx], rstd = g_rstd[gidx];

    __shared__ float t[64][65];
    for (int idx = threadIdx.x; idx < 1024; idx += 256) {
        int i  = idx >> 4;         // c-local
        int j4 = (idx & 15) * 4;   // l-local
        int c = c0 + i;
        float ga = gamma[c] * rstd;
        float be = beta[c] - mean * ga;
        float4 v = *(const float4*)(x + ((size_t)b*CC + c)*LL + l0 + j4);
        t[j4+0][i] = v.x*ga + be; t[j4+1][i] = v.y*ga + be;
        t[j4+2][i] = v.z*ga + be; t[j4+3][i] = v.w*ga + be;
    }
    __syncthreads();
    for (int idx = threadIdx.x; idx < 1024; idx += 256) {
        int l  = idx >> 4;
        int cq = (idx & 15) * 4;
        __nv_bfloat16 h[4], lo[4];
        #pragma unroll
        for (int q = 0; q < 4; q++) {
            float v = t[l][cq + q];
            h[q]  = __float2bfloat16(v);
            lo[q] = __float2bfloat16(v - __bfloat162float(h[q]));
        }
        size_t o = ((size_t)b*LL + l0 + l) * CC + c0 + cq;
        *(uint2*)(g_xnT_h + o) = *(uint2*)h;
        *(uint2*)(g_xnT_l + o) = *(uint2*)lo;
    }
}

// ---------------------------------------------------------------------------
// Weight fp32 -> bf16 hi/lo split
// ---------------------------------------------------------------------------
__global__ void __launch_bounds__(256) split_kernel(const float* __restrict__ src,
                                                    __nv_bfloat16* __restrict__ hi,
                                                    __nv_bfloat16* __restrict__ lo, int n) {
    int i = blockIdx.x * 256 + threadIdx.x;
    if (i < n) {
        float v = src[i];
        __nv_bfloat16 h = __float2bfloat16(v);
        hi[i] = h;
        lo[i] = __float2bfloat16(v - __bfloat162float(h));
    }
}

// ---------------------------------------------------------------------------
// mma.sync bf16 split GEMM: out[b][m][n] = sum_k A[m][k]*B[b][n][k] + bias[m]
//   3-term split product: AhBh + AlBh + AhBl  (fp32 accumulate)
//   CTA 128m x 128n, 8 warps (2x4), warp tile 64x32, K chunked by 32,
//   double-buffered smem, 80B row stride (16B aligned, conflict-free frags).
//   grid (LL/128, M/128, BB), 256 threads.
// ---------------------------------------------------------------------------
#define TILE_B 10240           // 128 rows x 80B
#define STAGE_B 40960          // 4 tiles: Ah, Al, Bh, Bl
template<bool RES>
__global__ void __launch_bounds__(256) gemm_mma_kernel(
        const __nv_bfloat16* __restrict__ Ah, const __nv_bfloat16* __restrict__ Al,
        const __nv_bfloat16* __restrict__ Bh_all, const __nv_bfloat16* __restrict__ Bl_all,
        const float* __restrict__ bias, const float* __restrict__ res,
        float* __restrict__ out, int M, int K) {
    extern __shared__ char smc[];
    const int tid = threadIdx.x;
    const int wid = tid >> 5;
    const int lane = tid & 31;
    const int g  = lane >> 2;        // 0..7
    const int tg = lane & 3;         // 0..3
    const int wm = wid >> 2;         // 0..1 : m offset 64
    const int wn = wid & 3;          // 0..3 : n offset 32
    const int b  = blockIdx.z;
    const int m0 = blockIdx.y * 128;
    const int n0 = blockIdx.x * 128;

    const __nv_bfloat16* Bh = Bh_all + (size_t)b * LL * CC;
    const __nv_bfloat16* Bl = Bl_all + (size_t)b * LL * CC;

    // chunk loader: 4 tiles x 128 rows x 64B (= 4 uint4/row)
    auto load_chunk = [&](int k0, int stage) {
        char* st = smc + stage * STAGE_B;
        #pragma unroll
        for (int i = 0; i < 8; i++) {
            int idx = tid + i * 256;           // 0..2047
            int t = idx >> 9;                  // tile 0..3
            int r = (idx >> 2) & 127;          // row
            int u = idx & 3;                   // 16B unit
            const __nv_bfloat16* src;
            if (t == 0)      src = Ah + (size_t)(m0 + r) * K + k0 + u * 8;
            else if (t == 1) src = Al + (size_t)(m0 + r) * K + k0 + u * 8;
            else if (t == 2) src = Bh + (size_t)(n0 + r) * K + k0 + u * 8;
            else             src = Bl + (size_t)(n0 + r) * K + k0 + u * 8;
            *(uint4*)(st + t * TILE_B + r * 80 + u * 16) = *(const uint4*)src;
        }
    };

    float acc[4][4][4];
    #pragma unroll
    for (int i = 0; i < 4; i++)
        #pragma unroll
        for (int j = 0; j < 4; j++)
            #pragma unroll
            for (int q = 0; q < 4; q++) acc[i][j][q] = 0.f;

    load_chunk(0, 0);
    __syncthreads();

    const int NCH = K / 32;    // 16
    for (int c = 0; c < NCH; c++) {
        if (c + 1 < NCH) load_chunk((c + 1) * 32, (c + 1) & 1);

        const char* st = smc + (c & 1) * STAGE_B;
        const char* pAh = st;
        const char* pAl = st + TILE_B;
        const char* pBh = st + 2 * TILE_B;
        const char* pBl = st + 3 * TILE_B;

        #pragma unroll
        for (int kk = 0; kk < 32; kk += 16) {
            const int kb = (kk + tg * 2) * 2;   // byte offset of k pair
            // B fragments for 4 n-tiles (hi & lo)
            uint32_t bh[4][2], bl[4][2];
            #pragma unroll
            for (int nt = 0; nt < 4; nt++) {
                int off = (wn * 32 + nt * 8 + g) * 80 + kb;
                bh[nt][0] = *(const uint32_t*)(pBh + off);
                bh[nt][1] = *(const uint32_t*)(pBh + off + 16);
                bl[nt][0] = *(const uint32_t*)(pBl + off);
                bl[nt][1] = *(const uint32_t*)(pBl + off + 16);
            }
            #pragma unroll
            for (int mt = 0; mt < 4; mt++) {
                int ro0 = (wm * 64 + mt * 16 + g) * 80 + kb;
                int ro1 = ro0 + 8 * 80;
                uint32_t ah[4], al[4];
                ah[0] = *(const uint32_t*)(pAh + ro0);
                ah[1] = *(const uint32_t*)(pAh + ro1);
                ah[2] = *(const uint32_t*)(pAh + ro0 + 16);
                ah[3] = *(const uint32_t*)(pAh + ro1 + 16);
                al[0] = *(const uint32_t*)(pAl + ro0);
                al[1] = *(const uint32_t*)(pAl + ro1);
                al[2] = *(const uint32_t*)(pAl + ro0 + 16);
                al[3] = *(const uint32_t*)(pAl + ro1 + 16);
                #pragma unroll
                for (int nt = 0; nt < 4; nt++) {
                    mma16816(acc[mt][nt], ah, bh[nt]);
                    mma16816(acc[mt][nt], al, bh[nt]);
                    mma16816(acc[mt][nt], ah, bl[nt]);
                }
            }
        }
        __syncthreads();
    }

    // Epilogue: bias (+ residual), write fp32
    #pragma unroll
    for (int mt = 0; mt < 4; mt++) {
        int r0 = m0 + wm * 64 + mt * 16 + g;
        int r1 = r0 + 8;
        float bv0 = bias[r0], bv1 = bias[r1];
        #pragma unroll
        for (int nt = 0; nt < 4; nt++) {
            int col = n0 + wn * 32 + nt * 8 + tg * 2;
            float2 o0 = make_float2(acc[mt][nt][0] + bv0, acc[mt][nt][1] + bv0);
            float2 o1 = make_float2(acc[mt][nt][2] + bv1, acc[mt][nt][3] + bv1);
            size_t off0 = ((size_t)b * M + r0) * LL + col;
            size_t off1 = ((size_t)b * M + r1) * LL + col;
            if (RES) {
                float2 q0 = *(const float2*)(res + off0);
                float2 q1 = *(const float2*)(res + off1);
                o0.x += q0.x; o0.y += q0.y; o1.x += q1.x; o1.y += q1.y;
            }
            *(float2*)(out + off0) = o0;
            *(float2*)(out + off1) = o1;
        }
    }
}

// ---------------------------------------------------------------------------
// Flash attention (fp32): epilogue writes att^T bf16 hi/lo
// ---------------------------------------------------------------------------
__global__ void __launch_bounds__(256) attn_kernel() {
    const int lq0 = blockIdx.x * 64;
    const int h   = blockIdx.y;
    const int b   = blockIdx.z;
    const float scale = 0.08838834764831845f;  // 1/sqrt(128)

    extern __shared__ float smf[];
    float* Qs = smf;
    float* Ks = Qs + 128*64;
    float* Vs = Ks + 128*64;
    float* Ps = Vs + 128*64;
    float* row_max   = Ps + 64*64;
    float* row_sum   = row_max + 64;
    float* row_alpha = row_sum + 64;
    float* part      = row_alpha + 64;

    const int tid = threadIdx.x;
    const int tx = tid & 15;
    const int ty = tid >> 4;

    const size_t base = ((size_t)b * 3 * CC + (size_t)h * HD) * LL;
    const float* qg = g_qkv + base;
    const float* kg = g_qkv + base + (size_t)CC * LL;
    const float* vg = g_qkv + base + (size_t)2 * CC * LL;

    #pragma unroll
    for (int i = 0; i < 32; i++) {
        int idx = tid + i * 256;
        int d = idx >> 6, l = idx & 63;
        Qs[idx] = qg[(size_t)d * LL + lq0 + l] * scale;
    }
    if (tid < 64) { row_max[tid] = -1e30f; row_sum[tid] = 0.f; }

    float Oacc[8][4];
    #pragma unroll
    for (int i = 0; i < 8; i++)
        #pragma unroll
        for (int j = 0; j < 4; j++) Oacc[i][j] = 0.f;

    for (int kt = 0; kt < 16; kt++) {
        const int lk0 = kt * 64;
        __syncthreads();
        #pragma unroll
        for (int i = 0; i < 32; i++) {
            int idx = tid + i * 256;
            int d = idx >> 6, m = idx & 63;
            Ks[idx] = kg[(size_t)d * LL + lk0 + m];
            Vs[idx] = vg[(size_t)d * LL + lk0 + m];
        }
        __syncthreads();

        float acc[4][4] = {};
        #pragma unroll 8
        for (int d = 0; d < 128; d++) {
            float4 kf = *(const float4*)&Ks[d*64 + ty*4];
            float4 qf = *(const float4*)&Qs[d*64 + tx*4];
            float ka[4] = {kf.x, kf.y, kf.z, kf.w};
            float qa[4] = {qf.x, qf.y, qf.z, qf.w};
            #pragma unroll
            for (int i = 0; i < 4; i++)
                #pragma unroll
                for (int j = 0; j < 4; j++)
                    acc[i][j] += ka[i] * qa[j];
        }
        #pragma unroll
        for (int i = 0; i < 4; i++)
            *(float4*)&Ps[(ty*4 + i)*64 + tx*4] =
                make_float4(acc[i][0], acc[i][1], acc[i][2], acc[i][3]);
        __syncthreads();

        {
            int l = tid & 63, q = tid >> 6;
            float mx = -1e30f;
            #pragma unroll
            for (int m = 0; m < 16; m++) mx = fmaxf(mx, Ps[(q*16 + m)*64 + l]);
            part[q*64 + l] = mx;
        }
        __syncthreads();
        if (tid < 64) {
            float mx = fmaxf(fmaxf(part[tid], part[64+tid]),
                             fmaxf(part[128+tid], part[192+tid]));
            float om = row_max[tid];
            float nm = fmaxf(om, mx);
            row_max[tid] = nm;
            row_alpha[tid] = __expf(om - nm);
        }
        __syncthreads();
        {
            int l = tid & 63, q = tid >> 6;
            float nm = row_max[l];
            float s = 0.f;
            #pragma unroll
            for (int m = 0; m < 16; m++) {
                float p = __expf(Ps[(q*16 + m)*64 + l] - nm);
                Ps[(q*16 + m)*64 + l] = p;
                s += p;
            }
            part[q*64 + l] = s;
        }
        __syncthreads();
        if (tid < 64) {
            float s = part[tid] + part[64+tid] + part[128+tid] + part[192+tid];
            row_sum[tid] = row_sum[tid] * row_alpha[tid] + s;
        }

        float al[4];
        #pragma unroll
        for (int j = 0; j < 4; j++) al[j] = row_alpha[tx*4 + j];
        #pragma unroll
        for (int i = 0; i < 8; i++)
            #pragma unroll
            for (int j = 0; j < 4; j++) Oacc[i][j] *= al[j];

        const int d0 = ty * 8;
        #pragma unroll 4
        for (int m4 = 0; m4 < 64; m4 += 4) {
            float4 pv[4];
            #pragma unroll
            for (int mm = 0; mm < 4; mm++)
                pv[mm] = *(const float4*)&Ps[(m4 + mm)*64 + tx*4];
            #pragma unroll
            for (int i = 0; i < 8; i++) {
                float4 vf = *(const float4*)&Vs[(d0 + i)*64 + m4];
                float va[4] = {vf.x, vf.y, vf.z, vf.w};
                #pragma unroll
                for (int mm = 0; mm < 4; mm++) {
                    float pj[4] = {pv[mm].x, pv[mm].y, pv[mm].z, pv[mm].w};
                    #pragma unroll
                    for (int j = 0; j < 4; j++)
                        Oacc[i][j] += va[mm] * pj[j];
                }
            }
        }
    }
    __syncthreads();

    // Epilogue: normalize, bf16-split, store transposed att^T[b][l][c]
    float inv[4];
    #pragma unroll
    for (int j = 0; j < 4; j++) inv[j] = 1.0f / row_sum[tx*4 + j];
    const int d0 = ty * 8;
    #pragma unroll
    for (int j = 0; j < 4; j++) {
        struct __align__(16) { __nv_bfloat16 v[8]; } hb, lb;
        #pragma unroll
        for (int i = 0; i < 8; i++) {
            float v = Oacc[i][j] * inv[j];
            hb.v[i] = __float2bfloat16(v);
            lb.v[i] = __float2bfloat16(v - __bfloat162float(hb.v[i]));
        }
        size_t o = ((size_t)b * LL + lq0 + tx*4 + j) * CC + (size_t)h * HD + d0;
        *(uint4*)(g_attT_h + o) = *(uint4*)&hb;
        *(uint4*)(g_attT_l + o) = *(uint4*)&lb;
    }
}

// ---------------------------------------------------------------------------
extern "C" void kernel_launch(void* const* d_in, const int* in_sizes, int n_in,
                              void* d_out, int out_size) {
    const float* x      = (const float*)d_in[0];
    const float* gamma  = (const float*)d_in[1];
    const float* beta   = (const float*)d_in[2];
    const float* w_qkv  = (const float*)d_in[3];
    const float* b_qkv  = (const float*)d_in[4];
    const float* w_proj = (const float*)d_in[5];
    const float* b_proj = (const float*)d_in[6];
    float* out = (float*)d_out;

    float* qkv_p;
    __nv_bfloat16 *xnh, *xnl, *ath, *atl, *wqh, *wql, *wph, *wpl;
    cudaGetSymbolAddress((void**)&qkv_p, g_qkv);
    cudaGetSymbolAddress((void**)&xnh, g_xnT_h);
    cudaGetSymbolAddress((void**)&xnl, g_xnT_l);
    cudaGetSymbolAddress((void**)&ath, g_attT_h);
    cudaGetSymbolAddress((void**)&atl, g_attT_l);
    cudaGetSymbolAddress((void**)&wqh, g_wq_h);
    cudaGetSymbolAddress((void**)&wql, g_wq_l);
    cudaGetSymbolAddress((void**)&wph, g_wp_h);
    cudaGetSymbolAddress((void**)&wpl, g_wp_l);

    // weight splits + GN
    split_kernel<<<(3*CC*CC + 255)/256, 256>>>(w_qkv, wqh, wql, 3*CC*CC);
    split_kernel<<<(CC*CC + 255)/256, 256>>>(w_proj, wph, wpl, CC*CC);
    gn_stats_kernel<<<BB*GG, 256>>>(x);
    gn_norm_t_kernel<<<dim3(LL/64, CC/64, BB), 256>>>(x, gamma, beta);

    // QKV projection (mma.sync): M=1536, K=512
    const int gemm_smem = 2 * STAGE_B;
    cudaFuncSetAttribute(gemm_mma_kernel<false>, cudaFuncAttributeMaxDynamicSharedMemorySize, gemm_smem);
    cudaFuncSetAttribute(gemm_mma_kernel<true>,  cudaFuncAttributeMaxDynamicSharedMemorySize, gemm_smem);
    gemm_mma_kernel<false><<<dim3(LL/128, (3*CC)/128, BB), 256, gemm_smem>>>(
        wqh, wql, xnh, xnl, b_qkv, nullptr, qkv_p, 3*CC, CC);

    // Attention (fp32)
    const int attn_smem = (128*64*3 + 64*64 + 64*3 + 4*64) * (int)sizeof(float);
    cudaFuncSetAttribute(attn_kernel, cudaFuncAttributeMaxDynamicSharedMemorySize, attn_smem);
    attn_kernel<<<dim3(LL/64, NH, BB), 256, attn_smem>>>();

    // Output projection + residual (mma.sync): M=512, K=512
    gemm_mma_kernel<true><<<dim3(LL/128, CC/128, BB), 256, gemm_smem>>>(
        wph, wpl, ath, atl, b_proj, x, out, CC, CC);
}

// round 6
// speedup vs baseline: 1.4921x; 1.1812x over previous
#include <cuda_runtime.h>
#include <cuda_bf16.h>
#include <cstdint>
#include <math.h>

#define BB 16
#define CC 512
#define LL 1024       // h*w
#define GG 8
#define CPG 64        // channels per group
#define NH 4
#define HD 128
#define EPS_GN 1e-5f
#define QK_SCALE 0.08838834764831845f

// ---------------------------------------------------------------------------
// Scratch (device globals: no allocation allowed)
// ---------------------------------------------------------------------------
__device__ float g_qkv[(size_t)BB*3*CC*LL];               // 96 MB fp32
__device__ __nv_bfloat16 g_xnT_h[(size_t)BB*LL*CC];       // xn^T hi  [b][l][c]
__device__ __nv_bfloat16 g_xnT_l[(size_t)BB*LL*CC];
__device__ __nv_bfloat16 g_attT_h[(size_t)BB*LL*CC];      // att^T hi [b][l][c]
__device__ __nv_bfloat16 g_attT_l[(size_t)BB*LL*CC];
__device__ __nv_bfloat16 g_wq_h[(size_t)3*CC*CC], g_wq_l[(size_t)3*CC*CC];
__device__ __nv_bfloat16 g_wp_h[(size_t)CC*CC],   g_wp_l[(size_t)CC*CC];
// attention operands
__device__ __nv_bfloat16 g_qt_h[(size_t)BB*NH*LL*HD], g_qt_l[(size_t)BB*NH*LL*HD]; // [b][h][l][d]
__device__ __nv_bfloat16 g_kt_h[(size_t)BB*NH*LL*HD], g_kt_l[(size_t)BB*NH*LL*HD]; // [b][h][l][d]
__device__ __nv_bfloat16 g_v_h [(size_t)BB*NH*HD*LL], g_v_l [(size_t)BB*NH*HD*LL]; // [b][h][d][l]
__device__ float g_mean[BB*GG];
__device__ float g_rstd[BB*GG];

// ---------------------------------------------------------------------------
// mma.sync bf16 (sm_80-era PTX; runs on tensor pipe, valid at compute_103)
// ---------------------------------------------------------------------------
__device__ __forceinline__ void mma16816(float* c, const uint32_t* a, const uint32_t* b) {
    asm volatile(
        "mma.sync.aligned.m16n8k16.row.col.f32.bf16.bf16.f32 "
        "{%0,%1,%2,%3}, {%4,%5,%6,%7}, {%8,%9}, {%0,%1,%2,%3};"
        : "+f"(c[0]), "+f"(c[1]), "+f"(c[2]), "+f"(c[3])
        : "r"(a[0]), "r"(a[1]), "r"(a[2]), "r"(a[3]), "r"(b[0]), "r"(b[1]));
}
__device__ __forceinline__ uint32_t pack_bf16x2(float a, float b) {
    __nv_bfloat162 t(__float2bfloat16(a), __float2bfloat16(b));
    return *(uint32_t*)&t;
}
__device__ __forceinline__ void split2(float a, float b, uint32_t& hi, uint32_t& lo) {
    __nv_bfloat16 ha = __float2bfloat16(a), hb = __float2bfloat16(b);
    float ra = a - __bfloat162float(ha), rb = b - __bfloat162float(hb);
    __nv_bfloat162 th(ha, hb), tl(__float2bfloat16(ra), __float2bfloat16(rb));
    hi = *(uint32_t*)&th; lo = *(uint32_t*)&tl;
}

// ---------------------------------------------------------------------------
// GroupNorm statistics
// ---------------------------------------------------------------------------
__global__ void __launch_bounds__(256) gn_stats_kernel(const float* __restrict__ x) {
    int bg = blockIdx.x;
    int b = bg / GG, g = bg % GG;
    const float4* p = (const float4*)(x + ((size_t)b*CC + (size_t)g*CPG) * LL);
    const int n4 = CPG * LL / 4;
    float s = 0.f, sq = 0.f;
    for (int i = threadIdx.x; i < n4; i += 256) {
        float4 v = p[i];
        s  += v.x + v.y + v.z + v.w;
        sq += v.x*v.x + v.y*v.y + v.z*v.z + v.w*v.w;
    }
    __shared__ float ss[256], sq_s[256];
    ss[threadIdx.x] = s; sq_s[threadIdx.x] = sq;
    __syncthreads();
    for (int o = 128; o > 0; o >>= 1) {
        if (threadIdx.x < o) { ss[threadIdx.x] += ss[threadIdx.x+o]; sq_s[threadIdx.x] += sq_s[threadIdx.x+o]; }
        __syncthreads();
    }
    if (threadIdx.x == 0) {
        const float invN = 1.0f / (float)(CPG * LL);
        float mean = ss[0] * invN;
        float var  = sq_s[0] * invN - mean * mean;
        g_mean[bg] = mean;
        g_rstd[bg] = rsqrtf(var + EPS_GN);
    }
}

// ---------------------------------------------------------------------------
// GroupNorm apply + transpose + bf16 split: x[b][c][l] -> xnT_{h,l}[b][l][c]
// ---------------------------------------------------------------------------
__global__ void __launch_bounds__(256) gn_norm_t_kernel(const float* __restrict__ x,
                                                        const float* __restrict__ gamma,
                                                        const float* __restrict__ beta) {
    const int b  = blockIdx.z;
    const int c0 = blockIdx.y * 64;
    const int l0 = blockIdx.x * 64;
    const int gidx = b * GG + c0 / CPG;
    const float mean = g_mean[gidx], rstd = g_rstd[gidx];

    __shared__ float t[64][65];
    for (int idx = threadIdx.x; idx < 1024; idx += 256) {
        int i  = idx >> 4;
        int j4 = (idx & 15) * 4;
        int c = c0 + i;
        float ga = gamma[c] * rstd;
        float be = beta[c] - mean * ga;
        float4 v = *(const float4*)(x + ((size_t)b*CC + c)*LL + l0 + j4);
        t[j4+0][i] = v.x*ga + be; t[j4+1][i] = v.y*ga + be;
        t[j4+2][i] = v.z*ga + be; t[j4+3][i] = v.w*ga + be;
    }
    __syncthreads();
    for (int idx = threadIdx.x; idx < 1024; idx += 256) {
        int l  = idx >> 4;
        int cq = (idx & 15) * 4;
        __nv_bfloat16 h[4], lo[4];
        #pragma unroll
        for (int q = 0; q < 4; q++) {
            float v = t[l][cq + q];
            h[q]  = __float2bfloat16(v);
            lo[q] = __float2bfloat16(v - __bfloat162float(h[q]));
        }
        size_t o = ((size_t)b*LL + l0 + l) * CC + c0 + cq;
        *(uint2*)(g_xnT_h + o) = *(uint2*)h;
        *(uint2*)(g_xnT_l + o) = *(uint2*)lo;
    }
}

// ---------------------------------------------------------------------------
// Weight fp32 -> bf16 hi/lo split
// ---------------------------------------------------------------------------
__global__ void __launch_bounds__(256) split_kernel(const float* __restrict__ src,
                                                    __nv_bfloat16* __restrict__ hi,
                                                    __nv_bfloat16* __restrict__ lo, int n) {
    int i = blockIdx.x * 256 + threadIdx.x;
    if (i < n) {
        float v = src[i];
        __nv_bfloat16 h = __float2bfloat16(v);
        hi[i] = h;
        lo[i] = __float2bfloat16(v - __bfloat162float(h));
    }
}

// ---------------------------------------------------------------------------
// QKV post-pass A: q,k channels -> transposed hi/lo [b][h][l][d], Q scaled
// grid (LL/64, 2*CC/64, BB), 256 threads
// ---------------------------------------------------------------------------
__global__ void __launch_bounds__(256) qkT_convert_kernel() {
    const int b  = blockIdx.z;
    const int c0 = blockIdx.y * 64;      // 0..1023 (q:0..511, k:512..1023)
    const int l0 = blockIdx.x * 64;
    const bool isQ = c0 < CC;
    const int cq = isQ ? c0 : c0 - CC;   // channel within q or k
    const int h  = cq / HD;
    const int d0 = cq % HD;
    const float scale = isQ ? QK_SCALE : 1.f;

    const float* in = g_qkv + ((size_t)b*3*CC + c0) * LL;
    __shared__ float t[64][65];
    for (int idx = threadIdx.x; idx < 1024; idx += 256) {
        int i  = idx >> 4;
        int j4 = (idx & 15) * 4;
        float4 v = *(const float4*)(in + (size_t)i * LL + l0 + j4);
        t[j4+0][i] = v.x*scale; t[j4+1][i] = v.y*scale;
        t[j4+2][i] = v.z*scale; t[j4+3][i] = v.w*scale;
    }
    __syncthreads();
    __nv_bfloat16* dh = (isQ ? g_qt_h : g_kt_h) + (size_t)(b*NH + h) * LL * HD;
    __nv_bfloat16* dl = (isQ ? g_qt_l : g_kt_l) + (size_t)(b*NH + h) * LL * HD;
    for (int idx = threadIdx.x; idx < 1024; idx += 256) {
        int l  = idx >> 4;
        int dq = (idx & 15) * 4;
        __nv_bfloat16 hh[4], lo[4];
        #pragma unroll
        for (int q = 0; q < 4; q++) {
            float v = t[l][dq + q];
            hh[q] = __float2bfloat16(v);
            lo[q] = __float2bfloat16(v - __bfloat162float(hh[q]));
        }
        size_t o = (size_t)(l0 + l) * HD + d0 + dq;
        *(uint2*)(dh + o) = *(uint2*)hh;
        *(uint2*)(dl + o) = *(uint2*)lo;
    }
}

// ---------------------------------------------------------------------------
// QKV post-pass B: v channels straight elementwise split [b][h][d][l]
// ---------------------------------------------------------------------------
__global__ void __launch_bounds__(256) v_convert_kernel() {
    const int n4 = CC * LL / 4;          // per batch
    int i = blockIdx.x * 256 + threadIdx.x;   // over BB*n4
    int b = i / n4, r = i % n4;
    float4 v = ((const float4*)(g_qkv + ((size_t)b*3*CC + 2*CC) * LL))[r];
    __nv_bfloat16 hh[4], lo[4];
    float vv[4] = {v.x, v.y, v.z, v.w};
    #pragma unroll
    for (int q = 0; q < 4; q++) {
        hh[q] = __float2bfloat16(vv[q]);
        lo[q] = __float2bfloat16(vv[q] - __bfloat162float(hh[q]));
    }
    size_t o = (size_t)b * CC * LL + (size_t)r * 4;
    *(uint2*)(g_v_h + o) = *(uint2*)hh;
    *(uint2*)(g_v_l + o) = *(uint2*)lo;
}

// ---------------------------------------------------------------------------
// mma.sync bf16 split GEMM (unchanged from R5, passing at 9.4e-7)
// ---------------------------------------------------------------------------
#define TILE_B 10240
#define STAGE_B 40960
template<bool RES>
__global__ void __launch_bounds__(256) gemm_mma_kernel(
        const __nv_bfloat16* __restrict__ Ah, const __nv_bfloat16* __restrict__ Al,
        const __nv_bfloat16* __restrict__ Bh_all, const __nv_bfloat16* __restrict__ Bl_all,
        const float* __restrict__ bias, const float* __restrict__ res,
        float* __restrict__ out, int M, int K) {
    extern __shared__ char smc[];
    const int tid = threadIdx.x;
    const int wid = tid >> 5;
    const int lane = tid & 31;
    const int g  = lane >> 2;
    const int tg = lane & 3;
    const int wm = wid >> 2;
    const int wn = wid & 3;
    const int b  = blockIdx.z;
    const int m0 = blockIdx.y * 128;
    const int n0 = blockIdx.x * 128;

    const __nv_bfloat16* Bh = Bh_all + (size_t)b * LL * CC;
    const __nv_bfloat16* Bl = Bl_all + (size_t)b * LL * CC;

    auto load_chunk = [&](int k0, int stage) {
        char* st = smc + stage * STAGE_B;
        #pragma unroll
        for (int i = 0; i < 8; i++) {
            int idx = tid + i * 256;
            int t = idx >> 9;
            int r = (idx >> 2) & 127;
            int u = idx & 3;
            const __nv_bfloat16* src;
            if (t == 0)      src = Ah + (size_t)(m0 + r) * K + k0 + u * 8;
            else if (t == 1) src = Al + (size_t)(m0 + r) * K + k0 + u * 8;
            else if (t == 2) src = Bh + (size_t)(n0 + r) * K + k0 + u * 8;
            else             src = Bl + (size_t)(n0 + r) * K + k0 + u * 8;
            *(uint4*)(st + t * TILE_B + r * 80 + u * 16) = *(const uint4*)src;
        }
    };

    float acc[4][4][4];
    #pragma unroll
    for (int i = 0; i < 4; i++)
        #pragma unroll
        for (int j = 0; j < 4; j++)
            #pragma unroll
            for (int q = 0; q < 4; q++) acc[i][j][q] = 0.f;

    load_chunk(0, 0);
    __syncthreads();

    const int NCH = K / 32;
    for (int c = 0; c < NCH; c++) {
        if (c + 1 < NCH) load_chunk((c + 1) * 32, (c + 1) & 1);

        const char* st = smc + (c & 1) * STAGE_B;
        const char* pAh = st;
        const char* pAl = st + TILE_B;
        const char* pBh = st + 2 * TILE_B;
        const char* pBl = st + 3 * TILE_B;

        #pragma unroll
        for (int kk = 0; kk < 32; kk += 16) {
            const int kb = (kk + tg * 2) * 2;
            uint32_t bh[4][2], bl[4][2];
            #pragma unroll
            for (int nt = 0; nt < 4; nt++) {
                int off = (wn * 32 + nt * 8 + g) * 80 + kb;
                bh[nt][0] = *(const uint32_t*)(pBh + off);
                bh[nt][1] = *(const uint32_t*)(pBh + off + 16);
                bl[nt][0] = *(const uint32_t*)(pBl + off);
                bl[nt][1] = *(const uint32_t*)(pBl + off + 16);
            }
            #pragma unroll
            for (int mt = 0; mt < 4; mt++) {
                int ro0 = (wm * 64 + mt * 16 + g) * 80 + kb;
                int ro1 = ro0 + 8 * 80;
                uint32_t ah[4], al[4];
                ah[0] = *(const uint32_t*)(pAh + ro0);
                ah[1] = *(const uint32_t*)(pAh + ro1);
                ah[2] = *(const uint32_t*)(pAh + ro0 + 16);
                ah[3] = *(const uint32_t*)(pAh + ro1 + 16);
                al[0] = *(const uint32_t*)(pAl + ro0);
                al[1] = *(const uint32_t*)(pAl + ro1);
                al[2] = *(const uint32_t*)(pAl + ro0 + 16);
                al[3] = *(const uint32_t*)(pAl + ro1 + 16);
                #pragma unroll
                for (int nt = 0; nt < 4; nt++) {
                    mma16816(acc[mt][nt], ah, bh[nt]);
                    mma16816(acc[mt][nt], al, bh[nt]);
                    mma16816(acc[mt][nt], ah, bl[nt]);
                }
            }
        }
        __syncthreads();
    }

    #pragma unroll
    for (int mt = 0; mt < 4; mt++) {
        int r0 = m0 + wm * 64 + mt * 16 + g;
        int r1 = r0 + 8;
        float bv0 = bias[r0], bv1 = bias[r1];
        #pragma unroll
        for (int nt = 0; nt < 4; nt++) {
            int col = n0 + wn * 32 + nt * 8 + tg * 2;
            float2 o0 = make_float2(acc[mt][nt][0] + bv0, acc[mt][nt][1] + bv0);
            float2 o1 = make_float2(acc[mt][nt][2] + bv1, acc[mt][nt][3] + bv1);
            size_t off0 = ((size_t)b * M + r0) * LL + col;
            size_t off1 = ((size_t)b * M + r1) * LL + col;
            if (RES) {
                float2 q0 = *(const float2*)(res + off0);
                float2 q1 = *(const float2*)(res + off1);
                o0.x += q0.x; o0.y += q0.y; o1.x += q1.x; o1.y += q1.y;
            }
            *(float2*)(out + off0) = o0;
            *(float2*)(out + off1) = o1;
        }
    }
}

// ---------------------------------------------------------------------------
// Flash attention on mma.sync with 3-term bf16 split.
// CTA = (lq-block of 64, h, b), 256 threads (8 warps).
// S phase: warps 4m x 2n (tile 16lq x 32lk);  PV phase: 2m x 4n (32lq x 32d).
// Smem strides padded for conflict-free fragment loads.
// ---------------------------------------------------------------------------
#define QSTR 272     // 256B rows (128 d bf16) + 16 pad
#define VSTR 144     // 128B rows (64 lk bf16) + 16 pad
#define OFF_Q  0
#define OFF_K  34816                       // + s*34816 ; Kl at +17408
#define OFF_V  104448                      // + s*36864 ; Vl at +18432
#define OFF_PH 178176
#define OFF_PL 187392
#define OFF_RM 196608
#define OFF_RS 196864
#define OFF_RA 197120
#define OFF_PT 197376
#define OFF_ST 197888
#define ATTN_SMEM 198400

__global__ void __launch_bounds__(256) attn_mma_kernel() {
    extern __shared__ char smc[];
    const int tid = threadIdx.x;
    const int wid = tid >> 5;
    const int lane = tid & 31;
    const int g  = lane >> 2;
    const int tg = lane & 3;
    const int lq0 = blockIdx.x * 64;
    const int h   = blockIdx.y;
    const int b   = blockIdx.z;

    const int wmS = wid >> 1, wnS = wid & 1;     // S phase
    const int wmO = wid >> 2, wnO = wid & 3;     // PV phase

    const size_t bh_ld = (size_t)(b * NH + h) * LL * HD;
    const __nv_bfloat16* qth = g_qt_h + bh_ld + (size_t)lq0 * HD;
    const __nv_bfloat16* qtl = g_qt_l + bh_ld + (size_t)lq0 * HD;
    const __nv_bfloat16* kth = g_kt_h + bh_ld;
    const __nv_bfloat16* ktl = g_kt_l + bh_ld;
    const __nv_bfloat16* vhp = g_v_h + bh_ld;    // [d][l]
    const __nv_bfloat16* vlp = g_v_l + bh_ld;

    char* Qh = smc + OFF_Q;
    char* Ql = Qh + 17408;
    char* Phs = smc + OFF_PH;
    char* Pls = smc + OFF_PL;
    float* row_max   = (float*)(smc + OFF_RM);
    float* row_sum   = (float*)(smc + OFF_RS);
    float* row_alpha = (float*)(smc + OFF_RA);
    float* part      = (float*)(smc + OFF_PT);   // [2][64]
    float* spart     = (float*)(smc + OFF_ST);   // [2][64]

    // load Q tile (64 rows x 256B, hi+lo)
    #pragma unroll
    for (int i = 0; i < 8; i++) {
        int idx = tid + i * 256;
        int t = idx >> 10, r = (idx >> 4) & 63, u = idx & 15;
        const __nv_bfloat16* src = (t ? qtl : qth) + (size_t)r * HD + u * 8;
        *(uint4*)((t ? Ql : Qh) + r * QSTR + u * 16) = *(const uint4*)src;
    }
    if (tid < 64) { row_max[tid] = -1e30f; row_sum[tid] = 0.f; }

    auto load_kv = [&](int lk0, int s) {
        char* Kb = smc + OFF_K + s * 34816;
        char* Vb = smc + OFF_V + s * 36864;
        #pragma unroll
        for (int i = 0; i < 8; i++) {
            int idx = tid + i * 256;
            int t = idx >> 10, r = (idx >> 4) & 63, u = idx & 15;
            const __nv_bfloat16* src = (t ? ktl : kth) + (size_t)(lk0 + r) * HD + u * 8;
            *(uint4*)(Kb + t * 17408 + r * QSTR + u * 16) = *(const uint4*)src;
        }
        #pragma unroll
        for (int i = 0; i < 8; i++) {
            int idx = tid + i * 256;
            int t = idx >> 10, r = (idx >> 3) & 127, u = idx & 7;
            const __nv_bfloat16* src = (t ? vlp : vhp) + (size_t)r * LL + lk0 + u * 8;
            *(uint4*)(Vb + t * 18432 + r * VSTR + u * 16) = *(const uint4*)src;
        }
    };
    load_kv(0, 0);

    float accO[2][4][4];
    #pragma unroll
    for (int ms = 0; ms < 2; ms++)
        #pragma unroll
        for (int nt = 0; nt < 4; nt++)
            #pragma unroll
            for (int q = 0; q < 4; q++) accO[ms][nt][q] = 0.f;

    for (int kb16 = 0; kb16 < 16; kb16++) {
        const int st = kb16 & 1;
        __syncthreads();   // stage st loaded; prev PV done

        // ---- S = Q^T K (3-term split), warp tile 16lq x 32lk ----
        float accS[4][4] = {};
        {
            const char* KhP = smc + OFF_K + st * 34816;
            const char* KlP = KhP + 17408;
            #pragma unroll
            for (int ks = 0; ks < 8; ks++) {
                int kb = ks * 32 + tg * 4;
                int ro0 = (wmS * 16 + g) * QSTR + kb, ro1 = ro0 + 8 * QSTR;
                uint32_t ah[4], al[4];
                ah[0] = *(const uint32_t*)(Qh + ro0);
                ah[1] = *(const uint32_t*)(Qh + ro1);
                ah[2] = *(const uint32_t*)(Qh + ro0 + 16);
                ah[3] = *(const uint32_t*)(Qh + ro1 + 16);
                al[0] = *(const uint32_t*)(Ql + ro0);
                al[1] = *(const uint32_t*)(Ql + ro1);
                al[2] = *(const uint32_t*)(Ql + ro0 + 16);
                al[3] = *(const uint32_t*)(Ql + ro1 + 16);
                #pragma unroll
                for (int nt = 0; nt < 4; nt++) {
                    int bo = (wnS * 32 + nt * 8 + g) * QSTR + kb;
                    uint32_t bh[2] = {*(const uint32_t*)(KhP + bo),
                                      *(const uint32_t*)(KhP + bo + 16)};
                    uint32_t bl[2] = {*(const uint32_t*)(KlP + bo),
                                      *(const uint32_t*)(KlP + bo + 16)};
                    mma16816(accS[nt], ah, bh);
                    mma16816(accS[nt], al, bh);
                    mma16816(accS[nt], ah, bl);
                }
            }
        }
        if (kb16 + 1 < 16) load_kv((kb16 + 1) * 64, st ^ 1);

        // ---- row max (online) ----
        float m0 = -1e30f, m1 = -1e30f;
        #pragma unroll
        for (int nt = 0; nt < 4; nt++) {
            m0 = fmaxf(m0, fmaxf(accS[nt][0], accS[nt][1]));
            m1 = fmaxf(m1, fmaxf(accS[nt][2], accS[nt][3]));
        }
        m0 = fmaxf(m0, __shfl_xor_sync(0xffffffff, m0, 1));
        m0 = fmaxf(m0, __shfl_xor_sync(0xffffffff, m0, 2));
        m1 = fmaxf(m1, __shfl_xor_sync(0xffffffff, m1, 1));
        m1 = fmaxf(m1, __shfl_xor_sync(0xffffffff, m1, 2));
        if (tg == 0) {
            part[wnS * 64 + wmS * 16 + g]     = m0;
            part[wnS * 64 + wmS * 16 + g + 8] = m1;
        }
        __syncthreads();
        if (tid < 64) {
            float nm = fmaxf(row_max[tid], fmaxf(part[tid], part[64 + tid]));
            row_alpha[tid] = __expf(row_max[tid] - nm);
            row_max[tid] = nm;
        }
        __syncthreads();

        // ---- exp, write P hi/lo, partial sums ----
        {
            int r0 = wmS * 16 + g, r1 = r0 + 8;
            float nm0 = row_max[r0], nm1 = row_max[r1];
            float s0 = 0.f, s1 = 0.f;
            #pragma unroll
            for (int nt = 0; nt < 4; nt++) {
                float p00 = __expf(accS[nt][0] - nm0);
                float p01 = __expf(accS[nt][1] - nm0);
                float p10 = __expf(accS[nt][2] - nm1);
                float p11 = __expf(accS[nt][3] - nm1);
                s0 += p00 + p01; s1 += p10 + p11;
                int colb = (wnS * 32 + nt * 8 + tg * 2) * 2;
                uint32_t hi, lo;
                split2(p00, p01, hi, lo);
                *(uint32_t*)(Phs + r0 * VSTR + colb) = hi;
                *(uint32_t*)(Pls + r0 * VSTR + colb) = lo;
                split2(p10, p11, hi, lo);
                *(uint32_t*)(Phs + r1 * VSTR + colb) = hi;
                *(uint32_t*)(Pls + r1 * VSTR + colb) = lo;
            }
            s0 += __shfl_xor_sync(0xffffffff, s0, 1);
            s0 += __shfl_xor_sync(0xffffffff, s0, 2);
            s1 += __shfl_xor_sync(0xffffffff, s1, 1);
            s1 += __shfl_xor_sync(0xffffffff, s1, 2);
            if (tg == 0) {
                spart[wnS * 64 + r0] = s0;
                spart[wnS * 64 + r1] = s1;
            }
        }
        __syncthreads();
        if (tid < 64)
            row_sum[tid] = row_sum[tid] * row_alpha[tid] + spart[tid] + spart[64 + tid];
        __syncthreads();   // P + row_alpha stable for PV

        // ---- rescale O, then O += P V (3-term split) ----
        {
            float alv[2][2];
            #pragma unroll
            for (int ms = 0; ms < 2; ms++) {
                alv[ms][0] = row_alpha[wmO * 32 + ms * 16 + g];
                alv[ms][1] = row_alpha[wmO * 32 + ms * 16 + g + 8];
            }
            #pragma unroll
            for (int ms = 0; ms < 2; ms++)
                #pragma unroll
                for (int nt = 0; nt < 4; nt++) {
                    accO[ms][nt][0] *= alv[ms][0]; accO[ms][nt][1] *= alv[ms][0];
                    accO[ms][nt][2] *= alv[ms][1]; accO[ms][nt][3] *= alv[ms][1];
                }
            const char* VhP = smc + OFF_V + st * 36864;
            const char* VlP = VhP + 18432;
            #pragma unroll
            for (int ks = 0; ks < 4; ks++) {
                int kb = ks * 32 + tg * 4;
                uint32_t ah[2][4], al[2][4];
                #pragma unroll
                for (int ms = 0; ms < 2; ms++) {
                    int ro0 = (wmO * 32 + ms * 16 + g) * VSTR + kb, ro1 = ro0 + 8 * VSTR;
                    ah[ms][0] = *(const uint32_t*)(Phs + ro0);
                    ah[ms][1] = *(const uint32_t*)(Phs + ro1);
                    ah[ms][2] = *(const uint32_t*)(Phs + ro0 + 16);
                    ah[ms][3] = *(const uint32_t*)(Phs + ro1 + 16);
                    al[ms][0] = *(const uint32_t*)(Pls + ro0);
                    al[ms][1] = *(const uint32_t*)(Pls + ro1);
                    al[ms][2] = *(const uint32_t*)(Pls + ro0 + 16);
                    al[ms][3] = *(const uint32_t*)(Pls + ro1 + 16);
                }
                #pragma unroll
                for (int nt = 0; nt < 4; nt++) {
                    int bo = (wnO * 32 + nt * 8 + g) * VSTR + kb;
                    uint32_t bh[2] = {*(const uint32_t*)(VhP + bo),
                                      *(const uint32_t*)(VhP + bo + 16)};
                    uint32_t bl[2] = {*(const uint32_t*)(VlP + bo),
                                      *(const uint32_t*)(VlP + bo + 16)};
                    #pragma unroll
                    for (int ms = 0; ms < 2; ms++) {
                        mma16816(accO[ms][nt], ah[ms], bh);
                        mma16816(accO[ms][nt], al[ms], bh);
                        mma16816(accO[ms][nt], ah[ms], bl);
                    }
                }
            }
        }
    }

    // ---- epilogue: normalize, split, store att^T[b][l][c] hi/lo ----
    #pragma unroll
    for (int ms = 0; ms < 2; ms++) {
        int ra = wmO * 32 + ms * 16 + g, rb = ra + 8;
        float inv0 = 1.0f / row_sum[ra];
        float inv1 = 1.0f / row_sum[rb];
        #pragma unroll
        for (int nt = 0; nt < 4; nt++) {
            int dcol = h * HD + wnO * 32 + nt * 8 + tg * 2;
            uint32_t hi, lo;
            size_t oa = ((size_t)b * LL + lq0 + ra) * CC + dcol;
            split2(accO[ms][nt][0] * inv0, accO[ms][nt][1] * inv0, hi, lo);
            *(uint32_t*)(g_attT_h + oa) = hi;
            *(uint32_t*)(g_attT_l + oa) = lo;
            size_t ob = ((size_t)b * LL + lq0 + rb) * CC + dcol;
            split2(accO[ms][nt][2] * inv1, accO[ms][nt][3] * inv1, hi, lo);
            *(uint32_t*)(g_attT_h + ob) = hi;
            *(uint32_t*)(g_attT_l + ob) = lo;
        }
    }
}

// ---------------------------------------------------------------------------
extern "C" void kernel_launch(void* const* d_in, const int* in_sizes, int n_in,
                              void* d_out, int out_size) {
    const float* x      = (const float*)d_in[0];
    const float* gamma  = (const float*)d_in[1];
    const float* beta   = (const float*)d_in[2];
    const float* w_qkv  = (const float*)d_in[3];
    const float* b_qkv  = (const float*)d_in[4];
    const float* w_proj = (const float*)d_in[5];
    const float* b_proj = (const float*)d_in[6];
    float* out = (float*)d_out;

    float* qkv_p;
    __nv_bfloat16 *xnh, *xnl, *ath, *atl, *wqh, *wql, *wph, *wpl;
    cudaGetSymbolAddress((void**)&qkv_p, g_qkv);
    cudaGetSymbolAddress((void**)&xnh, g_xnT_h);
    cudaGetSymbolAddress((void**)&xnl, g_xnT_l);
    cudaGetSymbolAddress((void**)&ath, g_attT_h);
    cudaGetSymbolAddress((void**)&atl, g_attT_l);
    cudaGetSymbolAddress((void**)&wqh, g_wq_h);
    cudaGetSymbolAddress((void**)&wql, g_wq_l);
    cudaGetSymbolAddress((void**)&wph, g_wp_h);
    cudaGetSymbolAddress((void**)&wpl, g_wp_l);

    // weight splits + GN
    split_kernel<<<(3*CC*CC + 255)/256, 256>>>(w_qkv, wqh, wql, 3*CC*CC);
    split_kernel<<<(CC*CC + 255)/256, 256>>>(w_proj, wph, wpl, CC*CC);
    gn_stats_kernel<<<BB*GG, 256>>>(x);
    gn_norm_t_kernel<<<dim3(LL/64, CC/64, BB), 256>>>(x, gamma, beta);

    // QKV projection (mma.sync): M=1536, K=512
    const int gemm_smem = 2 * STAGE_B;
    cudaFuncSetAttribute(gemm_mma_kernel<false>, cudaFuncAttributeMaxDynamicSharedMemorySize, gemm_smem);
    cudaFuncSetAttribute(gemm_mma_kernel<true>,  cudaFuncAttributeMaxDynamicSharedMemorySize, gemm_smem);
    gemm_mma_kernel<false><<<dim3(LL/128, (3*CC)/128, BB), 256, gemm_smem>>>(
        wqh, wql, xnh, xnl, b_qkv, nullptr, qkv_p, 3*CC, CC);

    // convert qkv fp32 -> bf16 hi/lo operand layouts
    qkT_convert_kernel<<<dim3(LL/64, 2*CC/64, BB), 256>>>();
    v_convert_kernel<<<(BB*CC*LL/4)/256, 256>>>();

    // attention (mma.sync, 3-term split)
    cudaFuncSetAttribute(attn_mma_kernel, cudaFuncAttributeMaxDynamicSharedMemorySize, ATTN_SMEM);
    attn_mma_kernel<<<dim3(LL/64, NH, BB), 256, ATTN_SMEM>>>();

    // Output projection + residual (mma.sync): M=512, K=512
    gemm_mma_kernel<true><<<dim3(LL/128, CC/128, BB), 256, gemm_smem>>>(
        wph, wpl, ath, atl, b_proj, x, out, CC, CC);
}

// round 7
// speedup vs baseline: 2.2759x; 1.5253x over previous
#include <cuda_runtime.h>
#include <cuda_bf16.h>
#include <cstdint>
#include <math.h>

#define BB 16
#define CC 512
#define LL 1024       // h*w
#define GG 8
#define CPG 64        // channels per group
#define NH 4
#define HD 128
#define EPS_GN 1e-5f
#define QK_SCALE 0.08838834764831845f

// ---------------------------------------------------------------------------
// Scratch (device globals: no allocation allowed)
// ---------------------------------------------------------------------------
__device__ float g_qkv[(size_t)BB*3*CC*LL];               // 96 MB fp32
__device__ __nv_bfloat16 g_xnT_h[(size_t)BB*LL*CC];       // xn^T hi  [b][l][c]
__device__ __nv_bfloat16 g_xnT_l[(size_t)BB*LL*CC];
__device__ __nv_bfloat16 g_attT_h[(size_t)BB*LL*CC];      // att^T hi [b][l][c]
__device__ __nv_bfloat16 g_attT_l[(size_t)BB*LL*CC];
__device__ __nv_bfloat16 g_wq_h[(size_t)3*CC*CC], g_wq_l[(size_t)3*CC*CC];
__device__ __nv_bfloat16 g_wp_h[(size_t)CC*CC],   g_wp_l[(size_t)CC*CC];
// attention operands
__device__ __nv_bfloat16 g_qt_h[(size_t)BB*NH*LL*HD], g_qt_l[(size_t)BB*NH*LL*HD]; // [b][h][l][d]
__device__ __nv_bfloat16 g_kt_h[(size_t)BB*NH*LL*HD], g_kt_l[(size_t)BB*NH*LL*HD]; // [b][h][l][d]
__device__ __nv_bfloat16 g_v_h [(size_t)BB*NH*HD*LL], g_v_l [(size_t)BB*NH*HD*LL]; // [b][h][d][l]
__device__ float g_mean[BB*GG];
__device__ float g_rstd[BB*GG];

// ---------------------------------------------------------------------------
// helpers
// ---------------------------------------------------------------------------
__device__ __forceinline__ uint32_t smem_u32(const void* p) {
    uint32_t a;
    asm("{ .reg .u64 t; cvta.to.shared.u64 t, %1; cvt.u32.u64 %0, t; }" : "=r"(a) : "l"(p));
    return a;
}
__device__ __forceinline__ void mma16816(float* c, const uint32_t* a, const uint32_t* b) {
    asm volatile(
        "mma.sync.aligned.m16n8k16.row.col.f32.bf16.bf16.f32 "
        "{%0,%1,%2,%3}, {%4,%5,%6,%7}, {%8,%9}, {%0,%1,%2,%3};"
        : "+f"(c[0]), "+f"(c[1]), "+f"(c[2]), "+f"(c[3])
        : "r"(a[0]), "r"(a[1]), "r"(a[2]), "r"(a[3]), "r"(b[0]), "r"(b[1]));
}
__device__ __forceinline__ void split2(float a, float b, uint32_t& hi, uint32_t& lo) {
    __nv_bfloat16 ha = __float2bfloat16(a), hb = __float2bfloat16(b);
    float ra = a - __bfloat162float(ha), rb = b - __bfloat162float(hb);
    __nv_bfloat162 th(ha, hb), tl(__float2bfloat16(ra), __float2bfloat16(rb));
    hi = *(uint32_t*)&th; lo = *(uint32_t*)&tl;
}
__device__ __forceinline__ void cp16(uint32_t s, const void* g) {
    asm volatile("cp.async.cg.shared.global [%0], [%1], 16;" :: "r"(s), "l"(g) : "memory");
}
#define CP_COMMIT() asm volatile("cp.async.commit_group;" ::: "memory")
#define CP_WAIT0()  asm volatile("cp.async.wait_group 0;" ::: "memory")

// ---------------------------------------------------------------------------
// GroupNorm statistics
// ---------------------------------------------------------------------------
__global__ void __launch_bounds__(256) gn_stats_kernel(const float* __restrict__ x) {
    int bg = blockIdx.x;
    int b = bg / GG, g = bg % GG;
    const float4* p = (const float4*)(x + ((size_t)b*CC + (size_t)g*CPG) * LL);
    const int n4 = CPG * LL / 4;
    float s = 0.f, sq = 0.f;
    for (int i = threadIdx.x; i < n4; i += 256) {
        float4 v = p[i];
        s  += v.x + v.y + v.z + v.w;
        sq += v.x*v.x + v.y*v.y + v.z*v.z + v.w*v.w;
    }
    __shared__ float ss[256], sq_s[256];
    ss[threadIdx.x] = s; sq_s[threadIdx.x] = sq;
    __syncthreads();
    for (int o = 128; o > 0; o >>= 1) {
        if (threadIdx.x < o) { ss[threadIdx.x] += ss[threadIdx.x+o]; sq_s[threadIdx.x] += sq_s[threadIdx.x+o]; }
        __syncthreads();
    }
    if (threadIdx.x == 0) {
        const float invN = 1.0f / (float)(CPG * LL);
        float mean = ss[0] * invN;
        float var  = sq_s[0] * invN - mean * mean;
        g_mean[bg] = mean;
        g_rstd[bg] = rsqrtf(var + EPS_GN);
    }
}

// ---------------------------------------------------------------------------
// GroupNorm apply + transpose + bf16 split: x[b][c][l] -> xnT_{h,l}[b][l][c]
// ---------------------------------------------------------------------------
__global__ void __launch_bounds__(256) gn_norm_t_kernel(const float* __restrict__ x,
                                                        const float* __restrict__ gamma,
                                                        const float* __restrict__ beta) {
    const int b  = blockIdx.z;
    const int c0 = blockIdx.y * 64;
    const int l0 = blockIdx.x * 64;
    const int gidx = b * GG + c0 / CPG;
    const float mean = g_mean[gidx], rstd = g_rstd[gidx];

    __shared__ float t[64][65];
    for (int idx = threadIdx.x; idx < 1024; idx += 256) {
        int i  = idx >> 4;
        int j4 = (idx & 15) * 4;
        int c = c0 + i;
        float ga = gamma[c] * rstd;
        float be = beta[c] - mean * ga;
        float4 v = *(const float4*)(x + ((size_t)b*CC + c)*LL + l0 + j4);
        t[j4+0][i] = v.x*ga + be; t[j4+1][i] = v.y*ga + be;
        t[j4+2][i] = v.z*ga + be; t[j4+3][i] = v.w*ga + be;
    }
    __syncthreads();
    for (int idx = threadIdx.x; idx < 1024; idx += 256) {
        int l  = idx >> 4;
        int cq = (idx & 15) * 4;
        __nv_bfloat16 h[4], lo[4];
        #pragma unroll
        for (int q = 0; q < 4; q++) {
            float v = t[l][cq + q];
            h[q]  = __float2bfloat16(v);
            lo[q] = __float2bfloat16(v - __bfloat162float(h[q]));
        }
        size_t o = ((size_t)b*LL + l0 + l) * CC + c0 + cq;
        *(uint2*)(g_xnT_h + o) = *(uint2*)h;
        *(uint2*)(g_xnT_l + o) = *(uint2*)lo;
    }
}

// ---------------------------------------------------------------------------
// Weight fp32 -> bf16 hi/lo split
// ---------------------------------------------------------------------------
__global__ void __launch_bounds__(256) split_kernel(const float* __restrict__ src,
                                                    __nv_bfloat16* __restrict__ hi,
                                                    __nv_bfloat16* __restrict__ lo, int n) {
    int i = blockIdx.x * 256 + threadIdx.x;
    if (i < n) {
        float v = src[i];
        __nv_bfloat16 h = __float2bfloat16(v);
        hi[i] = h;
        lo[i] = __float2bfloat16(v - __bfloat162float(h));
    }
}

// ---------------------------------------------------------------------------
// QKV post-pass A: q,k channels -> transposed hi/lo [b][h][l][d], Q scaled
// ---------------------------------------------------------------------------
__global__ void __launch_bounds__(256) qkT_convert_kernel() {
    const int b  = blockIdx.z;
    const int c0 = blockIdx.y * 64;
    const int l0 = blockIdx.x * 64;
    const bool isQ = c0 < CC;
    const int cq = isQ ? c0 : c0 - CC;
    const int h  = cq / HD;
    const int d0 = cq % HD;
    const float scale = isQ ? QK_SCALE : 1.f;

    const float* in = g_qkv + ((size_t)b*3*CC + c0) * LL;
    __shared__ float t[64][65];
    for (int idx = threadIdx.x; idx < 1024; idx += 256) {
        int i  = idx >> 4;
        int j4 = (idx & 15) * 4;
        float4 v = *(const float4*)(in + (size_t)i * LL + l0 + j4);
        t[j4+0][i] = v.x*scale; t[j4+1][i] = v.y*scale;
        t[j4+2][i] = v.z*scale; t[j4+3][i] = v.w*scale;
    }
    __syncthreads();
    __nv_bfloat16* dh = (isQ ? g_qt_h : g_kt_h) + (size_t)(b*NH + h) * LL * HD;
    __nv_bfloat16* dl = (isQ ? g_qt_l : g_kt_l) + (size_t)(b*NH + h) * LL * HD;
    for (int idx = threadIdx.x; idx < 1024; idx += 256) {
        int l  = idx >> 4;
        int dq = (idx & 15) * 4;
        __nv_bfloat16 hh[4], lo[4];
        #pragma unroll
        for (int q = 0; q < 4; q++) {
            float v = t[l][dq + q];
            hh[q] = __float2bfloat16(v);
            lo[q] = __float2bfloat16(v - __bfloat162float(hh[q]));
        }
        size_t o = (size_t)(l0 + l) * HD + d0 + dq;
        *(uint2*)(dh + o) = *(uint2*)hh;
        *(uint2*)(dl + o) = *(uint2*)lo;
    }
}

// ---------------------------------------------------------------------------
// QKV post-pass B: v channels elementwise split [b][h][d][l]
// ---------------------------------------------------------------------------
__global__ void __launch_bounds__(256) v_convert_kernel() {
    const int n4 = CC * LL / 4;
    int i = blockIdx.x * 256 + threadIdx.x;
    int b = i / n4, r = i % n4;
    float4 v = ((const float4*)(g_qkv + ((size_t)b*3*CC + 2*CC) * LL))[r];
    __nv_bfloat16 hh[4], lo[4];
    float vv[4] = {v.x, v.y, v.z, v.w};
    #pragma unroll
    for (int q = 0; q < 4; q++) {
        hh[q] = __float2bfloat16(vv[q]);
        lo[q] = __float2bfloat16(vv[q] - __bfloat162float(hh[q]));
    }
    size_t o = (size_t)b * CC * LL + (size_t)r * 4;
    *(uint2*)(g_v_h + o) = *(uint2*)hh;
    *(uint2*)(g_v_l + o) = *(uint2*)lo;
}

// ---------------------------------------------------------------------------
// mma.sync bf16 split GEMM (cp.async loader)
// ---------------------------------------------------------------------------
#define TILE_B 10240
#define STAGE_B 40960
template<bool RES>
__global__ void __launch_bounds__(256) gemm_mma_kernel(
        const __nv_bfloat16* __restrict__ Ah, const __nv_bfloat16* __restrict__ Al,
        const __nv_bfloat16* __restrict__ Bh_all, const __nv_bfloat16* __restrict__ Bl_all,
        const float* __restrict__ bias, const float* __restrict__ res,
        float* __restrict__ out, int M, int K) {
    extern __shared__ char smc[];
    const uint32_t sbase = smem_u32(smc);
    const int tid = threadIdx.x;
    const int wid = tid >> 5;
    const int lane = tid & 31;
    const int g  = lane >> 2;
    const int tg = lane & 3;
    const int wm = wid >> 2;
    const int wn = wid & 3;
    const int b  = blockIdx.z;
    const int m0 = blockIdx.y * 128;
    const int n0 = blockIdx.x * 128;

    const __nv_bfloat16* Bh = Bh_all + (size_t)b * LL * CC;
    const __nv_bfloat16* Bl = Bl_all + (size_t)b * LL * CC;

    auto load_chunk = [&](int k0, int stage) {
        uint32_t st = sbase + stage * STAGE_B;
        #pragma unroll
        for (int i = 0; i < 8; i++) {
            int idx = tid + i * 256;
            int t = idx >> 9;
            int r = (idx >> 2) & 127;
            int u = idx & 3;
            const __nv_bfloat16* src;
            if (t == 0)      src = Ah + (size_t)(m0 + r) * K + k0 + u * 8;
            else if (t == 1) src = Al + (size_t)(m0 + r) * K + k0 + u * 8;
            else if (t == 2) src = Bh + (size_t)(n0 + r) * K + k0 + u * 8;
            else             src = Bl + (size_t)(n0 + r) * K + k0 + u * 8;
            cp16(st + t * TILE_B + r * 80 + u * 16, src);
        }
    };

    float acc[4][4][4];
    #pragma unroll
    for (int i = 0; i < 4; i++)
        #pragma unroll
        for (int j = 0; j < 4; j++)
            #pragma unroll
            for (int q = 0; q < 4; q++) acc[i][j][q] = 0.f;

    load_chunk(0, 0);
    CP_COMMIT();

    const int NCH = K / 32;
    for (int c = 0; c < NCH; c++) {
        CP_WAIT0();
        __syncthreads();
        if (c + 1 < NCH) { load_chunk((c + 1) * 32, (c + 1) & 1); CP_COMMIT(); }

        const char* st = smc + (c & 1) * STAGE_B;
        const char* pAh = st;
        const char* pAl = st + TILE_B;
        const char* pBh = st + 2 * TILE_B;
        const char* pBl = st + 3 * TILE_B;

        #pragma unroll
        for (int kk = 0; kk < 32; kk += 16) {
            const int kb = (kk + tg * 2) * 2;
            uint32_t bh[4][2], bl[4][2];
            #pragma unroll
            for (int nt = 0; nt < 4; nt++) {
                int off = (wn * 32 + nt * 8 + g) * 80 + kb;
                bh[nt][0] = *(const uint32_t*)(pBh + off);
                bh[nt][1] = *(const uint32_t*)(pBh + off + 16);
                bl[nt][0] = *(const uint32_t*)(pBl + off);
                bl[nt][1] = *(const uint32_t*)(pBl + off + 16);
            }
            #pragma unroll
            for (int mt = 0; mt < 4; mt++) {
                int ro0 = (wm * 64 + mt * 16 + g) * 80 + kb;
                int ro1 = ro0 + 8 * 80;
                uint32_t ah[4], al[4];
                ah[0] = *(const uint32_t*)(pAh + ro0);
                ah[1] = *(const uint32_t*)(pAh + ro1);
                ah[2] = *(const uint32_t*)(pAh + ro0 + 16);
                ah[3] = *(const uint32_t*)(pAh + ro1 + 16);
                al[0] = *(const uint32_t*)(pAl + ro0);
                al[1] = *(const uint32_t*)(pAl + ro1);
                al[2] = *(const uint32_t*)(pAl + ro0 + 16);
                al[3] = *(const uint32_t*)(pAl + ro1 + 16);
                #pragma unroll
                for (int nt = 0; nt < 4; nt++) {
                    mma16816(acc[mt][nt], ah, bh[nt]);
                    mma16816(acc[mt][nt], al, bh[nt]);
                    mma16816(acc[mt][nt], ah, bl[nt]);
                }
            }
        }
        __syncthreads();
    }

    #pragma unroll
    for (int mt = 0; mt < 4; mt++) {
        int r0 = m0 + wm * 64 + mt * 16 + g;
        int r1 = r0 + 8;
        float bv0 = bias[r0], bv1 = bias[r1];
        #pragma unroll
        for (int nt = 0; nt < 4; nt++) {
            int col = n0 + wn * 32 + nt * 8 + tg * 2;
            float2 o0 = make_float2(acc[mt][nt][0] + bv0, acc[mt][nt][1] + bv0);
            float2 o1 = make_float2(acc[mt][nt][2] + bv1, acc[mt][nt][3] + bv1);
            size_t off0 = ((size_t)b * M + r0) * LL + col;
            size_t off1 = ((size_t)b * M + r1) * LL + col;
            if (RES) {
                float2 q0 = *(const float2*)(res + off0);
                float2 q1 = *(const float2*)(res + off1);
                o0.x += q0.x; o0.y += q0.y; o1.x += q1.x; o1.y += q1.y;
            }
            *(float2*)(out + off0) = o0;
            *(float2*)(out + off1) = o1;
        }
    }
}

// ---------------------------------------------------------------------------
// Flash attention, register-resident softmax + P (no P smem round trip).
// CTA = (128 q-rows, h, b), 256 threads; warp owns 16 q-rows (full k-range).
// Q persistent in smem; K/V double-buffered via cp.async.
// ---------------------------------------------------------------------------
#define QSTR 272     // 256B row + 16 pad
#define VSTR 144     // 128B row + 16 pad
#define AQ_OFF 0                    // Qh 128x272=34816, Ql +34816   (69632)
#define AK_OFF 69632                // stage: 34816 (Kh 17408 + Kl)  x2
#define AV_OFF 139264               // stage: 36864 (Vh 18432 + Vl)  x2
#define ATTN_SMEM 212992

__global__ void __launch_bounds__(256) attn_mma_kernel() {
    extern __shared__ char smc[];
    const uint32_t sbase = smem_u32(smc);
    const int tid = threadIdx.x;
    const int wid = tid >> 5;
    const int lane = tid & 31;
    const int g  = lane >> 2;
    const int tg = lane & 3;
    const int lq0 = blockIdx.x * 128;
    const int h   = blockIdx.y;
    const int b   = blockIdx.z;
    const int wq0 = wid * 16;

    const size_t bh_ld = (size_t)(b * NH + h) * LL * HD;
    const __nv_bfloat16* qth = g_qt_h + bh_ld + (size_t)lq0 * HD;
    const __nv_bfloat16* qtl = g_qt_l + bh_ld + (size_t)lq0 * HD;
    const __nv_bfloat16* kth = g_kt_h + bh_ld;
    const __nv_bfloat16* ktl = g_kt_l + bh_ld;
    const __nv_bfloat16* vhp = g_v_h + bh_ld;    // [d][l]
    const __nv_bfloat16* vlp = g_v_l + bh_ld;

    auto load_kv = [&](int lk0, int s) {
        uint32_t kb = sbase + AK_OFF + s * 34816;
        uint32_t vb = sbase + AV_OFF + s * 36864;
        #pragma unroll
        for (int i = 0; i < 8; i++) {
            int idx = tid + i * 256;                 // 0..2047
            int t = idx >> 10, r = (idx >> 4) & 63, u = idx & 15;
            cp16(kb + t * 17408 + r * QSTR + u * 16,
                 (t ? ktl : kth) + (size_t)(lk0 + r) * HD + u * 8);
        }
        #pragma unroll
        for (int i = 0; i < 8; i++) {
            int idx = tid + i * 256;
            int t = idx >> 10, r = (idx >> 3) & 127, u = idx & 7;
            cp16(vb + t * 18432 + r * VSTR + u * 16,
                 (t ? vlp : vhp) + (size_t)r * LL + lk0 + u * 8);
        }
    };

    // initial group: Q (hi+lo) + K/V stage 0
    #pragma unroll
    for (int i = 0; i < 16; i++) {
        int idx = tid + i * 256;                     // 0..4095
        int t = idx >> 11, r = (idx >> 4) & 127, u = idx & 15;
        cp16(sbase + AQ_OFF + t * 34816 + r * QSTR + u * 16,
             (t ? qtl : qth) + (size_t)r * HD + u * 8);
    }
    load_kv(0, 0);
    CP_COMMIT();

    float rm0 = -1e30f, rm1 = -1e30f, rs0 = 0.f, rs1 = 0.f;
    float accO[16][4];
    #pragma unroll
    for (int i = 0; i < 16; i++)
        #pragma unroll
        for (int q = 0; q < 4; q++) accO[i][q] = 0.f;

    const char* Qh = smc + AQ_OFF;
    const char* Ql = Qh + 34816;

    for (int it = 0; it < 16; it++) {
        const int st = it & 1;
        CP_WAIT0();
        __syncthreads();
        if (it + 1 < 16) { load_kv((it + 1) * 64, st ^ 1); CP_COMMIT(); }

        // ---- S = Q K^T (3-term split), warp tile 16q x 64k ----
        float accS[8][4];
        #pragma unroll
        for (int i = 0; i < 8; i++)
            #pragma unroll
            for (int q = 0; q < 4; q++) accS[i][q] = 0.f;
        {
            const char* Kh = smc + AK_OFF + st * 34816;
            const char* Kl = Kh + 17408;
            #pragma unroll
            for (int ks = 0; ks < 8; ks++) {
                int kbyte = ks * 32 + tg * 4;
                int ro0 = (wq0 + g) * QSTR + kbyte, ro1 = ro0 + 8 * QSTR;
                uint32_t ah[4], al[4];
                ah[0] = *(const uint32_t*)(Qh + ro0);
                ah[1] = *(const uint32_t*)(Qh + ro1);
                ah[2] = *(const uint32_t*)(Qh + ro0 + 16);
                ah[3] = *(const uint32_t*)(Qh + ro1 + 16);
                al[0] = *(const uint32_t*)(Ql + ro0);
                al[1] = *(const uint32_t*)(Ql + ro1);
                al[2] = *(const uint32_t*)(Ql + ro0 + 16);
                al[3] = *(const uint32_t*)(Ql + ro1 + 16);
                #pragma unroll
                for (int nt = 0; nt < 8; nt++) {
                    int bo = (nt * 8 + g) * QSTR + kbyte;
                    uint32_t bh[2] = {*(const uint32_t*)(Kh + bo),
                                      *(const uint32_t*)(Kh + bo + 16)};
                    uint32_t bl[2] = {*(const uint32_t*)(Kl + bo),
                                      *(const uint32_t*)(Kl + bo + 16)};
                    mma16816(accS[nt], ah, bh);
                    mma16816(accS[nt], al, bh);
                    mma16816(accS[nt], ah, bl);
                }
            }
        }

        // ---- online softmax, fully in registers (rows g, g+8) ----
        float m0 = -1e30f, m1 = -1e30f;
        #pragma unroll
        for (int nt = 0; nt < 8; nt++) {
            m0 = fmaxf(m0, fmaxf(accS[nt][0], accS[nt][1]));
            m1 = fmaxf(m1, fmaxf(accS[nt][2], accS[nt][3]));
        }
        m0 = fmaxf(m0, __shfl_xor_sync(0xffffffff, m0, 1));
        m0 = fmaxf(m0, __shfl_xor_sync(0xffffffff, m0, 2));
        m1 = fmaxf(m1, __shfl_xor_sync(0xffffffff, m1, 1));
        m1 = fmaxf(m1, __shfl_xor_sync(0xffffffff, m1, 2));
        float nm0 = fmaxf(rm0, m0), nm1 = fmaxf(rm1, m1);
        float al0 = __expf(rm0 - nm0), al1 = __expf(rm1 - nm1);
        rm0 = nm0; rm1 = nm1;

        // exp + pack P into PV A-fragments (hi/lo), accumulate sums
        uint32_t pah[4][4], pal[4][4];
        float s0 = 0.f, s1 = 0.f;
        #pragma unroll
        for (int kk = 0; kk < 4; kk++) {
            float p00 = __expf(accS[2*kk][0] - nm0);
            float p01 = __expf(accS[2*kk][1] - nm0);
            float p10 = __expf(accS[2*kk][2] - nm1);
            float p11 = __expf(accS[2*kk][3] - nm1);
            float q00 = __expf(accS[2*kk+1][0] - nm0);
            float q01 = __expf(accS[2*kk+1][1] - nm0);
            float q10 = __expf(accS[2*kk+1][2] - nm1);
            float q11 = __expf(accS[2*kk+1][3] - nm1);
            s0 += p00 + p01 + q00 + q01;
            s1 += p10 + p11 + q10 + q11;
            split2(p00, p01, pah[kk][0], pal[kk][0]);
            split2(p10, p11, pah[kk][1], pal[kk][1]);
            split2(q00, q01, pah[kk][2], pal[kk][2]);
            split2(q10, q11, pah[kk][3], pal[kk][3]);
        }
        s0 += __shfl_xor_sync(0xffffffff, s0, 1);
        s0 += __shfl_xor_sync(0xffffffff, s0, 2);
        s1 += __shfl_xor_sync(0xffffffff, s1, 1);
        s1 += __shfl_xor_sync(0xffffffff, s1, 2);
        rs0 = rs0 * al0 + s0;
        rs1 = rs1 * al1 + s1;

        // rescale O
        #pragma unroll
        for (int nt = 0; nt < 16; nt++) {
            accO[nt][0] *= al0; accO[nt][1] *= al0;
            accO[nt][2] *= al1; accO[nt][3] *= al1;
        }

        // ---- O += P V (3-term split), warp tile 16q x 128d ----
        {
            const char* Vh = smc + AV_OFF + st * 36864;
            const char* Vl = Vh + 18432;
            #pragma unroll
            for (int kk = 0; kk < 4; kk++) {
                #pragma unroll
                for (int nt = 0; nt < 16; nt++) {
                    int bo = (nt * 8 + g) * VSTR + kk * 32 + tg * 4;
                    uint32_t bh[2] = {*(const uint32_t*)(Vh + bo),
                                      *(const uint32_t*)(Vh + bo + 16)};
                    uint32_t bl[2] = {*(const uint32_t*)(Vl + bo),
                                      *(const uint32_t*)(Vl + bo + 16)};
                    mma16816(accO[nt], pah[kk], bh);
                    mma16816(accO[nt], pal[kk], bh);
                    mma16816(accO[nt], pah[kk], bl);
                }
            }
        }
    }

    // ---- epilogue: normalize, split, store att^T[b][l][c] hi/lo ----
    float inv0 = 1.0f / rs0, inv1 = 1.0f / rs1;
    int ra = lq0 + wq0 + g, rb = ra + 8;
    #pragma unroll
    for (int nt = 0; nt < 16; nt++) {
        int dcol = h * HD + nt * 8 + tg * 2;
        uint32_t hi, lo;
        size_t oa = ((size_t)b * LL + ra) * CC + dcol;
        split2(accO[nt][0] * inv0, accO[nt][1] * inv0, hi, lo);
        *(uint32_t*)(g_attT_h + oa) = hi;
        *(uint32_t*)(g_attT_l + oa) = lo;
        size_t ob = ((size_t)b * LL + rb) * CC + dcol;
        split2(accO[nt][2] * inv1, accO[nt][3] * inv1, hi, lo);
        *(uint32_t*)(g_attT_h + ob) = hi;
        *(uint32_t*)(g_attT_l + ob) = lo;
    }
}

// ---------------------------------------------------------------------------
extern "C" void kernel_launch(void* const* d_in, const int* in_sizes, int n_in,
                              void* d_out, int out_size) {
    const float* x      = (const float*)d_in[0];
    const float* gamma  = (const float*)d_in[1];
    const float* beta   = (const float*)d_in[2];
    const float* w_qkv  = (const float*)d_in[3];
    const float* b_qkv  = (const float*)d_in[4];
    const float* w_proj = (const float*)d_in[5];
    const float* b_proj = (const float*)d_in[6];
    float* out = (float*)d_out;

    float* qkv_p;
    __nv_bfloat16 *xnh, *xnl, *ath, *atl, *wqh, *wql, *wph, *wpl;
    cudaGetSymbolAddress((void**)&qkv_p, g_qkv);
    cudaGetSymbolAddress((void**)&xnh, g_xnT_h);
    cudaGetSymbolAddress((void**)&xnl, g_xnT_l);
    cudaGetSymbolAddress((void**)&ath, g_attT_h);
    cudaGetSymbolAddress((void**)&atl, g_attT_l);
    cudaGetSymbolAddress((void**)&wqh, g_wq_h);
    cudaGetSymbolAddress((void**)&wql, g_wq_l);
    cudaGetSymbolAddress((void**)&wph, g_wp_h);
    cudaGetSymbolAddress((void**)&wpl, g_wp_l);

    // weight splits + GN
    split_kernel<<<(3*CC*CC + 255)/256, 256>>>(w_qkv, wqh, wql, 3*CC*CC);
    split_kernel<<<(CC*CC + 255)/256, 256>>>(w_proj, wph, wpl, CC*CC);
    gn_stats_kernel<<<BB*GG, 256>>>(x);
    gn_norm_t_kernel<<<dim3(LL/64, CC/64, BB), 256>>>(x, gamma, beta);

    // QKV projection (mma.sync): M=1536, K=512
    const int gemm_smem = 2 * STAGE_B;
    cudaFuncSetAttribute(gemm_mma_kernel<false>, cudaFuncAttributeMaxDynamicSharedMemorySize, gemm_smem);
    cudaFuncSetAttribute(gemm_mma_kernel<true>,  cudaFuncAttributeMaxDynamicSharedMemorySize, gemm_smem);
    gemm_mma_kernel<false><<<dim3(LL/128, (3*CC)/128, BB), 256, gemm_smem>>>(
        wqh, wql, xnh, xnl, b_qkv, nullptr, qkv_p, 3*CC, CC);

    // convert qkv fp32 -> bf16 hi/lo operand layouts
    qkT_convert_kernel<<<dim3(LL/64, 2*CC/64, BB), 256>>>();
    v_convert_kernel<<<(BB*CC*LL/4)/256, 256>>>();

    // attention (mma.sync, register softmax)
    cudaFuncSetAttribute(attn_mma_kernel, cudaFuncAttributeMaxDynamicSharedMemorySize, ATTN_SMEM);
    attn_mma_kernel<<<dim3(LL/128, NH, BB), 256, ATTN_SMEM>>>();

    // Output projection + residual (mma.sync): M=512, K=512
    gemm_mma_kernel<true><<<dim3(LL/128, CC/128, BB), 256, gemm_smem>>>(
        wph, wpl, ath, atl, b_proj, x, out, CC, CC);
}

// round 10
// speedup vs baseline: 2.5708x; 1.1295x over previous
#include <cuda_runtime.h>
#include <cuda_bf16.h>
#include <cstdint>
#include <math.h>

#define BB 16
#define CC 512
#define LL 1024       // h*w
#define GG 8
#define CPG 64        // channels per group
#define NH 4
#define HD 128
#define EPS_GN 1e-5f
#define QK_SCALE 0.08838834764831845f

// ---------------------------------------------------------------------------
// Scratch (device globals: no allocation allowed)
// ---------------------------------------------------------------------------
__device__ float g_qkv[(size_t)BB*3*CC*LL];               // 96 MB fp32
__device__ __nv_bfloat16 g_xnT_h[(size_t)BB*LL*CC];       // xn^T hi  [b][l][c]
__device__ __nv_bfloat16 g_xnT_l[(size_t)BB*LL*CC];
__device__ __nv_bfloat16 g_attT_h[(size_t)BB*LL*CC];      // att^T hi [b][l][c]
__device__ __nv_bfloat16 g_attT_l[(size_t)BB*LL*CC];
__device__ __nv_bfloat16 g_wq_h[(size_t)3*CC*CC], g_wq_l[(size_t)3*CC*CC];
__device__ __nv_bfloat16 g_wp_h[(size_t)CC*CC],   g_wp_l[(size_t)CC*CC];
// attention operands
__device__ __nv_bfloat16 g_qt_h[(size_t)BB*NH*LL*HD], g_qt_l[(size_t)BB*NH*LL*HD]; // [b][h][l][d]
__device__ __nv_bfloat16 g_kt_h[(size_t)BB*NH*LL*HD], g_kt_l[(size_t)BB*NH*LL*HD]; // [b][h][l][d]
__device__ __nv_bfloat16 g_v_h [(size_t)BB*NH*HD*LL], g_v_l [(size_t)BB*NH*HD*LL]; // [b][h][d][l]
__device__ float g_mean[BB*GG];
__device__ float g_rstd[BB*GG];

// ---------------------------------------------------------------------------
// helpers
// ---------------------------------------------------------------------------
__device__ __forceinline__ uint32_t smem_u32(const void* p) {
    uint32_t a;
    asm("{ .reg .u64 t; cvta.to.shared.u64 t, %1; cvt.u32.u64 %0, t; }" : "=r"(a) : "l"(p));
    return a;
}
__device__ __forceinline__ void mma16816(float* c, const uint32_t* a, const uint32_t* b) {
    asm volatile(
        "mma.sync.aligned.m16n8k16.row.col.f32.bf16.bf16.f32 "
        "{%0,%1,%2,%3}, {%4,%5,%6,%7}, {%8,%9}, {%0,%1,%2,%3};"
        : "+f"(c[0]), "+f"(c[1]), "+f"(c[2]), "+f"(c[3])
        : "r"(a[0]), "r"(a[1]), "r"(a[2]), "r"(a[3]), "r"(b[0]), "r"(b[1]));
}
__device__ __forceinline__ void ldm4(uint32_t* r, uint32_t a) {
    asm volatile("ldmatrix.sync.aligned.m8n8.x4.shared.b16 {%0,%1,%2,%3}, [%4];"
        : "=r"(r[0]), "=r"(r[1]), "=r"(r[2]), "=r"(r[3]) : "r"(a));
}
__device__ __forceinline__ void split2(float a, float b, uint32_t& hi, uint32_t& lo) {
    __nv_bfloat16 ha = __float2bfloat16(a), hb = __float2bfloat16(b);
    float ra = a - __bfloat162float(ha), rb = b - __bfloat162float(hb);
    __nv_bfloat162 th(ha, hb), tl(__float2bfloat16(ra), __float2bfloat16(rb));
    hi = *(uint32_t*)&th; lo = *(uint32_t*)&tl;
}
__device__ __forceinline__ void cp16(uint32_t s, const void* g) {
    asm volatile("cp.async.cg.shared.global [%0], [%1], 16;" :: "r"(s), "l"(g) : "memory");
}
#define CP_COMMIT() asm volatile("cp.async.commit_group;" ::: "memory")
#define CP_WAIT0()  asm volatile("cp.async.wait_group 0;" ::: "memory")

// ---------------------------------------------------------------------------
// GroupNorm statistics
// ---------------------------------------------------------------------------
__global__ void __launch_bounds__(256) gn_stats_kernel(const float* __restrict__ x) {
    int bg = blockIdx.x;
    int b = bg / GG, g = bg % GG;
    const float4* p = (const float4*)(x + ((size_t)b*CC + (size_t)g*CPG) * LL);
    const int n4 = CPG * LL / 4;
    float s = 0.f, sq = 0.f;
    for (int i = threadIdx.x; i < n4; i += 256) {
        float4 v = p[i];
        s  += v.x + v.y + v.z + v.w;
        sq += v.x*v.x + v.y*v.y + v.z*v.z + v.w*v.w;
    }
    __shared__ float ss[256], sq_s[256];
    ss[threadIdx.x] = s; sq_s[threadIdx.x] = sq;
    __syncthreads();
    for (int o = 128; o > 0; o >>= 1) {
        if (threadIdx.x < o) { ss[threadIdx.x] += ss[threadIdx.x+o]; sq_s[threadIdx.x] += sq_s[threadIdx.x+o]; }
        __syncthreads();
    }
    if (threadIdx.x == 0) {
        const float invN = 1.0f / (float)(CPG * LL);
        float mean = ss[0] * invN;
        float var  = sq_s[0] * invN - mean * mean;
        g_mean[bg] = mean;
        g_rstd[bg] = rsqrtf(var + EPS_GN);
    }
}

// ---------------------------------------------------------------------------
// GroupNorm apply + transpose + bf16 split: x[b][c][l] -> xnT_{h,l}[b][l][c]
// ---------------------------------------------------------------------------
__global__ void __launch_bounds__(256) gn_norm_t_kernel(const float* __restrict__ x,
                                                        const float* __restrict__ gamma,
                                                        const float* __restrict__ beta) {
    const int b  = blockIdx.z;
    const int c0 = blockIdx.y * 64;
    const int l0 = blockIdx.x * 64;
    const int gidx = b * GG + c0 / CPG;
    const float mean = g_mean[gidx], rstd = g_rstd[gidx];

    __shared__ float t[64][65];
    for (int idx = threadIdx.x; idx < 1024; idx += 256) {
        int i  = idx >> 4;
        int j4 = (idx & 15) * 4;
        int c = c0 + i;
        float ga = gamma[c] * rstd;
        float be = beta[c] - mean * ga;
        float4 v = *(const float4*)(x + ((size_t)b*CC + c)*LL + l0 + j4);
        t[j4+0][i] = v.x*ga + be; t[j4+1][i] = v.y*ga + be;
        t[j4+2][i] = v.z*ga + be; t[j4+3][i] = v.w*ga + be;
    }
    __syncthreads();
    for (int idx = threadIdx.x; idx < 1024; idx += 256) {
        int l  = idx >> 4;
        int cq = (idx & 15) * 4;
        __nv_bfloat16 h[4], lo[4];
        #pragma unroll
        for (int q = 0; q < 4; q++) {
            float v = t[l][cq + q];
            h[q]  = __float2bfloat16(v);
            lo[q] = __float2bfloat16(v - __bfloat162float(h[q]));
        }
        size_t o = ((size_t)b*LL + l0 + l) * CC + c0 + cq;
        *(uint2*)(g_xnT_h + o) = *(uint2*)h;
        *(uint2*)(g_xnT_l + o) = *(uint2*)lo;
    }
}

// ---------------------------------------------------------------------------
// Weight fp32 -> bf16 hi/lo split
// ---------------------------------------------------------------------------
__global__ void __launch_bounds__(256) split_kernel(const float* __restrict__ src,
                                                    __nv_bfloat16* __restrict__ hi,
                                                    __nv_bfloat16* __restrict__ lo, int n) {
    int i = blockIdx.x * 256 + threadIdx.x;
    if (i < n) {
        float v = src[i];
        __nv_bfloat16 h = __float2bfloat16(v);
        hi[i] = h;
        lo[i] = __float2bfloat16(v - __bfloat162float(h));
    }
}

// ---------------------------------------------------------------------------
// QKV post-pass A: q,k channels -> transposed hi/lo [b][h][l][d], Q scaled
// ---------------------------------------------------------------------------
__global__ void __launch_bounds__(256) qkT_convert_kernel() {
    const int b  = blockIdx.z;
    const int c0 = blockIdx.y * 64;
    const int l0 = blockIdx.x * 64;
    const bool isQ = c0 < CC;
    const int cq = isQ ? c0 : c0 - CC;
    const int h  = cq / HD;
    const int d0 = cq % HD;
    const float scale = isQ ? QK_SCALE : 1.f;

    const float* in = g_qkv + ((size_t)b*3*CC + c0) * LL;
    __shared__ float t[64][65];
    for (int idx = threadIdx.x; idx < 1024; idx += 256) {
        int i  = idx >> 4;
        int j4 = (idx & 15) * 4;
        float4 v = *(const float4*)(in + (size_t)i * LL + l0 + j4);
        t[j4+0][i] = v.x*scale; t[j4+1][i] = v.y*scale;
        t[j4+2][i] = v.z*scale; t[j4+3][i] = v.w*scale;
    }
    __syncthreads();
    __nv_bfloat16* dh = (isQ ? g_qt_h : g_kt_h) + (size_t)(b*NH + h) * LL * HD;
    __nv_bfloat16* dl = (isQ ? g_qt_l : g_kt_l) + (size_t)(b*NH + h) * LL * HD;
    for (int idx = threadIdx.x; idx < 1024; idx += 256) {
        int l  = idx >> 4;
        int dq = (idx & 15) * 4;
        __nv_bfloat16 hh[4], lo[4];
        #pragma unroll
        for (int q = 0; q < 4; q++) {
            float v = t[l][dq + q];
            hh[q] = __float2bfloat16(v);
            lo[q] = __float2bfloat16(v - __bfloat162float(hh[q]));
        }
        size_t o = (size_t)(l0 + l) * HD + d0 + dq;
        *(uint2*)(dh + o) = *(uint2*)hh;
        *(uint2*)(dl + o) = *(uint2*)lo;
    }
}

// ---------------------------------------------------------------------------
// QKV post-pass B: v channels elementwise split [b][h][d][l]
// ---------------------------------------------------------------------------
__global__ void __launch_bounds__(256) v_convert_kernel() {
    const int n4 = CC * LL / 4;
    int i = blockIdx.x * 256 + threadIdx.x;
    int b = i / n4, r = i % n4;
    float4 v = ((const float4*)(g_qkv + ((size_t)b*3*CC + 2*CC) * LL))[r];
    __nv_bfloat16 hh[4], lo[4];
    float vv[4] = {v.x, v.y, v.z, v.w};
    #pragma unroll
    for (int q = 0; q < 4; q++) {
        hh[q] = __float2bfloat16(vv[q]);
        lo[q] = __float2bfloat16(vv[q] - __bfloat162float(hh[q]));
    }
    size_t o = (size_t)b * CC * LL + (size_t)r * 4;
    *(uint2*)(g_v_h + o) = *(uint2*)hh;
    *(uint2*)(g_v_l + o) = *(uint2*)lo;
}

// ---------------------------------------------------------------------------
// mma.sync bf16 split GEMM (cp.async loader + ldmatrix fragments)
// ---------------------------------------------------------------------------
#define TILE_B 10240
#define STAGE_B 40960
template<bool RES>
__global__ void __launch_bounds__(256) gemm_mma_kernel(
        const __nv_bfloat16* __restrict__ Ah, const __nv_bfloat16* __restrict__ Al,
        const __nv_bfloat16* __restrict__ Bh_all, const __nv_bfloat16* __restrict__ Bl_all,
        const float* __restrict__ bias, const float* __restrict__ res,
        float* __restrict__ out, int M, int K) {
    extern __shared__ char smc[];
    const uint32_t sbase = smem_u32(smc);
    const int tid = threadIdx.x;
    const int wid = tid >> 5;
    const int lane = tid & 31;
    const int g  = lane >> 2;
    const int tg = lane & 3;
    const int wm = wid >> 2;
    const int wn = wid & 3;
    const int b  = blockIdx.z;
    const int m0 = blockIdx.y * 128;
    const int n0 = blockIdx.x * 128;

    const __nv_bfloat16* Bh = Bh_all + (size_t)b * LL * CC;
    const __nv_bfloat16* Bl = Bl_all + (size_t)b * LL * CC;

    auto load_chunk = [&](int k0, int stage) {
        uint32_t st = sbase + stage * STAGE_B;
        #pragma unroll
        for (int i = 0; i < 8; i++) {
            int idx = tid + i * 256;
            int t = idx >> 9;
            int r = (idx >> 2) & 127;
            int u = idx & 3;
            const __nv_bfloat16* src;
            if (t == 0)      src = Ah + (size_t)(m0 + r) * K + k0 + u * 8;
            else if (t == 1) src = Al + (size_t)(m0 + r) * K + k0 + u * 8;
            else if (t == 2) src = Bh + (size_t)(n0 + r) * K + k0 + u * 8;
            else             src = Bl + (size_t)(n0 + r) * K + k0 + u * 8;
            cp16(st + t * TILE_B + r * 80 + u * 16, src);
        }
    };

    // per-thread ldmatrix base offsets
    const uint32_t aOff = (uint32_t)(wm * 64 + (lane & 15)) * 80 + ((lane >> 4) << 4);
    const uint32_t bOff = (uint32_t)(wn * 32 + (lane & 7) + ((lane >> 4) << 3)) * 80
                        + (((lane >> 3) & 1) << 4);

    float acc[4][4][4];
    #pragma unroll
    for (int i = 0; i < 4; i++)
        #pragma unroll
        for (int j = 0; j < 4; j++)
            #pragma unroll
            for (int q = 0; q < 4; q++) acc[i][j][q] = 0.f;

    load_chunk(0, 0);
    CP_COMMIT();

    const int NCH = K / 32;
    for (int c = 0; c < NCH; c++) {
        CP_WAIT0();
        __syncthreads();
        if (c + 1 < NCH) { load_chunk((c + 1) * 32, (c + 1) & 1); CP_COMMIT(); }

        const uint32_t st = sbase + (c & 1) * STAGE_B;

        #pragma unroll
        for (int kk = 0; kk < 2; kk++) {            // two k16 steps
            const uint32_t kb = kk * 32;            // bytes
            uint32_t bfh[2][4], bfl[2][4];          // 2 pairs x (b0,b1,b0',b1')
            #pragma unroll
            for (int p = 0; p < 2; p++) {
                ldm4(bfh[p], st + 2 * TILE_B + bOff + p * 16 * 80 + kb);
                ldm4(bfl[p], st + 3 * TILE_B + bOff + p * 16 * 80 + kb);
            }
            #pragma unroll
            for (int mt = 0; mt < 4; mt++) {
                uint32_t ah[4], al[4];
                ldm4(ah, st + aOff + mt * 16 * 80 + kb);
                ldm4(al, st + TILE_B + aOff + mt * 16 * 80 + kb);
                #pragma unroll
                for (int nt = 0; nt < 4; nt++) {
                    const uint32_t* bh = bfh[nt >> 1] + (nt & 1) * 2;
                    const uint32_t* bl = bfl[nt >> 1] + (nt & 1) * 2;
                    mma16816(acc[mt][nt], ah, bh);
                    mma16816(acc[mt][nt], al, bh);
                    mma16816(acc[mt][nt], ah, bl);
                }
            }
        }
        __syncthreads();
    }

    #pragma unroll
    for (int mt = 0; mt < 4; mt++) {
        int r0 = m0 + wm * 64 + mt * 16 + g;
        int r1 = r0 + 8;
        float bv0 = bias[r0], bv1 = bias[r1];
        #pragma unroll
        for (int nt = 0; nt < 4; nt++) {
            int col = n0 + wn * 32 + nt * 8 + tg * 2;
            float2 o0 = make_float2(acc[mt][nt][0] + bv0, acc[mt][nt][1] + bv0);
            float2 o1 = make_float2(acc[mt][nt][2] + bv1, acc[mt][nt][3] + bv1);
            size_t off0 = ((size_t)b * M + r0) * LL + col;
            size_t off1 = ((size_t)b * M + r1) * LL + col;
            if (RES) {
                float2 q0 = *(const float2*)(res + off0);
                float2 q1 = *(const float2*)(res + off1);
                o0.x += q0.x; o0.y += q0.y; o1.x += q1.x; o1.y += q1.y;
            }
            *(float2*)(out + off0) = o0;
            *(float2*)(out + off1) = o1;
        }
    }
}

// ---------------------------------------------------------------------------
// Flash attention, register softmax + ldmatrix fragments.
// CTA = (128 q-rows, h, b), 256 threads; warp owns 16 q-rows (full k-range).
// ---------------------------------------------------------------------------
#define QSTR 272     // 256B row + 16 pad
#define VSTR 144     // 128B row + 16 pad
#define AQ_OFF 0                    // Qh 128x272=34816, Ql +34816   (69632)
#define AK_OFF 69632                // stage: 34816 (Kh 17408 + Kl)  x2
#define AV_OFF 139264               // stage: 36864 (Vh 18432 + Vl)  x2
#define ATTN_SMEM 212992

__global__ void __launch_bounds__(256) attn_mma_kernel() {
    extern __shared__ char smc[];
    const uint32_t sbase = smem_u32(smc);
    const int tid = threadIdx.x;
    const int wid = tid >> 5;
    const int lane = tid & 31;
    const int g  = lane >> 2;
    const int tg = lane & 3;
    const int lq0 = blockIdx.x * 128;
    const int h   = blockIdx.y;
    const int b   = blockIdx.z;
    const int wq0 = wid * 16;

    const size_t bh_ld = (size_t)(b * NH + h) * LL * HD;
    const __nv_bfloat16* qth = g_qt_h + bh_ld + (size_t)lq0 * HD;
    const __nv_bfloat16* qtl = g_qt_l + bh_ld + (size_t)lq0 * HD;
    const __nv_bfloat16* kth = g_kt_h + bh_ld;
    const __nv_bfloat16* ktl = g_kt_l + bh_ld;
    const __nv_bfloat16* vhp = g_v_h + bh_ld;    // [d][l]
    const __nv_bfloat16* vlp = g_v_l + bh_ld;

    auto load_kv = [&](int lk0, int s) {
        uint32_t kb = sbase + AK_OFF + s * 34816;
        uint32_t vb = sbase + AV_OFF + s * 36864;
        #pragma unroll
        for (int i = 0; i < 8; i++) {
            int idx = tid + i * 256;
            int t = idx >> 10, r = (idx >> 4) & 63, u = idx & 15;
            cp16(kb + t * 17408 + r * QSTR + u * 16,
                 (t ? ktl : kth) + (size_t)(lk0 + r) * HD + u * 8);
        }
        #pragma unroll
        for (int i = 0; i < 8; i++) {
            int idx = tid + i * 256;
            int t = idx >> 10, r = (idx >> 3) & 127, u = idx & 7;
            cp16(vb + t * 18432 + r * VSTR + u * 16,
                 (t ? vlp : vhp) + (size_t)r * LL + lk0 + u * 8);
        }
    };

    // initial group: Q (hi+lo) + K/V stage 0
    #pragma unroll
    for (int i = 0; i < 16; i++) {
        int idx = tid + i * 256;
        int t = idx >> 11, r = (idx >> 4) & 127, u = idx & 15;
        cp16(sbase + AQ_OFF + t * 34816 + r * QSTR + u * 16,
             (t ? qtl : qth) + (size_t)r * HD + u * 8);
    }
    load_kv(0, 0);
    CP_COMMIT();

    float rm0 = -1e30f, rm1 = -1e30f, rs0 = 0.f, rs1 = 0.f;
    float accO[16][4];
    #pragma unroll
    for (int i = 0; i < 16; i++)
        #pragma unroll
        for (int q = 0; q < 4; q++) accO[i][q] = 0.f;

    // per-thread ldmatrix base offsets
    const uint32_t qOff = (uint32_t)(wq0 + (lane & 15)) * QSTR + ((lane >> 4) << 4);
    const uint32_t kOff = (uint32_t)((lane & 7) + ((lane >> 4) << 3)) * QSTR
                        + (((lane >> 3) & 1) << 4);
    const uint32_t vOff = (uint32_t)((lane & 7) + ((lane >> 4) << 3)) * VSTR
                        + (((lane >> 3) & 1) << 4);

    for (int it = 0; it < 16; it++) {
        const int st = it & 1;
        CP_WAIT0();
        __syncthreads();
        if (it + 1 < 16) { load_kv((it + 1) * 64, st ^ 1); CP_COMMIT(); }

        // ---- S = Q K^T (3-term split), warp tile 16q x 64k ----
        float accS[8][4];
        #pragma unroll
        for (int i = 0; i < 8; i++)
            #pragma unroll
            for (int q = 0; q < 4; q++) accS[i][q] = 0.f;
        {
            const uint32_t KhA = sbase + AK_OFF + st * 34816;
            #pragma unroll
            for (int ks = 0; ks < 8; ks++) {
                const uint32_t kb = ks * 32;
                uint32_t ah[4], al[4];
                ldm4(ah, sbase + AQ_OFF + qOff + kb);
                ldm4(al, sbase + AQ_OFF + 34816 + qOff + kb);
                #pragma unroll
                for (int p = 0; p < 4; p++) {
                    uint32_t kh4[4], kl4[4];
                    ldm4(kh4, KhA + kOff + p * 16 * QSTR + kb);
                    ldm4(kl4, KhA + 17408 + kOff + p * 16 * QSTR + kb);
                    #pragma unroll
                    for (int hf = 0; hf < 2; hf++) {
                        mma16816(accS[p*2+hf], ah, kh4 + hf*2);
                        mma16816(accS[p*2+hf], al, kh4 + hf*2);
                        mma16816(accS[p*2+hf], ah, kl4 + hf*2);
                    }
                }
            }
        }

        // ---- online softmax, fully in registers (rows g, g+8) ----
        float m0 = -1e30f, m1 = -1e30f;
        #pragma unroll
        for (int nt = 0; nt < 8; nt++) {
            m0 = fmaxf(m0, fmaxf(accS[nt][0], accS[nt][1]));
            m1 = fmaxf(m1, fmaxf(accS[nt][2], accS[nt][3]));
        }
        m0 = fmaxf(m0, __shfl_xor_sync(0xffffffff, m0, 1));
        m0 = fmaxf(m0, __shfl_xor_sync(0xffffffff, m0, 2));
        m1 = fmaxf(m1, __shfl_xor_sync(0xffffffff, m1, 1));
        m1 = fmaxf(m1, __shfl_xor_sync(0xffffffff, m1, 2));
        float nm0 = fmaxf(rm0, m0), nm1 = fmaxf(rm1, m1);
        float al0 = __expf(rm0 - nm0), al1 = __expf(rm1 - nm1);
        rm0 = nm0; rm1 = nm1;

        uint32_t pah[4][4], pal[4][4];
        float s0 = 0.f, s1 = 0.f;
        #pragma unroll
        for (int kk = 0; kk < 4; kk++) {
            float p00 = __expf(accS[2*kk][0] - nm0);
            float p01 = __expf(accS[2*kk][1] - nm0);
            float p10 = __expf(accS[2*kk][2] - nm1);
            float p11 = __expf(accS[2*kk][3] - nm1);
            float q00 = __expf(accS[2*kk+1][0] - nm0);
            float q01 = __expf(accS[2*kk+1][1] - nm0);
            float q10 = __expf(accS[2*kk+1][2] - nm1);
            float q11 = __expf(accS[2*kk+1][3] - nm1);
            s0 += p00 + p01 + q00 + q01;
            s1 += p10 + p11 + q10 + q11;
            split2(p00, p01, pah[kk][0], pal[kk][0]);
            split2(p10, p11, pah[kk][1], pal[kk][1]);
            split2(q00, q01, pah[kk][2], pal[kk][2]);
            split2(q10, q11, pah[kk][3], pal[kk][3]);
        }
        s0 += __shfl_xor_sync(0xffffffff, s0, 1);
        s0 += __shfl_xor_sync(0xffffffff, s0, 2);
        s1 += __shfl_xor_sync(0xffffffff, s1, 1);
        s1 += __shfl_xor_sync(0xffffffff, s1, 2);
        rs0 = rs0 * al0 + s0;
        rs1 = rs1 * al1 + s1;

        #pragma unroll
        for (int nt = 0; nt < 16; nt++) {
            accO[nt][0] *= al0; accO[nt][1] *= al0;
            accO[nt][2] *= al1; accO[nt][3] *= al1;
        }

        // ---- O += P V (3-term split), warp tile 16q x 128d ----
        {
            const uint32_t VhA = sbase + AV_OFF + st * 36864;
            #pragma unroll
            for (int kk = 0; kk < 4; kk++) {
                const uint32_t kb = kk * 32;
                #pragma unroll
                for (int p = 0; p < 8; p++) {
                    uint32_t vh4[4], vl4[4];
                    ldm4(vh4, VhA + vOff + p * 16 * VSTR + kb);
                    ldm4(vl4, VhA + 18432 + vOff + p * 16 * VSTR + kb);
                    #pragma unroll
                    for (int hf = 0; hf < 2; hf++) {
                        mma16816(accO[p*2+hf], pah[kk], vh4 + hf*2);
                        mma16816(accO[p*2+hf], pal[kk], vh4 + hf*2);
                        mma16816(accO[p*2+hf], pah[kk], vl4 + hf*2);
                    }
                }
            }
        }
    }

    // ---- epilogue: normalize, split, store att^T[b][l][c] hi/lo ----
    float inv0 = 1.0f / rs0, inv1 = 1.0f / rs1;
    int ra = lq0 + wq0 + g, rb = ra + 8;
    #pragma unroll
    for (int nt = 0; nt < 16; nt++) {
        int dcol = h * HD + nt * 8 + tg * 2;
        uint32_t hi, lo;
        size_t oa = ((size_t)b * LL + ra) * CC + dcol;
        split2(accO[nt][0] * inv0, accO[nt][1] * inv0, hi, lo);
        *(uint32_t*)(g_attT_h + oa) = hi;
        *(uint32_t*)(g_attT_l + oa) = lo;
        size_t ob = ((size_t)b * LL + rb) * CC + dcol;
        split2(accO[nt][2] * inv1, accO[nt][3] * inv1, hi, lo);
        *(uint32_t*)(g_attT_h + ob) = hi;
        *(uint32_t*)(g_attT_l + ob) = lo;
    }
}

// ---------------------------------------------------------------------------
extern "C" void kernel_launch(void* const* d_in, const int* in_sizes, int n_in,
                              void* d_out, int out_size) {
    const float* x      = (const float*)d_in[0];
    const float* gamma  = (const float*)d_in[1];
    const float* beta   = (const float*)d_in[2];
    const float* w_qkv  = (const float*)d_in[3];
    const float* b_qkv  = (const float*)d_in[4];
    const float* w_proj = (const float*)d_in[5];
    const float* b_proj = (const float*)d_in[6];
    float* out = (float*)d_out;

    float* qkv_p;
    __nv_bfloat16 *xnh, *xnl, *ath, *atl, *wqh, *wql, *wph, *wpl;
    cudaGetSymbolAddress((void**)&qkv_p, g_qkv);
    cudaGetSymbolAddress((void**)&xnh, g_xnT_h);
    cudaGetSymbolAddress((void**)&xnl, g_xnT_l);
    cudaGetSymbolAddress((void**)&ath, g_attT_h);
    cudaGetSymbolAddress((void**)&atl, g_attT_l);
    cudaGetSymbolAddress((void**)&wqh, g_wq_h);
    cudaGetSymbolAddress((void**)&wql, g_wq_l);
    cudaGetSymbolAddress((void**)&wph, g_wp_h);
    cudaGetSymbolAddress((void**)&wpl, g_wp_l);

    // weight splits + GN
    split_kernel<<<(3*CC*CC + 255)/256, 256>>>(w_qkv, wqh, wql, 3*CC*CC);
    split_kernel<<<(CC*CC + 255)/256, 256>>>(w_proj, wph, wpl, CC*CC);
    gn_stats_kernel<<<BB*GG, 256>>>(x);
    gn_norm_t_kernel<<<dim3(LL/64, CC/64, BB), 256>>>(x, gamma, beta);

    // QKV projection (mma.sync): M=1536, K=512
    const int gemm_smem = 2 * STAGE_B;
    cudaFuncSetAttribute(gemm_mma_kernel<false>, cudaFuncAttributeMaxDynamicSharedMemorySize, gemm_smem);
    cudaFuncSetAttribute(gemm_mma_kernel<true>,  cudaFuncAttributeMaxDynamicSharedMemorySize, gemm_smem);
    gemm_mma_kernel<false><<<dim3(LL/128, (3*CC)/128, BB), 256, gemm_smem>>>(
        wqh, wql, xnh, xnl, b_qkv, nullptr, qkv_p, 3*CC, CC);

    // convert qkv fp32 -> bf16 hi/lo operand layouts
    qkT_convert_kernel<<<dim3(LL/64, 2*CC/64, BB), 256>>>();
    v_convert_kernel<<<(BB*CC*LL/4)/256, 256>>>();

    // attention (mma.sync, register softmax)
    cudaFuncSetAttribute(attn_mma_kernel, cudaFuncAttributeMaxDynamicSharedMemorySize, ATTN_SMEM);
    attn_mma_kernel<<<dim3(LL/128, NH, BB), 256, ATTN_SMEM>>>();

    // Output projection + residual (mma.sync): M=512, K=512
    gemm_mma_kernel<true><<<dim3(LL/128, CC/128, BB), 256, gemm_smem>>>(
        wph, wpl, ath, atl, b_proj, x, out, CC, CC);
}

// round 11
// speedup vs baseline: 2.7273x; 1.0609x over previous
#include <cuda_runtime.h>
#include <cuda_bf16.h>
#include <cstdint>
#include <math.h>

#define BB 16
#define CC 512
#define LL 1024       // h*w
#define GG 8
#define CPG 64        // channels per group
#define NH 4
#define HD 128
#define EPS_GN 1e-5f
#define QK_SCALE 0.08838834764831845f

// ---------------------------------------------------------------------------
// Scratch (device globals: no allocation allowed)
// ---------------------------------------------------------------------------
__device__ __nv_bfloat16 g_xnT_h[(size_t)BB*LL*CC];       // xn^T hi  [b][l][c]
__device__ __nv_bfloat16 g_xnT_l[(size_t)BB*LL*CC];
__device__ __nv_bfloat16 g_attT_h[(size_t)BB*LL*CC];      // att^T hi [b][l][c]
__device__ __nv_bfloat16 g_attT_l[(size_t)BB*LL*CC];
__device__ __nv_bfloat16 g_wq_h[(size_t)3*CC*CC], g_wq_l[(size_t)3*CC*CC];
__device__ __nv_bfloat16 g_wp_h[(size_t)CC*CC],   g_wp_l[(size_t)CC*CC];
// attention operands
__device__ __nv_bfloat16 g_qt_h[(size_t)BB*NH*LL*HD], g_qt_l[(size_t)BB*NH*LL*HD]; // [b][h][l][d]
__device__ __nv_bfloat16 g_kt_h[(size_t)BB*NH*LL*HD], g_kt_l[(size_t)BB*NH*LL*HD]; // [b][h][l][d]
__device__ __nv_bfloat16 g_v_h [(size_t)BB*NH*HD*LL], g_v_l [(size_t)BB*NH*HD*LL]; // [b][h][d][l]
__device__ float g_mean[BB*GG];
__device__ float g_rstd[BB*GG];

// ---------------------------------------------------------------------------
// helpers
// ---------------------------------------------------------------------------
__device__ __forceinline__ uint32_t smem_u32(const void* p) {
    uint32_t a;
    asm("{ .reg .u64 t; cvta.to.shared.u64 t, %1; cvt.u32.u64 %0, t; }" : "=r"(a) : "l"(p));
    return a;
}
__device__ __forceinline__ void mma16816(float* c, const uint32_t* a, const uint32_t* b) {
    asm volatile(
        "mma.sync.aligned.m16n8k16.row.col.f32.bf16.bf16.f32 "
        "{%0,%1,%2,%3}, {%4,%5,%6,%7}, {%8,%9}, {%0,%1,%2,%3};"
        : "+f"(c[0]), "+f"(c[1]), "+f"(c[2]), "+f"(c[3])
        : "r"(a[0]), "r"(a[1]), "r"(a[2]), "r"(a[3]), "r"(b[0]), "r"(b[1]));
}
__device__ __forceinline__ void ldm4(uint32_t* r, uint32_t a) {
    asm volatile("ldmatrix.sync.aligned.m8n8.x4.shared.b16 {%0,%1,%2,%3}, [%4];"
        : "=r"(r[0]), "=r"(r[1]), "=r"(r[2]), "=r"(r[3]) : "r"(a));
}
__device__ __forceinline__ void split2(float a, float b, uint32_t& hi, uint32_t& lo) {
    __nv_bfloat16 ha = __float2bfloat16(a), hb = __float2bfloat16(b);
    float ra = a - __bfloat162float(ha), rb = b - __bfloat162float(hb);
    __nv_bfloat162 th(ha, hb), tl(__float2bfloat16(ra), __float2bfloat16(rb));
    hi = *(uint32_t*)&th; lo = *(uint32_t*)&tl;
}
__device__ __forceinline__ void cp16(uint32_t s, const void* g) {
    asm volatile("cp.async.cg.shared.global [%0], [%1], 16;" :: "r"(s), "l"(g) : "memory");
}
#define CP_COMMIT() asm volatile("cp.async.commit_group;" ::: "memory")
#define CP_WAIT0()  asm volatile("cp.async.wait_group 0;" ::: "memory")

// ---------------------------------------------------------------------------
// GroupNorm statistics
// ---------------------------------------------------------------------------
__global__ void __launch_bounds__(256) gn_stats_kernel(const float* __restrict__ x) {
    int bg = blockIdx.x;
    int b = bg / GG, g = bg % GG;
    const float4* p = (const float4*)(x + ((size_t)b*CC + (size_t)g*CPG) * LL);
    const int n4 = CPG * LL / 4;
    float s = 0.f, sq = 0.f;
    for (int i = threadIdx.x; i < n4; i += 256) {
        float4 v = p[i];
        s  += v.x + v.y + v.z + v.w;
        sq += v.x*v.x + v.y*v.y + v.z*v.z + v.w*v.w;
    }
    __shared__ float ss[256], sq_s[256];
    ss[threadIdx.x] = s; sq_s[threadIdx.x] = sq;
    __syncthreads();
    for (int o = 128; o > 0; o >>= 1) {
        if (threadIdx.x < o) { ss[threadIdx.x] += ss[threadIdx.x+o]; sq_s[threadIdx.x] += sq_s[threadIdx.x+o]; }
        __syncthreads();
    }
    if (threadIdx.x == 0) {
        const float invN = 1.0f / (float)(CPG * LL);
        float mean = ss[0] * invN;
        float var  = sq_s[0] * invN - mean * mean;
        g_mean[bg] = mean;
        g_rstd[bg] = rsqrtf(var + EPS_GN);
    }
}

// ---------------------------------------------------------------------------
// GroupNorm apply + transpose + bf16 split: x[b][c][l] -> xnT_{h,l}[b][l][c]
// ---------------------------------------------------------------------------
__global__ void __launch_bounds__(256) gn_norm_t_kernel(const float* __restrict__ x,
                                                        const float* __restrict__ gamma,
                                                        const float* __restrict__ beta) {
    const int b  = blockIdx.z;
    const int c0 = blockIdx.y * 64;
    const int l0 = blockIdx.x * 64;
    const int gidx = b * GG + c0 / CPG;
    const float mean = g_mean[gidx], rstd = g_rstd[gidx];

    __shared__ float t[64][65];
    for (int idx = threadIdx.x; idx < 1024; idx += 256) {
        int i  = idx >> 4;
        int j4 = (idx & 15) * 4;
        int c = c0 + i;
        float ga = gamma[c] * rstd;
        float be = beta[c] - mean * ga;
        float4 v = *(const float4*)(x + ((size_t)b*CC + c)*LL + l0 + j4);
        t[j4+0][i] = v.x*ga + be; t[j4+1][i] = v.y*ga + be;
        t[j4+2][i] = v.z*ga + be; t[j4+3][i] = v.w*ga + be;
    }
    __syncthreads();
    for (int idx = threadIdx.x; idx < 1024; idx += 256) {
        int l  = idx >> 4;
        int cq = (idx & 15) * 4;
        __nv_bfloat16 h[4], lo[4];
        #pragma unroll
        for (int q = 0; q < 4; q++) {
            float v = t[l][cq + q];
            h[q]  = __float2bfloat16(v);
            lo[q] = __float2bfloat16(v - __bfloat162float(h[q]));
        }
        size_t o = ((size_t)b*LL + l0 + l) * CC + c0 + cq;
        *(uint2*)(g_xnT_h + o) = *(uint2*)h;
        *(uint2*)(g_xnT_l + o) = *(uint2*)lo;
    }
}

// ---------------------------------------------------------------------------
// Weight fp32 -> bf16 hi/lo split
// ---------------------------------------------------------------------------
__global__ void __launch_bounds__(256) split_kernel(const float* __restrict__ src,
                                                    __nv_bfloat16* __restrict__ hi,
                                                    __nv_bfloat16* __restrict__ lo, int n) {
    int i = blockIdx.x * 256 + threadIdx.x;
    if (i < n) {
        float v = src[i];
        __nv_bfloat16 h = __float2bfloat16(v);
        hi[i] = h;
        lo[i] = __float2bfloat16(v - __bfloat162float(h));
    }
}

// ---------------------------------------------------------------------------
// Fused QKV GEMM (mma.sync, cp.async, ldmatrix) with conversion epilogue:
//   tile role by blockIdx.y: 0-3 Q(head y), 4-7 K(head y-4), 8-11 V(head y-8)
//   Q/K: smem-transposed, split to [b][h][l][d] hi/lo (Q scaled by QK_SCALE)
//   V:   direct split to [b][h][d][l] hi/lo
// ---------------------------------------------------------------------------
#define TILE_B 10240
#define STAGE_B 40960
__global__ void __launch_bounds__(256) gemm_qkv_kernel(
        const __nv_bfloat16* __restrict__ Ah, const __nv_bfloat16* __restrict__ Al,
        const __nv_bfloat16* __restrict__ Bh_all, const __nv_bfloat16* __restrict__ Bl_all,
        const float* __restrict__ bias) {
    extern __shared__ char smc[];
    const uint32_t sbase = smem_u32(smc);
    const int tid = threadIdx.x;
    const int wid = tid >> 5;
    const int lane = tid & 31;
    const int g  = lane >> 2;
    const int tg = lane & 3;
    const int wm = wid >> 2;
    const int wn = wid & 3;
    const int b  = blockIdx.z;
    const int m0 = blockIdx.y * 128;
    const int n0 = blockIdx.x * 128;
    const int K  = CC;

    const __nv_bfloat16* Bh = Bh_all + (size_t)b * LL * CC;
    const __nv_bfloat16* Bl = Bl_all + (size_t)b * LL * CC;

    auto load_chunk = [&](int k0, int stage) {
        uint32_t st = sbase + stage * STAGE_B;
        #pragma unroll
        for (int i = 0; i < 8; i++) {
            int idx = tid + i * 256;
            int t = idx >> 9;
            int r = (idx >> 2) & 127;
            int u = idx & 3;
            const __nv_bfloat16* src;
            if (t == 0)      src = Ah + (size_t)(m0 + r) * K + k0 + u * 8;
            else if (t == 1) src = Al + (size_t)(m0 + r) * K + k0 + u * 8;
            else if (t == 2) src = Bh + (size_t)(n0 + r) * K + k0 + u * 8;
            else             src = Bl + (size_t)(n0 + r) * K + k0 + u * 8;
            cp16(st + t * TILE_B + r * 80 + u * 16, src);
        }
    };

    const uint32_t aOff = (uint32_t)(wm * 64 + (lane & 15)) * 80 + ((lane >> 4) << 4);
    const uint32_t bOff = (uint32_t)(wn * 32 + (lane & 7) + ((lane >> 4) << 3)) * 80
                        + (((lane >> 3) & 1) << 4);

    float acc[4][4][4];
    #pragma unroll
    for (int i = 0; i < 4; i++)
        #pragma unroll
        for (int j = 0; j < 4; j++)
            #pragma unroll
            for (int q = 0; q < 4; q++) acc[i][j][q] = 0.f;

    load_chunk(0, 0);
    CP_COMMIT();

    const int NCH = K / 32;
    for (int c = 0; c < NCH; c++) {
        CP_WAIT0();
        __syncthreads();
        if (c + 1 < NCH) { load_chunk((c + 1) * 32, (c + 1) & 1); CP_COMMIT(); }

        const uint32_t st = sbase + (c & 1) * STAGE_B;
        #pragma unroll
        for (int kk = 0; kk < 2; kk++) {
            const uint32_t kb = kk * 32;
            uint32_t bfh[2][4], bfl[2][4];
            #pragma unroll
            for (int p = 0; p < 2; p++) {
                ldm4(bfh[p], st + 2 * TILE_B + bOff + p * 16 * 80 + kb);
                ldm4(bfl[p], st + 3 * TILE_B + bOff + p * 16 * 80 + kb);
            }
            #pragma unroll
            for (int mt = 0; mt < 4; mt++) {
                uint32_t ah[4], al[4];
                ldm4(ah, st + aOff + mt * 16 * 80 + kb);
                ldm4(al, st + TILE_B + aOff + mt * 16 * 80 + kb);
                #pragma unroll
                for (int nt = 0; nt < 4; nt++) {
                    const uint32_t* bh = bfh[nt >> 1] + (nt & 1) * 2;
                    const uint32_t* bl = bfl[nt >> 1] + (nt & 1) * 2;
                    mma16816(acc[mt][nt], ah, bh);
                    mma16816(acc[mt][nt], al, bh);
                    mma16816(acc[mt][nt], ah, bl);
                }
            }
        }
        __syncthreads();
    }

    // ---- conversion epilogue ----
    const int role = blockIdx.y >> 2;       // 0 q, 1 k, 2 v
    const int h    = blockIdx.y & 3;
    const float scale = (role == 0) ? QK_SCALE : 1.f;

    if (role == 2) {
        // V: direct hi/lo store, [b][h][d(=row)][l]
        #pragma unroll
        for (int mt = 0; mt < 4; mt++) {
            int d0 = wm * 64 + mt * 16 + g;
            int d1 = d0 + 8;
            float bv0 = bias[m0 + d0], bv1 = bias[m0 + d1];
            #pragma unroll
            for (int nt = 0; nt < 4; nt++) {
                int col = n0 + wn * 32 + nt * 8 + tg * 2;
                uint32_t hi, lo;
                size_t o0 = ((size_t)(b * NH + h) * HD + d0) * LL + col;
                split2(acc[mt][nt][0] + bv0, acc[mt][nt][1] + bv0, hi, lo);
                *(uint32_t*)(g_v_h + o0) = hi;
                *(uint32_t*)(g_v_l + o0) = lo;
                size_t o1 = ((size_t)(b * NH + h) * HD + d1) * LL + col;
                split2(acc[mt][nt][2] + bv1, acc[mt][nt][3] + bv1, hi, lo);
                *(uint32_t*)(g_v_h + o1) = hi;
                *(uint32_t*)(g_v_l + o1) = lo;
            }
        }
        return;
    }

    // Q/K: transpose through smem (128 l-rows x 132-float stride), then split
    float* ts = (float*)smc;
    #pragma unroll
    for (int mt = 0; mt < 4; mt++) {
        int d0 = wm * 64 + mt * 16 + g;
        int d1 = d0 + 8;
        float bv0 = bias[m0 + d0], bv1 = bias[m0 + d1];
        #pragma unroll
        for (int nt = 0; nt < 4; nt++) {
            int col = wn * 32 + nt * 8 + tg * 2;
            ts[(col + 0) * 132 + d0] = (acc[mt][nt][0] + bv0) * scale;
            ts[(col + 1) * 132 + d0] = (acc[mt][nt][1] + bv0) * scale;
            ts[(col + 0) * 132 + d1] = (acc[mt][nt][2] + bv1) * scale;
            ts[(col + 1) * 132 + d1] = (acc[mt][nt][3] + bv1) * scale;
        }
    }
    __syncthreads();
    __nv_bfloat16* dh = (role == 0 ? g_qt_h : g_kt_h) + (size_t)(b * NH + h) * LL * HD;
    __nv_bfloat16* dl = (role == 0 ? g_qt_l : g_kt_l) + (size_t)(b * NH + h) * LL * HD;
    {
        int l  = tid >> 1;                  // 0..127
        int dq = (tid & 1) * 64;            // half of the d range
        #pragma unroll
        for (int i = 0; i < 16; i++) {
            float4 v = *(const float4*)&ts[l * 132 + dq + i * 4];
            __nv_bfloat16 hh[4], lo[4];
            float vv[4] = {v.x, v.y, v.z, v.w};
            #pragma unroll
            for (int q = 0; q < 4; q++) {
                hh[q] = __float2bfloat16(vv[q]);
                lo[q] = __float2bfloat16(vv[q] - __bfloat162float(hh[q]));
            }
            size_t o = (size_t)(n0 + l) * HD + dq + i * 4;
            *(uint2*)(dh + o) = *(uint2*)hh;
            *(uint2*)(dl + o) = *(uint2*)lo;
        }
    }
}

// ---------------------------------------------------------------------------
// mma.sync bf16 split GEMM (cp.async loader + ldmatrix fragments) — proj
// ---------------------------------------------------------------------------
template<bool RES>
__global__ void __launch_bounds__(256) gemm_mma_kernel(
        const __nv_bfloat16* __restrict__ Ah, const __nv_bfloat16* __restrict__ Al,
        const __nv_bfloat16* __restrict__ Bh_all, const __nv_bfloat16* __restrict__ Bl_all,
        const float* __restrict__ bias, const float* __restrict__ res,
        float* __restrict__ out, int M, int K) {
    extern __shared__ char smc[];
    const uint32_t sbase = smem_u32(smc);
    const int tid = threadIdx.x;
    const int wid = tid >> 5;
    const int lane = tid & 31;
    const int g  = lane >> 2;
    const int tg = lane & 3;
    const int wm = wid >> 2;
    const int wn = wid & 3;
    const int b  = blockIdx.z;
    const int m0 = blockIdx.y * 128;
    const int n0 = blockIdx.x * 128;

    const __nv_bfloat16* Bh = Bh_all + (size_t)b * LL * CC;
    const __nv_bfloat16* Bl = Bl_all + (size_t)b * LL * CC;

    auto load_chunk = [&](int k0, int stage) {
        uint32_t st = sbase + stage * STAGE_B;
        #pragma unroll
        for (int i = 0; i < 8; i++) {
            int idx = tid + i * 256;
            int t = idx >> 9;
            int r = (idx >> 2) & 127;
            int u = idx & 3;
            const __nv_bfloat16* src;
            if (t == 0)      src = Ah + (size_t)(m0 + r) * K + k0 + u * 8;
            else if (t == 1) src = Al + (size_t)(m0 + r) * K + k0 + u * 8;
            else if (t == 2) src = Bh + (size_t)(n0 + r) * K + k0 + u * 8;
            else             src = Bl + (size_t)(n0 + r) * K + k0 + u * 8;
            cp16(st + t * TILE_B + r * 80 + u * 16, src);
        }
    };

    const uint32_t aOff = (uint32_t)(wm * 64 + (lane & 15)) * 80 + ((lane >> 4) << 4);
    const uint32_t bOff = (uint32_t)(wn * 32 + (lane & 7) + ((lane >> 4) << 3)) * 80
                        + (((lane >> 3) & 1) << 4);

    float acc[4][4][4];
    #pragma unroll
    for (int i = 0; i < 4; i++)
        #pragma unroll
        for (int j = 0; j < 4; j++)
            #pragma unroll
            for (int q = 0; q < 4; q++) acc[i][j][q] = 0.f;

    load_chunk(0, 0);
    CP_COMMIT();

    const int NCH = K / 32;
    for (int c = 0; c < NCH; c++) {
        CP_WAIT0();
        __syncthreads();
        if (c + 1 < NCH) { load_chunk((c + 1) * 32, (c + 1) & 1); CP_COMMIT(); }

        const uint32_t st = sbase + (c & 1) * STAGE_B;
        #pragma unroll
        for (int kk = 0; kk < 2; kk++) {
            const uint32_t kb = kk * 32;
            uint32_t bfh[2][4], bfl[2][4];
            #pragma unroll
            for (int p = 0; p < 2; p++) {
                ldm4(bfh[p], st + 2 * TILE_B + bOff + p * 16 * 80 + kb);
                ldm4(bfl[p], st + 3 * TILE_B + bOff + p * 16 * 80 + kb);
            }
            #pragma unroll
            for (int mt = 0; mt < 4; mt++) {
                uint32_t ah[4], al[4];
                ldm4(ah, st + aOff + mt * 16 * 80 + kb);
                ldm4(al, st + TILE_B + aOff + mt * 16 * 80 + kb);
                #pragma unroll
                for (int nt = 0; nt < 4; nt++) {
                    const uint32_t* bh = bfh[nt >> 1] + (nt & 1) * 2;
                    const uint32_t* bl = bfl[nt >> 1] + (nt & 1) * 2;
                    mma16816(acc[mt][nt], ah, bh);
                    mma16816(acc[mt][nt], al, bh);
                    mma16816(acc[mt][nt], ah, bl);
                }
            }
        }
        __syncthreads();
    }

    #pragma unroll
    for (int mt = 0; mt < 4; mt++) {
        int r0 = m0 + wm * 64 + mt * 16 + g;
        int r1 = r0 + 8;
        float bv0 = bias[r0], bv1 = bias[r1];
        #pragma unroll
        for (int nt = 0; nt < 4; nt++) {
            int col = n0 + wn * 32 + nt * 8 + tg * 2;
            float2 o0 = make_float2(acc[mt][nt][0] + bv0, acc[mt][nt][1] + bv0);
            float2 o1 = make_float2(acc[mt][nt][2] + bv1, acc[mt][nt][3] + bv1);
            size_t off0 = ((size_t)b * M + r0) * LL + col;
            size_t off1 = ((size_t)b * M + r1) * LL + col;
            if (RES) {
                float2 q0 = *(const float2*)(res + off0);
                float2 q1 = *(const float2*)(res + off1);
                o0.x += q0.x; o0.y += q0.y; o1.x += q1.x; o1.y += q1.y;
            }
            *(float2*)(out + off0) = o0;
            *(float2*)(out + off1) = o1;
        }
    }
}

// ---------------------------------------------------------------------------
// Flash attention, register softmax + ldmatrix fragments.
// CTA = (128 q-rows, h, b), 256 threads; warp owns 16 q-rows (full k-range).
// ---------------------------------------------------------------------------
#define QSTR 272     // 256B row + 16 pad
#define VSTR 144     // 128B row + 16 pad
#define AQ_OFF 0                    // Qh 128x272=34816, Ql +34816   (69632)
#define AK_OFF 69632                // stage: 34816 (Kh 17408 + Kl)  x2
#define AV_OFF 139264               // stage: 36864 (Vh 18432 + Vl)  x2
#define ATTN_SMEM 212992

__global__ void __launch_bounds__(256) attn_mma_kernel() {
    extern __shared__ char smc[];
    const uint32_t sbase = smem_u32(smc);
    const int tid = threadIdx.x;
    const int wid = tid >> 5;
    const int lane = tid & 31;
    const int g  = lane >> 2;
    const int tg = lane & 3;
    const int lq0 = blockIdx.x * 128;
    const int h   = blockIdx.y;
    const int b   = blockIdx.z;
    const int wq0 = wid * 16;

    const size_t bh_ld = (size_t)(b * NH + h) * LL * HD;
    const __nv_bfloat16* qth = g_qt_h + bh_ld + (size_t)lq0 * HD;
    const __nv_bfloat16* qtl = g_qt_l + bh_ld + (size_t)lq0 * HD;
    const __nv_bfloat16* kth = g_kt_h + bh_ld;
    const __nv_bfloat16* ktl = g_kt_l + bh_ld;
    const __nv_bfloat16* vhp = g_v_h + bh_ld;    // [d][l]
    const __nv_bfloat16* vlp = g_v_l + bh_ld;

    auto load_kv = [&](int lk0, int s) {
        uint32_t kb = sbase + AK_OFF + s * 34816;
        uint32_t vb = sbase + AV_OFF + s * 36864;
        #pragma unroll
        for (int i = 0; i < 8; i++) {
            int idx = tid + i * 256;
            int t = idx >> 10, r = (idx >> 4) & 63, u = idx & 15;
            cp16(kb + t * 17408 + r * QSTR + u * 16,
                 (t ? ktl : kth) + (size_t)(lk0 + r) * HD + u * 8);
        }
        #pragma unroll
        for (int i = 0; i < 8; i++) {
            int idx = tid + i * 256;
            int t = idx >> 10, r = (idx >> 3) & 127, u = idx & 7;
            cp16(vb + t * 18432 + r * VSTR + u * 16,
                 (t ? vlp : vhp) + (size_t)r * LL + lk0 + u * 8);
        }
    };

    // initial group: Q (hi+lo) + K/V stage 0
    #pragma unroll
    for (int i = 0; i < 16; i++) {
        int idx = tid + i * 256;
        int t = idx >> 11, r = (idx >> 4) & 127, u = idx & 15;
        cp16(sbase + AQ_OFF + t * 34816 + r * QSTR + u * 16,
             (t ? qtl : qth) + (size_t)r * HD + u * 8);
    }
    load_kv(0, 0);
    CP_COMMIT();

    float rm0 = -1e30f, rm1 = -1e30f, rs0 = 0.f, rs1 = 0.f;
    float accO[16][4];
    #pragma unroll
    for (int i = 0; i < 16; i++)
        #pragma unroll
        for (int q = 0; q < 4; q++) accO[i][q] = 0.f;

    const uint32_t qOff = (uint32_t)(wq0 + (lane & 15)) * QSTR + ((lane >> 4) << 4);
    const uint32_t kOff = (uint32_t)((lane & 7) + ((lane >> 4) << 3)) * QSTR
                        + (((lane >> 3) & 1) << 4);
    const uint32_t vOff = (uint32_t)((lane & 7) + ((lane >> 4) << 3)) * VSTR
                        + (((lane >> 3) & 1) << 4);

    for (int it = 0; it < 16; it++) {
        const int st = it & 1;
        CP_WAIT0();
        __syncthreads();
        if (it + 1 < 16) { load_kv((it + 1) * 64, st ^ 1); CP_COMMIT(); }

        // ---- S = Q K^T (3-term split), warp tile 16q x 64k ----
        float accS[8][4];
        #pragma unroll
        for (int i = 0; i < 8; i++)
            #pragma unroll
            for (int q = 0; q < 4; q++) accS[i][q] = 0.f;
        {
            const uint32_t KhA = sbase + AK_OFF + st * 34816;
            #pragma unroll
            for (int ks = 0; ks < 8; ks++) {
                const uint32_t kb = ks * 32;
                uint32_t ah[4], al[4];
                ldm4(ah, sbase + AQ_OFF + qOff + kb);
                ldm4(al, sbase + AQ_OFF + 34816 + qOff + kb);
                #pragma unroll
                for (int p = 0; p < 4; p++) {
                    uint32_t kh4[4], kl4[4];
                    ldm4(kh4, KhA + kOff + p * 16 * QSTR + kb);
                    ldm4(kl4, KhA + 17408 + kOff + p * 16 * QSTR + kb);
                    #pragma unroll
                    for (int hf = 0; hf < 2; hf++) {
                        mma16816(accS[p*2+hf], ah, kh4 + hf*2);
                        mma16816(accS[p*2+hf], al, kh4 + hf*2);
                        mma16816(accS[p*2+hf], ah, kl4 + hf*2);
                    }
                }
            }
        }

        // ---- online softmax, fully in registers (rows g, g+8) ----
        float m0 = -1e30f, m1 = -1e30f;
        #pragma unroll
        for (int nt = 0; nt < 8; nt++) {
            m0 = fmaxf(m0, fmaxf(accS[nt][0], accS[nt][1]));
            m1 = fmaxf(m1, fmaxf(accS[nt][2], accS[nt][3]));
        }
        m0 = fmaxf(m0, __shfl_xor_sync(0xffffffff, m0, 1));
        m0 = fmaxf(m0, __shfl_xor_sync(0xffffffff, m0, 2));
        m1 = fmaxf(m1, __shfl_xor_sync(0xffffffff, m1, 1));
        m1 = fmaxf(m1, __shfl_xor_sync(0xffffffff, m1, 2));
        float nm0 = fmaxf(rm0, m0), nm1 = fmaxf(rm1, m1);
        float al0 = __expf(rm0 - nm0), al1 = __expf(rm1 - nm1);
        rm0 = nm0; rm1 = nm1;

        uint32_t pah[4][4], pal[4][4];
        float s0 = 0.f, s1 = 0.f;
        #pragma unroll
        for (int kk = 0; kk < 4; kk++) {
            float p00 = __expf(accS[2*kk][0] - nm0);
            float p01 = __expf(accS[2*kk][1] - nm0);
            float p10 = __expf(accS[2*kk][2] - nm1);
            float p11 = __expf(accS[2*kk][3] - nm1);
            float q00 = __expf(accS[2*kk+1][0] - nm0);
            float q01 = __expf(accS[2*kk+1][1] - nm0);
            float q10 = __expf(accS[2*kk+1][2] - nm1);
            float q11 = __expf(accS[2*kk+1][3] - nm1);
            s0 += p00 + p01 + q00 + q01;
            s1 += p10 + p11 + q10 + q11;
            split2(p00, p01, pah[kk][0], pal[kk][0]);
            split2(p10, p11, pah[kk][1], pal[kk][1]);
            split2(q00, q01, pah[kk][2], pal[kk][2]);
            split2(q10, q11, pah[kk][3], pal[kk][3]);
        }
        s0 += __shfl_xor_sync(0xffffffff, s0, 1);
        s0 += __shfl_xor_sync(0xffffffff, s0, 2);
        s1 += __shfl_xor_sync(0xffffffff, s1, 1);
        s1 += __shfl_xor_sync(0xffffffff, s1, 2);
        rs0 = rs0 * al0 + s0;
        rs1 = rs1 * al1 + s1;

        #pragma unroll
        for (int nt = 0; nt < 16; nt++) {
            accO[nt][0] *= al0; accO[nt][1] *= al0;
            accO[nt][2] *= al1; accO[nt][3] *= al1;
        }

        // ---- O += P V (3-term split), warp tile 16q x 128d ----
        {
            const uint32_t VhA = sbase + AV_OFF + st * 36864;
            #pragma unroll
            for (int kk = 0; kk < 4; kk++) {
                const uint32_t kb = kk * 32;
                #pragma unroll
                for (int p = 0; p < 8; p++) {
                    uint32_t vh4[4], vl4[4];
                    ldm4(vh4, VhA + vOff + p * 16 * VSTR + kb);
                    ldm4(vl4, VhA + 18432 + vOff + p * 16 * VSTR + kb);
                    #pragma unroll
                    for (int hf = 0; hf < 2; hf++) {
                        mma16816(accO[p*2+hf], pah[kk], vh4 + hf*2);
                        mma16816(accO[p*2+hf], pal[kk], vh4 + hf*2);
                        mma16816(accO[p*2+hf], pah[kk], vl4 + hf*2);
                    }
                }
            }
        }
    }

    // ---- epilogue: normalize, split, store att^T[b][l][c] hi/lo ----
    float inv0 = 1.0f / rs0, inv1 = 1.0f / rs1;
    int ra = lq0 + wq0 + g, rb = ra + 8;
    #pragma unroll
    for (int nt = 0; nt < 16; nt++) {
        int dcol = h * HD + nt * 8 + tg * 2;
        uint32_t hi, lo;
        size_t oa = ((size_t)b * LL + ra) * CC + dcol;
        split2(accO[nt][0] * inv0, accO[nt][1] * inv0, hi, lo);
        *(uint32_t*)(g_attT_h + oa) = hi;
        *(uint32_t*)(g_attT_l + oa) = lo;
        size_t ob = ((size_t)b * LL + rb) * CC + dcol;
        split2(accO[nt][2] * inv1, accO[nt][3] * inv1, hi, lo);
        *(uint32_t*)(g_attT_h + ob) = hi;
        *(uint32_t*)(g_attT_l + ob) = lo;
    }
}

// ---------------------------------------------------------------------------
extern "C" void kernel_launch(void* const* d_in, const int* in_sizes, int n_in,
                              void* d_out, int out_size) {
    const float* x      = (const float*)d_in[0];
    const float* gamma  = (const float*)d_in[1];
    const float* beta   = (const float*)d_in[2];
    const float* w_qkv  = (const float*)d_in[3];
    const float* b_qkv  = (const float*)d_in[4];
    const float* w_proj = (const float*)d_in[5];
    const float* b_proj = (const float*)d_in[6];
    float* out = (float*)d_out;

    __nv_bfloat16 *xnh, *xnl, *ath, *atl, *wqh, *wql, *wph, *wpl;
    cudaGetSymbolAddress((void**)&xnh, g_xnT_h);
    cudaGetSymbolAddress((void**)&xnl, g_xnT_l);
    cudaGetSymbolAddress((void**)&ath, g_attT_h);
    cudaGetSymbolAddress((void**)&atl, g_attT_l);
    cudaGetSymbolAddress((void**)&wqh, g_wq_h);
    cudaGetSymbolAddress((void**)&wql, g_wq_l);
    cudaGetSymbolAddress((void**)&wph, g_wp_h);
    cudaGetSymbolAddress((void**)&wpl, g_wp_l);

    // weight splits + GN
    split_kernel<<<(3*CC*CC + 255)/256, 256>>>(w_qkv, wqh, wql, 3*CC*CC);
    split_kernel<<<(CC*CC + 255)/256, 256>>>(w_proj, wph, wpl, CC*CC);
    gn_stats_kernel<<<BB*GG, 256>>>(x);
    gn_norm_t_kernel<<<dim3(LL/64, CC/64, BB), 256>>>(x, gamma, beta);

    // Fused QKV projection + conversion epilogue
    const int gemm_smem = 2 * STAGE_B;
    cudaFuncSetAttribute(gemm_qkv_kernel, cudaFuncAttributeMaxDynamicSharedMemorySize, gemm_smem);
    cudaFuncSetAttribute(gemm_mma_kernel<true>, cudaFuncAttributeMaxDynamicSharedMemorySize, gemm_smem);
    gemm_qkv_kernel<<<dim3(LL/128, 12, BB), 256, gemm_smem>>>(
        wqh, wql, xnh, xnl, b_qkv);

    // attention (mma.sync, register softmax)
    cudaFuncSetAttribute(attn_mma_kernel, cudaFuncAttributeMaxDynamicSharedMemorySize, ATTN_SMEM);
    attn_mma_kernel<<<dim3(LL/128, NH, BB), 256, ATTN_SMEM>>>();

    // Output projection + residual (mma.sync): M=512, K=512
    gemm_mma_kernel<true><<<dim3(LL/128, CC/128, BB), 256, gemm_smem>>>(
        wph, wpl, ath, atl, b_proj, x, out, CC, CC);
}

// round 13
// speedup vs baseline: 3.8797x; 1.4225x over previous
#include <cuda_runtime.h>
#include <cuda_bf16.h>
#include <cuda_fp16.h>
#include <cstdint>
#include <math.h>

#define BB 16
#define CC 512
#define LL 1024       // h*w
#define GG 8
#define CPG 64        // channels per group
#define NH 4
#define HD 128
#define EPS_GN 1e-5f
#define QK_SCALE 0.08838834764831845f

// ---------------------------------------------------------------------------
// Scratch (device globals: no allocation allowed)
// ---------------------------------------------------------------------------
__device__ __nv_bfloat16 g_xnT_h[(size_t)BB*LL*CC];       // xn^T hi  [b][l][c]
__device__ __nv_bfloat16 g_xnT_l[(size_t)BB*LL*CC];
__device__ __nv_bfloat16 g_attT_h[(size_t)BB*LL*CC];      // att^T hi [b][l][c]
__device__ __nv_bfloat16 g_attT_l[(size_t)BB*LL*CC];
__device__ __nv_bfloat16 g_wq_h[(size_t)3*CC*CC], g_wq_l[(size_t)3*CC*CC];
__device__ __nv_bfloat16 g_wp_h[(size_t)CC*CC],   g_wp_l[(size_t)CC*CC];
// attention operands (single fp16)
__device__ __half g_qt[(size_t)BB*NH*LL*HD];              // [b][h][l][d]  (scaled)
__device__ __half g_kt[(size_t)BB*NH*LL*HD];              // [b][h][l][d]
__device__ __half g_v [(size_t)BB*NH*HD*LL];              // [b][h][d][l]
__device__ float g_mean[BB*GG];
__device__ float g_rstd[BB*GG];

// ---------------------------------------------------------------------------
// helpers
// ---------------------------------------------------------------------------
__device__ __forceinline__ uint32_t smem_u32(const void* p) {
    uint32_t a;
    asm("{ .reg .u64 t; cvta.to.shared.u64 t, %1; cvt.u32.u64 %0, t; }" : "=r"(a) : "l"(p));
    return a;
}
__device__ __forceinline__ void mma16816(float* c, const uint32_t* a, const uint32_t* b) {
    asm volatile(
        "mma.sync.aligned.m16n8k16.row.col.f32.bf16.bf16.f32 "
        "{%0,%1,%2,%3}, {%4,%5,%6,%7}, {%8,%9}, {%0,%1,%2,%3};"
        : "+f"(c[0]), "+f"(c[1]), "+f"(c[2]), "+f"(c[3])
        : "r"(a[0]), "r"(a[1]), "r"(a[2]), "r"(a[3]), "r"(b[0]), "r"(b[1]));
}
__device__ __forceinline__ void mma16816h(float* c, const uint32_t* a, const uint32_t* b) {
    asm volatile(
        "mma.sync.aligned.m16n8k16.row.col.f32.f16.f16.f32 "
        "{%0,%1,%2,%3}, {%4,%5,%6,%7}, {%8,%9}, {%0,%1,%2,%3};"
        : "+f"(c[0]), "+f"(c[1]), "+f"(c[2]), "+f"(c[3])
        : "r"(a[0]), "r"(a[1]), "r"(a[2]), "r"(a[3]), "r"(b[0]), "r"(b[1]));
}
__device__ __forceinline__ void ldm4(uint32_t* r, uint32_t a) {
    asm volatile("ldmatrix.sync.aligned.m8n8.x4.shared.b16 {%0,%1,%2,%3}, [%4];"
        : "=r"(r[0]), "=r"(r[1]), "=r"(r[2]), "=r"(r[3]) : "r"(a));
}
__device__ __forceinline__ void split2(float a, float b, uint32_t& hi, uint32_t& lo) {
    __nv_bfloat16 ha = __float2bfloat16(a), hb = __float2bfloat16(b);
    float ra = a - __bfloat162float(ha), rb = b - __bfloat162float(hb);
    __nv_bfloat162 th(ha, hb), tl(__float2bfloat16(ra), __float2bfloat16(rb));
    hi = *(uint32_t*)&th; lo = *(uint32_t*)&tl;
}
__device__ __forceinline__ uint32_t packh2(float a, float b) {
    __half2 t = __floats2half2_rn(a, b);
    return *(uint32_t*)&t;
}
__device__ __forceinline__ void cp16(uint32_t s, const void* g) {
    asm volatile("cp.async.cg.shared.global [%0], [%1], 16;" :: "r"(s), "l"(g) : "memory");
}
#define CP_COMMIT() asm volatile("cp.async.commit_group;" ::: "memory")
#define CP_WAIT0()  asm volatile("cp.async.wait_group 0;" ::: "memory")

// ---------------------------------------------------------------------------
// GroupNorm statistics
// ---------------------------------------------------------------------------
__global__ void __launch_bounds__(256) gn_stats_kernel(const float* __restrict__ x) {
    int bg = blockIdx.x;
    int b = bg / GG, g = bg % GG;
    const float4* p = (const float4*)(x + ((size_t)b*CC + (size_t)g*CPG) * LL);
    const int n4 = CPG * LL / 4;
    float s = 0.f, sq = 0.f;
    for (int i = threadIdx.x; i < n4; i += 256) {
        float4 v = p[i];
        s  += v.x + v.y + v.z + v.w;
        sq += v.x*v.x + v.y*v.y + v.z*v.z + v.w*v.w;
    }
    __shared__ float ss[256], sq_s[256];
    ss[threadIdx.x] = s; sq_s[threadIdx.x] = sq;
    __syncthreads();
    for (int o = 128; o > 0; o >>= 1) {
        if (threadIdx.x < o) { ss[threadIdx.x] += ss[threadIdx.x+o]; sq_s[threadIdx.x] += sq_s[threadIdx.x+o]; }
        __syncthreads();
    }
    if (threadIdx.x == 0) {
        const float invN = 1.0f / (float)(CPG * LL);
        float mean = ss[0] * invN;
        float var  = sq_s[0] * invN - mean * mean;
        g_mean[bg] = mean;
        g_rstd[bg] = rsqrtf(var + EPS_GN);
    }
}

// ---------------------------------------------------------------------------
// GroupNorm apply + transpose + bf16 split: x[b][c][l] -> xnT_{h,l}[b][l][c]
// ---------------------------------------------------------------------------
__global__ void __launch_bounds__(256) gn_norm_t_kernel(const float* __restrict__ x,
                                                        const float* __restrict__ gamma,
                                                        const float* __restrict__ beta) {
    const int b  = blockIdx.z;
    const int c0 = blockIdx.y * 64;
    const int l0 = blockIdx.x * 64;
    const int gidx = b * GG + c0 / CPG;
    const float mean = g_mean[gidx], rstd = g_rstd[gidx];

    __shared__ float t[64][65];
    for (int idx = threadIdx.x; idx < 1024; idx += 256) {
        int i  = idx >> 4;
        int j4 = (idx & 15) * 4;
        int c = c0 + i;
        float ga = gamma[c] * rstd;
        float be = beta[c] - mean * ga;
        float4 v = *(const float4*)(x + ((size_t)b*CC + c)*LL + l0 + j4);
        t[j4+0][i] = v.x*ga + be; t[j4+1][i] = v.y*ga + be;
        t[j4+2][i] = v.z*ga + be; t[j4+3][i] = v.w*ga + be;
    }
    __syncthreads();
    for (int idx = threadIdx.x; idx < 1024; idx += 256) {
        int l  = idx >> 4;
        int cq = (idx & 15) * 4;
        __nv_bfloat16 h[4], lo[4];
        #pragma unroll
        for (int q = 0; q < 4; q++) {
            float v = t[l][cq + q];
            h[q]  = __float2bfloat16(v);
            lo[q] = __float2bfloat16(v - __bfloat162float(h[q]));
        }
        size_t o = ((size_t)b*LL + l0 + l) * CC + c0 + cq;
        *(uint2*)(g_xnT_h + o) = *(uint2*)h;
        *(uint2*)(g_xnT_l + o) = *(uint2*)lo;
    }
}

// ---------------------------------------------------------------------------
// Weight fp32 -> bf16 hi/lo split
// ---------------------------------------------------------------------------
__global__ void __launch_bounds__(256) split_kernel(const float* __restrict__ src,
                                                    __nv_bfloat16* __restrict__ hi,
                                                    __nv_bfloat16* __restrict__ lo, int n) {
    int i = blockIdx.x * 256 + threadIdx.x;
    if (i < n) {
        float v = src[i];
        __nv_bfloat16 h = __float2bfloat16(v);
        hi[i] = h;
        lo[i] = __float2bfloat16(v - __bfloat162float(h));
    }
}

// ---------------------------------------------------------------------------
// Fused QKV GEMM (mma.sync, cp.async, ldmatrix) with fp16 conversion epilogue
//   tile role by blockIdx.y: 0-3 Q(head y), 4-7 K(head y-4), 8-11 V(head y-8)
// ---------------------------------------------------------------------------
#define TILE_B 10240
#define STAGE_B 40960
__global__ void __launch_bounds__(256) gemm_qkv_kernel(
        const __nv_bfloat16* __restrict__ Ah, const __nv_bfloat16* __restrict__ Al,
        const __nv_bfloat16* __restrict__ Bh_all, const __nv_bfloat16* __restrict__ Bl_all,
        const float* __restrict__ bias) {
    extern __shared__ char smc[];
    const uint32_t sbase = smem_u32(smc);
    const int tid = threadIdx.x;
    const int wid = tid >> 5;
    const int lane = tid & 31;
    const int g  = lane >> 2;
    const int tg = lane & 3;
    const int wm = wid >> 2;
    const int wn = wid & 3;
    const int b  = blockIdx.z;
    const int m0 = blockIdx.y * 128;
    const int n0 = blockIdx.x * 128;
    const int K  = CC;

    const __nv_bfloat16* Bh = Bh_all + (size_t)b * LL * CC;
    const __nv_bfloat16* Bl = Bl_all + (size_t)b * LL * CC;

    auto load_chunk = [&](int k0, int stage) {
        uint32_t st = sbase + stage * STAGE_B;
        #pragma unroll
        for (int i = 0; i < 8; i++) {
            int idx = tid + i * 256;
            int t = idx >> 9;
            int r = (idx >> 2) & 127;
            int u = idx & 3;
            const __nv_bfloat16* src;
            if (t == 0)      src = Ah + (size_t)(m0 + r) * K + k0 + u * 8;
            else if (t == 1) src = Al + (size_t)(m0 + r) * K + k0 + u * 8;
            else if (t == 2) src = Bh + (size_t)(n0 + r) * K + k0 + u * 8;
            else             src = Bl + (size_t)(n0 + r) * K + k0 + u * 8;
            cp16(st + t * TILE_B + r * 80 + u * 16, src);
        }
    };

    const uint32_t aOff = (uint32_t)(wm * 64 + (lane & 15)) * 80 + ((lane >> 4) << 4);
    const uint32_t bOff = (uint32_t)(wn * 32 + (lane & 7) + ((lane >> 4) << 3)) * 80
                        + (((lane >> 3) & 1) << 4);

    float acc[4][4][4];
    #pragma unroll
    for (int i = 0; i < 4; i++)
        #pragma unroll
        for (int j = 0; j < 4; j++)
            #pragma unroll
            for (int q = 0; q < 4; q++) acc[i][j][q] = 0.f;

    load_chunk(0, 0);
    CP_COMMIT();

    const int NCH = K / 32;
    for (int c = 0; c < NCH; c++) {
        CP_WAIT0();
        __syncthreads();
        if (c + 1 < NCH) { load_chunk((c + 1) * 32, (c + 1) & 1); CP_COMMIT(); }

        const uint32_t st = sbase + (c & 1) * STAGE_B;
        #pragma unroll
        for (int kk = 0; kk < 2; kk++) {
            const uint32_t kb = kk * 32;
            uint32_t bfh[2][4], bfl[2][4];
            #pragma unroll
            for (int p = 0; p < 2; p++) {
                ldm4(bfh[p], st + 2 * TILE_B + bOff + p * 16 * 80 + kb);
                ldm4(bfl[p], st + 3 * TILE_B + bOff + p * 16 * 80 + kb);
            }
            #pragma unroll
            for (int mt = 0; mt < 4; mt++) {
                uint32_t ah[4], al[4];
                ldm4(ah, st + aOff + mt * 16 * 80 + kb);
                ldm4(al, st + TILE_B + aOff + mt * 16 * 80 + kb);
                #pragma unroll
                for (int nt = 0; nt < 4; nt++) {
                    const uint32_t* bh = bfh[nt >> 1] + (nt & 1) * 2;
                    const uint32_t* bl = bfl[nt >> 1] + (nt & 1) * 2;
                    mma16816(acc[mt][nt], ah, bh);
                    mma16816(acc[mt][nt], al, bh);
                    mma16816(acc[mt][nt], ah, bl);
                }
            }
        }
        __syncthreads();
    }

    // ---- fp16 conversion epilogue ----
    const int role = blockIdx.y >> 2;       // 0 q, 1 k, 2 v
    const int h    = blockIdx.y & 3;
    const float scale = (role == 0) ? QK_SCALE : 1.f;

    if (role == 2) {
        // V: direct fp16 store, [b][h][d(=row)][l]
        #pragma unroll
        for (int mt = 0; mt < 4; mt++) {
            int d0 = wm * 64 + mt * 16 + g;
            int d1 = d0 + 8;
            float bv0 = bias[m0 + d0], bv1 = bias[m0 + d1];
            #pragma unroll
            for (int nt = 0; nt < 4; nt++) {
                int col = n0 + wn * 32 + nt * 8 + tg * 2;
                size_t o0 = ((size_t)(b * NH + h) * HD + d0) * LL + col;
                *(uint32_t*)(g_v + o0) = packh2(acc[mt][nt][0] + bv0, acc[mt][nt][1] + bv0);
                size_t o1 = ((size_t)(b * NH + h) * HD + d1) * LL + col;
                *(uint32_t*)(g_v + o1) = packh2(acc[mt][nt][2] + bv1, acc[mt][nt][3] + bv1);
            }
        }
        return;
    }

    // Q/K: transpose through smem (128 l-rows x 132-float stride), then fp16
    float* ts = (float*)smc;
    #pragma unroll
    for (int mt = 0; mt < 4; mt++) {
        int d0 = wm * 64 + mt * 16 + g;
        int d1 = d0 + 8;
        float bv0 = bias[m0 + d0], bv1 = bias[m0 + d1];
        #pragma unroll
        for (int nt = 0; nt < 4; nt++) {
            int col = wn * 32 + nt * 8 + tg * 2;
            ts[(col + 0) * 132 + d0] = (acc[mt][nt][0] + bv0) * scale;
            ts[(col + 1) * 132 + d0] = (acc[mt][nt][1] + bv0) * scale;
            ts[(col + 0) * 132 + d1] = (acc[mt][nt][2] + bv1) * scale;
            ts[(col + 1) * 132 + d1] = (acc[mt][nt][3] + bv1) * scale;
        }
    }
    __syncthreads();
    __half* dh = (role == 0 ? g_qt : g_kt) + (size_t)(b * NH + h) * LL * HD;
    {
        int l  = tid >> 1;                  // 0..127
        int dq = (tid & 1) * 64;            // half of the d range
        #pragma unroll
        for (int i = 0; i < 8; i++) {
            float4 v0 = *(const float4*)&ts[l * 132 + dq + i * 8];
            float4 v1 = *(const float4*)&ts[l * 132 + dq + i * 8 + 4];
            uint32_t w[4];
            w[0] = packh2(v0.x, v0.y); w[1] = packh2(v0.z, v0.w);
            w[2] = packh2(v1.x, v1.y); w[3] = packh2(v1.z, v1.w);
            size_t o = (size_t)(n0 + l) * HD + dq + i * 8;
            *(uint4*)(dh + o) = *(uint4*)w;
        }
    }
}

// ---------------------------------------------------------------------------
// mma.sync bf16 split GEMM (cp.async loader + ldmatrix fragments) — proj
// ---------------------------------------------------------------------------
template<bool RES>
__global__ void __launch_bounds__(256) gemm_mma_kernel(
        const __nv_bfloat16* __restrict__ Ah, const __nv_bfloat16* __restrict__ Al,
        const __nv_bfloat16* __restrict__ Bh_all, const __nv_bfloat16* __restrict__ Bl_all,
        const float* __restrict__ bias, const float* __restrict__ res,
        float* __restrict__ out, int M, int K) {
    extern __shared__ char smc[];
    const uint32_t sbase = smem_u32(smc);
    const int tid = threadIdx.x;
    const int wid = tid >> 5;
    const int lane = tid & 31;
    const int g  = lane >> 2;
    const int tg = lane & 3;
    const int wm = wid >> 2;
    const int wn = wid & 3;
    const int b  = blockIdx.z;
    const int m0 = blockIdx.y * 128;
    const int n0 = blockIdx.x * 128;

    const __nv_bfloat16* Bh = Bh_all + (size_t)b * LL * CC;
    const __nv_bfloat16* Bl = Bl_all + (size_t)b * LL * CC;

    auto load_chunk = [&](int k0, int stage) {
        uint32_t st = sbase + stage * STAGE_B;
        #pragma unroll
        for (int i = 0; i < 8; i++) {
            int idx = tid + i * 256;
            int t = idx >> 9;
            int r = (idx >> 2) & 127;
            int u = idx & 3;
            const __nv_bfloat16* src;
            if (t == 0)      src = Ah + (size_t)(m0 + r) * K + k0 + u * 8;
            else if (t == 1) src = Al + (size_t)(m0 + r) * K + k0 + u * 8;
            else if (t == 2) src = Bh + (size_t)(n0 + r) * K + k0 + u * 8;
            else             src = Bl + (size_t)(n0 + r) * K + k0 + u * 8;
            cp16(st + t * TILE_B + r * 80 + u * 16, src);
        }
    };

    const uint32_t aOff = (uint32_t)(wm * 64 + (lane & 15)) * 80 + ((lane >> 4) << 4);
    const uint32_t bOff = (uint32_t)(wn * 32 + (lane & 7) + ((lane >> 4) << 3)) * 80
                        + (((lane >> 3) & 1) << 4);

    float acc[4][4][4];
    #pragma unroll
    for (int i = 0; i < 4; i++)
        #pragma unroll
        for (int j = 0; j < 4; j++)
            #pragma unroll
            for (int q = 0; q < 4; q++) acc[i][j][q] = 0.f;

    load_chunk(0, 0);
    CP_COMMIT();

    const int NCH = K / 32;
    for (int c = 0; c < NCH; c++) {
        CP_WAIT0();
        __syncthreads();
        if (c + 1 < NCH) { load_chunk((c + 1) * 32, (c + 1) & 1); CP_COMMIT(); }

        const uint32_t st = sbase + (c & 1) * STAGE_B;
        #pragma unroll
        for (int kk = 0; kk < 2; kk++) {
            const uint32_t kb = kk * 32;
            uint32_t bfh[2][4], bfl[2][4];
            #pragma unroll
            for (int p = 0; p < 2; p++) {
                ldm4(bfh[p], st + 2 * TILE_B + bOff + p * 16 * 80 + kb);
                ldm4(bfl[p], st + 3 * TILE_B + bOff + p * 16 * 80 + kb);
            }
            #pragma unroll
            for (int mt = 0; mt < 4; mt++) {
                uint32_t ah[4], al[4];
                ldm4(ah, st + aOff + mt * 16 * 80 + kb);
                ldm4(al, st + TILE_B + aOff + mt * 16 * 80 + kb);
                #pragma unroll
                for (int nt = 0; nt < 4; nt++) {
                    const uint32_t* bh = bfh[nt >> 1] + (nt & 1) * 2;
                    const uint32_t* bl = bfl[nt >> 1] + (nt & 1) * 2;
                    mma16816(acc[mt][nt], ah, bh);
                    mma16816(acc[mt][nt], al, bh);
                    mma16816(acc[mt][nt], ah, bl);
                }
            }
        }
        __syncthreads();
    }

    #pragma unroll
    for (int mt = 0; mt < 4; mt++) {
        int r0 = m0 + wm * 64 + mt * 16 + g;
        int r1 = r0 + 8;
        float bv0 = bias[r0], bv1 = bias[r1];
        #pragma unroll
        for (int nt = 0; nt < 4; nt++) {
            int col = n0 + wn * 32 + nt * 8 + tg * 2;
            float2 o0 = make_float2(acc[mt][nt][0] + bv0, acc[mt][nt][1] + bv0);
            float2 o1 = make_float2(acc[mt][nt][2] + bv1, acc[mt][nt][3] + bv1);
            size_t off0 = ((size_t)b * M + r0) * LL + col;
            size_t off1 = ((size_t)b * M + r1) * LL + col;
            if (RES) {
                float2 q0 = *(const float2*)(res + off0);
                float2 q1 = *(const float2*)(res + off1);
                o0.x += q0.x; o0.y += q0.y; o1.x += q1.x; o1.y += q1.y;
            }
            *(float2*)(out + off0) = o0;
            *(float2*)(out + off1) = o1;
        }
    }
}

// ---------------------------------------------------------------------------
// Flash attention, fp16 single-term MMAs, register softmax, ldmatrix.
// CTA = (128 q-rows, h, b), 256 threads; warp owns 16 q-rows (full k-range).
// ---------------------------------------------------------------------------
#define QSTR 272     // 256B row + 16 pad
#define VSTR 144     // 128B row + 16 pad
#define AQ_OFF 0                    // Q 128x272 = 34816
#define AK_OFF 34816                // stage: 17408  x2
#define AV_OFF 69632                // stage: 18432  x2
#define ATTN_SMEM 106496

__global__ void __launch_bounds__(256) attn_mma_kernel() {
    extern __shared__ char smc[];
    const uint32_t sbase = smem_u32(smc);
    const int tid = threadIdx.x;
    const int wid = tid >> 5;
    const int lane = tid & 31;
    const int g  = lane >> 2;
    const int tg = lane & 3;
    const int lq0 = blockIdx.x * 128;
    const int h   = blockIdx.y;
    const int b   = blockIdx.z;
    const int wq0 = wid * 16;

    const size_t bh_ld = (size_t)(b * NH + h) * LL * HD;
    const __half* qt = g_qt + bh_ld + (size_t)lq0 * HD;
    const __half* kt = g_kt + bh_ld;
    const __half* vp = g_v + bh_ld;              // [d][l]

    auto load_kv = [&](int lk0, int s) {
        uint32_t kb = sbase + AK_OFF + s * 17408;
        uint32_t vb = sbase + AV_OFF + s * 18432;
        #pragma unroll
        for (int i = 0; i < 4; i++) {
            int idx = tid + i * 256;                 // 0..1023
            int r = idx >> 4, u = idx & 15;
            cp16(kb + r * QSTR + u * 16, kt + (size_t)(lk0 + r) * HD + u * 8);
        }
        #pragma unroll
        for (int i = 0; i < 4; i++) {
            int idx = tid + i * 256;
            int r = idx >> 3, u = idx & 7;
            cp16(vb + r * VSTR + u * 16, vp + (size_t)r * LL + lk0 + u * 8);
        }
    };

    // initial group: Q + K/V stage 0
    #pragma unroll
    for (int i = 0; i < 8; i++) {
        int idx = tid + i * 256;                     // 0..2047
        int r = idx >> 4, u = idx & 15;
        cp16(sbase + AQ_OFF + r * QSTR + u * 16, qt + (size_t)r * HD + u * 8);
    }
    load_kv(0, 0);
    CP_COMMIT();

    float rm0 = -1e30f, rm1 = -1e30f, rs0 = 0.f, rs1 = 0.f;
    float accO[16][4];
    #pragma unroll
    for (int i = 0; i < 16; i++)
        #pragma unroll
        for (int q = 0; q < 4; q++) accO[i][q] = 0.f;

    const uint32_t qOff = (uint32_t)(wq0 + (lane & 15)) * QSTR + ((lane >> 4) << 4);
    const uint32_t kOff = (uint32_t)((lane & 7) + ((lane >> 4) << 3)) * QSTR
                        + (((lane >> 3) & 1) << 4);
    const uint32_t vOff = (uint32_t)((lane & 7) + ((lane >> 4) << 3)) * VSTR
                        + (((lane >> 3) & 1) << 4);

    for (int it = 0; it < 16; it++) {
        const int st = it & 1;
        CP_WAIT0();
        __syncthreads();
        if (it + 1 < 16) { load_kv((it + 1) * 64, st ^ 1); CP_COMMIT(); }

        // ---- S = Q K^T (fp16), warp tile 16q x 64k ----
        float accS[8][4];
        #pragma unroll
        for (int i = 0; i < 8; i++)
            #pragma unroll
            for (int q = 0; q < 4; q++) accS[i][q] = 0.f;
        {
            const uint32_t KA = sbase + AK_OFF + st * 17408;
            #pragma unroll
            for (int ks = 0; ks < 8; ks++) {
                const uint32_t kb = ks * 32;
                uint32_t a4[4];
                ldm4(a4, sbase + AQ_OFF + qOff + kb);
                #pragma unroll
                for (int p = 0; p < 4; p++) {
                    uint32_t k4[4];
                    ldm4(k4, KA + kOff + p * 16 * QSTR + kb);
                    mma16816h(accS[p*2+0], a4, k4);
                    mma16816h(accS[p*2+1], a4, k4 + 2);
                }
            }
        }

        // ---- online softmax, fully in registers (rows g, g+8) ----
        float m0 = -1e30f, m1 = -1e30f;
        #pragma unroll
        for (int nt = 0; nt < 8; nt++) {
            m0 = fmaxf(m0, fmaxf(accS[nt][0], accS[nt][1]));
            m1 = fmaxf(m1, fmaxf(accS[nt][2], accS[nt][3]));
        }
        m0 = fmaxf(m0, __shfl_xor_sync(0xffffffff, m0, 1));
        m0 = fmaxf(m0, __shfl_xor_sync(0xffffffff, m0, 2));
        m1 = fmaxf(m1, __shfl_xor_sync(0xffffffff, m1, 1));
        m1 = fmaxf(m1, __shfl_xor_sync(0xffffffff, m1, 2));
        float nm0 = fmaxf(rm0, m0), nm1 = fmaxf(rm1, m1);
        float al0 = __expf(rm0 - nm0), al1 = __expf(rm1 - nm1);
        rm0 = nm0; rm1 = nm1;

        uint32_t pa[4][4];
        float s0 = 0.f, s1 = 0.f;
        #pragma unroll
        for (int kk = 0; kk < 4; kk++) {
            float p00 = __expf(accS[2*kk][0] - nm0);
            float p01 = __expf(accS[2*kk][1] - nm0);
            float p10 = __expf(accS[2*kk][2] - nm1);
            float p11 = __expf(accS[2*kk][3] - nm1);
            float q00 = __expf(accS[2*kk+1][0] - nm0);
            float q01 = __expf(accS[2*kk+1][1] - nm0);
            float q10 = __expf(accS[2*kk+1][2] - nm1);
            float q11 = __expf(accS[2*kk+1][3] - nm1);
            s0 += p00 + p01 + q00 + q01;
            s1 += p10 + p11 + q10 + q11;
            pa[kk][0] = packh2(p00, p01);
            pa[kk][1] = packh2(p10, p11);
            pa[kk][2] = packh2(q00, q01);
            pa[kk][3] = packh2(q10, q11);
        }
        s0 += __shfl_xor_sync(0xffffffff, s0, 1);
        s0 += __shfl_xor_sync(0xffffffff, s0, 2);
        s1 += __shfl_xor_sync(0xffffffff, s1, 1);
        s1 += __shfl_xor_sync(0xffffffff, s1, 2);
        rs0 = rs0 * al0 + s0;
        rs1 = rs1 * al1 + s1;

        #pragma unroll
        for (int nt = 0; nt < 16; nt++) {
            accO[nt][0] *= al0; accO[nt][1] *= al0;
            accO[nt][2] *= al1; accO[nt][3] *= al1;
        }

        // ---- O += P V (fp16), warp tile 16q x 128d ----
        {
            const uint32_t VA = sbase + AV_OFF + st * 18432;
            #pragma unroll
            for (int kk = 0; kk < 4; kk++) {
                const uint32_t kb = kk * 32;
                #pragma unroll
                for (int p = 0; p < 8; p++) {
                    uint32_t v4[4];
                    ldm4(v4, VA + vOff + p * 16 * VSTR + kb);
                    mma16816h(accO[p*2+0], pa[kk], v4);
                    mma16816h(accO[p*2+1], pa[kk], v4 + 2);
                }
            }
        }
    }

    // ---- epilogue: normalize, split, store att^T[b][l][c] hi/lo ----
    float inv0 = 1.0f / rs0, inv1 = 1.0f / rs1;
    int ra = lq0 + wq0 + g, rb = ra + 8;
    #pragma unroll
    for (int nt = 0; nt < 16; nt++) {
        int dcol = h * HD + nt * 8 + tg * 2;
        uint32_t hi, lo;
        size_t oa = ((size_t)b * LL + ra) * CC + dcol;
        split2(accO[nt][0] * inv0, accO[nt][1] * inv0, hi, lo);
        *(uint32_t*)(g_attT_h + oa) = hi;
        *(uint32_t*)(g_attT_l + oa) = lo;
        size_t ob = ((size_t)b * LL + rb) * CC + dcol;
        split2(accO[nt][2] * inv1, accO[nt][3] * inv1, hi, lo);
        *(uint32_t*)(g_attT_h + ob) = hi;
        *(uint32_t*)(g_attT_l + ob) = lo;
    }
}

// ---------------------------------------------------------------------------
extern "C" void kernel_launch(void* const* d_in, const int* in_sizes, int n_in,
                              void* d_out, int out_size) {
    const float* x      = (const float*)d_in[0];
    const float* gamma  = (const float*)d_in[1];
    const float* beta   = (const float*)d_in[2];
    const float* w_qkv  = (const float*)d_in[3];
    const float* b_qkv  = (const float*)d_in[4];
    const float* w_proj = (const float*)d_in[5];
    const float* b_proj = (const float*)d_in[6];
    float* out = (float*)d_out;

    __nv_bfloat16 *xnh, *xnl, *ath, *atl, *wqh, *wql, *wph, *wpl;
    cudaGetSymbolAddress((void**)&xnh, g_xnT_h);
    cudaGetSymbolAddress((void**)&xnl, g_xnT_l);
    cudaGetSymbolAddress((void**)&ath, g_attT_h);
    cudaGetSymbolAddress((void**)&atl, g_attT_l);
    cudaGetSymbolAddress((void**)&wqh, g_wq_h);
    cudaGetSymbolAddress((void**)&wql, g_wq_l);
    cudaGetSymbolAddress((void**)&wph, g_wp_h);
    cudaGetSymbolAddress((void**)&wpl, g_wp_l);

    // weight splits + GN
    split_kernel<<<(3*CC*CC + 255)/256, 256>>>(w_qkv, wqh, wql, 3*CC*CC);
    split_kernel<<<(CC*CC + 255)/256, 256>>>(w_proj, wph, wpl, CC*CC);
    gn_stats_kernel<<<BB*GG, 256>>>(x);
    gn_norm_t_kernel<<<dim3(LL/64, CC/64, BB), 256>>>(x, gamma, beta);

    // Fused QKV projection + fp16 conversion epilogue
    const int gemm_smem = 2 * STAGE_B;
    cudaFuncSetAttribute(gemm_qkv_kernel, cudaFuncAttributeMaxDynamicSharedMemorySize, gemm_smem);
    cudaFuncSetAttribute(gemm_mma_kernel<true>, cudaFuncAttributeMaxDynamicSharedMemorySize, gemm_smem);
    gemm_qkv_kernel<<<dim3(LL/128, 12, BB), 256, gemm_smem>>>(
        wqh, wql, xnh, xnl, b_qkv);

    // attention (fp16 mma.sync, register softmax)
    cudaFuncSetAttribute(attn_mma_kernel, cudaFuncAttributeMaxDynamicSharedMemorySize, ATTN_SMEM);
    attn_mma_kernel<<<dim3(LL/128, NH, BB), 256, ATTN_SMEM>>>();

    // Output projection + residual (mma.sync): M=512, K=512
    gemm_mma_kernel<true><<<dim3(LL/128, CC/128, BB), 256, gemm_smem>>>(
        wph, wpl, ath, atl, b_proj, x, out, CC, CC);
}

// round 16
// speedup vs baseline: 6.2587x; 1.6132x over previous
#include <cuda_runtime.h>
#include <cuda_bf16.h>
#include <cuda_fp16.h>
#include <cstdint>
#include <math.h>

#define BB 16
#define CC 512
#define LL 1024       // h*w
#define GG 8
#define CPG 64        // channels per group
#define NH 4
#define HD 128
#define EPS_GN 1e-5f
#define QK_SCALE 0.08838834764831845f

// ---------------------------------------------------------------------------
// Scratch (device globals: no allocation allowed) — all fp16 single plane
// ---------------------------------------------------------------------------
__device__ __half g_xnT [(size_t)BB*LL*CC];               // xn^T  [b][l][c]
__device__ __half g_attT[(size_t)BB*LL*CC];               // att^T [b][l][c]
__device__ __half g_wq[(size_t)3*CC*CC];
__device__ __half g_wp[(size_t)CC*CC];
__device__ __half g_qt[(size_t)BB*NH*LL*HD];              // [b][h][l][d] (scaled)
__device__ __half g_kt[(size_t)BB*NH*LL*HD];              // [b][h][l][d]
__device__ __half g_v [(size_t)BB*NH*HD*LL];              // [b][h][d][l]
__device__ float g_mean[BB*GG];
__device__ float g_rstd[BB*GG];

// ---------------------------------------------------------------------------
// helpers
// ---------------------------------------------------------------------------
__device__ __forceinline__ uint32_t smem_u32(const void* p) {
    uint32_t a;
    asm("{ .reg .u64 t; cvta.to.shared.u64 t, %1; cvt.u32.u64 %0, t; }" : "=r"(a) : "l"(p));
    return a;
}
__device__ __forceinline__ void mma16816h(float* c, const uint32_t* a, const uint32_t* b) {
    asm volatile(
        "mma.sync.aligned.m16n8k16.row.col.f32.f16.f16.f32 "
        "{%0,%1,%2,%3}, {%4,%5,%6,%7}, {%8,%9}, {%0,%1,%2,%3};"
        : "+f"(c[0]), "+f"(c[1]), "+f"(c[2]), "+f"(c[3])
        : "r"(a[0]), "r"(a[1]), "r"(a[2]), "r"(a[3]), "r"(b[0]), "r"(b[1]));
}
__device__ __forceinline__ void ldm4(uint32_t* r, uint32_t a) {
    asm volatile("ldmatrix.sync.aligned.m8n8.x4.shared.b16 {%0,%1,%2,%3}, [%4];"
        : "=r"(r[0]), "=r"(r[1]), "=r"(r[2]), "=r"(r[3]) : "r"(a));
}
__device__ __forceinline__ uint32_t packh2(float a, float b) {
    __half2 t = __floats2half2_rn(a, b);
    return *(uint32_t*)&t;
}
__device__ __forceinline__ void cp16(uint32_t s, const void* g) {
    asm volatile("cp.async.cg.shared.global [%0], [%1], 16;" :: "r"(s), "l"(g) : "memory");
}
#define CP_COMMIT() asm volatile("cp.async.commit_group;" ::: "memory")
#define CP_WAIT0()  asm volatile("cp.async.wait_group 0;" ::: "memory")

// ---------------------------------------------------------------------------
// GroupNorm statistics
// ---------------------------------------------------------------------------
__global__ void __launch_bounds__(256) gn_stats_kernel(const float* __restrict__ x) {
    int bg = blockIdx.x;
    int b = bg / GG, g = bg % GG;
    const float4* p = (const float4*)(x + ((size_t)b*CC + (size_t)g*CPG) * LL);
    const int n4 = CPG * LL / 4;
    float s = 0.f, sq = 0.f;
    for (int i = threadIdx.x; i < n4; i += 256) {
        float4 v = p[i];
        s  += v.x + v.y + v.z + v.w;
        sq += v.x*v.x + v.y*v.y + v.z*v.z + v.w*v.w;
    }
    __shared__ float ss[256], sq_s[256];
    ss[threadIdx.x] = s; sq_s[threadIdx.x] = sq;
    __syncthreads();
    for (int o = 128; o > 0; o >>= 1) {
        if (threadIdx.x < o) { ss[threadIdx.x] += ss[threadIdx.x+o]; sq_s[threadIdx.x] += sq_s[threadIdx.x+o]; }
        __syncthreads();
    }
    if (threadIdx.x == 0) {
        const float invN = 1.0f / (float)(CPG * LL);
        float mean = ss[0] * invN;
        float var  = sq_s[0] * invN - mean * mean;
        g_mean[bg] = mean;
        g_rstd[bg] = rsqrtf(var + EPS_GN);
    }
}

// ---------------------------------------------------------------------------
// GroupNorm apply + transpose + fp16: x[b][c][l] -> xnT[b][l][c]
// ---------------------------------------------------------------------------
__global__ void __launch_bounds__(256) gn_norm_t_kernel(const float* __restrict__ x,
                                                        const float* __restrict__ gamma,
                                                        const float* __restrict__ beta) {
    const int b  = blockIdx.z;
    const int c0 = blockIdx.y * 64;
    const int l0 = blockIdx.x * 64;
    const int gidx = b * GG + c0 / CPG;
    const float mean = g_mean[gidx], rstd = g_rstd[gidx];

    __shared__ float t[64][65];
    for (int idx = threadIdx.x; idx < 1024; idx += 256) {
        int i  = idx >> 4;
        int j4 = (idx & 15) * 4;
        int c = c0 + i;
        float ga = gamma[c] * rstd;
        float be = beta[c] - mean * ga;
        float4 v = *(const float4*)(x + ((size_t)b*CC + c)*LL + l0 + j4);
        t[j4+0][i] = v.x*ga + be; t[j4+1][i] = v.y*ga + be;
        t[j4+2][i] = v.z*ga + be; t[j4+3][i] = v.w*ga + be;
    }
    __syncthreads();
    for (int idx = threadIdx.x; idx < 1024; idx += 256) {
        int l  = idx >> 4;
        int cq = (idx & 15) * 4;
        uint32_t w[2];
        w[0] = packh2(t[l][cq + 0], t[l][cq + 1]);
        w[1] = packh2(t[l][cq + 2], t[l][cq + 3]);
        size_t o = ((size_t)b*LL + l0 + l) * CC + c0 + cq;
        *(uint2*)(g_xnT + o) = *(uint2*)w;
    }
}

// ---------------------------------------------------------------------------
// Weight fp32 -> fp16 convert
// ---------------------------------------------------------------------------
__global__ void __launch_bounds__(256) convert_kernel(const float* __restrict__ src,
                                                      __half* __restrict__ dst, int n) {
    int i = blockIdx.x * 256 + threadIdx.x;
    if (i < n) dst[i] = __float2half(src[i]);
}

// ---------------------------------------------------------------------------
// Fused QKV GEMM (fp16 1-term mma.sync, cp.async, ldmatrix) + conversion
//   epilogue.  role by blockIdx.y: 0-3 Q(head y), 4-7 K, 8-11 V
// ---------------------------------------------------------------------------
#define TILE_B 10240          // 128 rows x 80B (64B fp16 data + 16 pad)
#define STAGE_B 20480         // 2 tiles: A, B
__global__ void __launch_bounds__(256) gemm_qkv_kernel(
        const __half* __restrict__ A, const __half* __restrict__ B_all,
        const float* __restrict__ bias) {
    extern __shared__ char smc[];
    const uint32_t sbase = smem_u32(smc);
    const int tid = threadIdx.x;
    const int wid = tid >> 5;
    const int lane = tid & 31;
    const int g  = lane >> 2;
    const int tg = lane & 3;
    const int wm = wid >> 2;
    const int wn = wid & 3;
    const int b  = blockIdx.z;
    const int m0 = blockIdx.y * 128;
    const int n0 = blockIdx.x * 128;
    const int K  = CC;

    const __half* B = B_all + (size_t)b * LL * CC;

    auto load_chunk = [&](int k0, int stage) {
        uint32_t st = sbase + stage * STAGE_B;
        #pragma unroll
        for (int i = 0; i < 4; i++) {
            int idx = tid + i * 256;            // 0..1023
            int t = idx >> 9;                   // 0 A / 1 B
            int r = (idx >> 2) & 127;
            int u = idx & 3;
            const __half* src = (t ? B + (size_t)(n0 + r) * K
                                   : A + (size_t)(m0 + r) * K) + k0 + u * 8;
            cp16(st + t * TILE_B + r * 80 + u * 16, src);
        }
    };

    const uint32_t aOff = (uint32_t)(wm * 64 + (lane & 15)) * 80 + ((lane >> 4) << 4);
    const uint32_t bOff = (uint32_t)(wn * 32 + (lane & 7) + ((lane >> 4) << 3)) * 80
                        + (((lane >> 3) & 1) << 4);

    float acc[4][4][4];
    #pragma unroll
    for (int i = 0; i < 4; i++)
        #pragma unroll
        for (int j = 0; j < 4; j++)
            #pragma unroll
            for (int q = 0; q < 4; q++) acc[i][j][q] = 0.f;

    load_chunk(0, 0);
    CP_COMMIT();

    const int NCH = K / 32;
    for (int c = 0; c < NCH; c++) {
        CP_WAIT0();
        __syncthreads();
        if (c + 1 < NCH) { load_chunk((c + 1) * 32, (c + 1) & 1); CP_COMMIT(); }

        const uint32_t st = sbase + (c & 1) * STAGE_B;
        #pragma unroll
        for (int kk = 0; kk < 2; kk++) {
            const uint32_t kb = kk * 32;
            uint32_t bf[2][4];
            ldm4(bf[0], st + TILE_B + bOff + kb);
            ldm4(bf[1], st + TILE_B + bOff + 16 * 80 + kb);
            #pragma unroll
            for (int mt = 0; mt < 4; mt++) {
                uint32_t a4[4];
                ldm4(a4, st + aOff + mt * 16 * 80 + kb);
                #pragma unroll
                for (int nt = 0; nt < 4; nt++)
                    mma16816h(acc[mt][nt], a4, bf[nt >> 1] + (nt & 1) * 2);
            }
        }
        __syncthreads();
    }

    // ---- conversion epilogue ----
    const int role = blockIdx.y >> 2;       // 0 q, 1 k, 2 v
    const int h    = blockIdx.y & 3;
    const float scale = (role == 0) ? QK_SCALE : 1.f;

    if (role == 2) {
        // V: direct fp16 store, [b][h][d(=row)][l]
        #pragma unroll
        for (int mt = 0; mt < 4; mt++) {
            int d0 = wm * 64 + mt * 16 + g;
            int d1 = d0 + 8;
            float bv0 = bias[m0 + d0], bv1 = bias[m0 + d1];
            #pragma unroll
            for (int nt = 0; nt < 4; nt++) {
                int col = n0 + wn * 32 + nt * 8 + tg * 2;
                size_t o0 = ((size_t)(b * NH + h) * HD + d0) * LL + col;
                *(uint32_t*)(g_v + o0) = packh2(acc[mt][nt][0] + bv0, acc[mt][nt][1] + bv0);
                size_t o1 = ((size_t)(b * NH + h) * HD + d1) * LL + col;
                *(uint32_t*)(g_v + o1) = packh2(acc[mt][nt][2] + bv1, acc[mt][nt][3] + bv1);
            }
        }
        return;
    }

    // Q/K: transpose through smem (128 l-rows x 132-float stride), then fp16
    float* ts = (float*)smc;
    #pragma unroll
    for (int mt = 0; mt < 4; mt++) {
        int d0 = wm * 64 + mt * 16 + g;
        int d1 = d0 + 8;
        float bv0 = bias[m0 + d0], bv1 = bias[m0 + d1];
        #pragma unroll
        for (int nt = 0; nt < 4; nt++) {
            int col = wn * 32 + nt * 8 + tg * 2;
            ts[(col + 0) * 132 + d0] = (acc[mt][nt][0] + bv0) * scale;
            ts[(col + 1) * 132 + d0] = (acc[mt][nt][1] + bv0) * scale;
            ts[(col + 0) * 132 + d1] = (acc[mt][nt][2] + bv1) * scale;
            ts[(col + 1) * 132 + d1] = (acc[mt][nt][3] + bv1) * scale;
        }
    }
    __syncthreads();
    __half* dh = (role == 0 ? g_qt : g_kt) + (size_t)(b * NH + h) * LL * HD;
    {
        int l  = tid >> 1;                  // 0..127
        int dq = (tid & 1) * 64;
        #pragma unroll
        for (int i = 0; i < 8; i++) {
            float4 v0 = *(const float4*)&ts[l * 132 + dq + i * 8];
            float4 v1 = *(const float4*)&ts[l * 132 + dq + i * 8 + 4];
            uint32_t w[4];
            w[0] = packh2(v0.x, v0.y); w[1] = packh2(v0.z, v0.w);
            w[2] = packh2(v1.x, v1.y); w[3] = packh2(v1.z, v1.w);
            size_t o = (size_t)(n0 + l) * HD + dq + i * 8;
            *(uint4*)(dh + o) = *(uint4*)w;
        }
    }
}

// ---------------------------------------------------------------------------
// Proj GEMM (fp16 1-term) + bias + residual, fp32 out
// ---------------------------------------------------------------------------
__global__ void __launch_bounds__(256) gemm_proj_kernel(
        const __half* __restrict__ A, const __half* __restrict__ B_all,
        const float* __restrict__ bias, const float* __restrict__ res,
        float* __restrict__ out) {
    extern __shared__ char smc[];
    const uint32_t sbase = smem_u32(smc);
    const int tid = threadIdx.x;
    const int wid = tid >> 5;
    const int lane = tid & 31;
    const int g  = lane >> 2;
    const int tg = lane & 3;
    const int wm = wid >> 2;
    const int wn = wid & 3;
    const int b  = blockIdx.z;
    const int m0 = blockIdx.y * 128;
    const int n0 = blockIdx.x * 128;
    const int K  = CC;
    const int M  = CC;

    const __half* B = B_all + (size_t)b * LL * CC;

    auto load_chunk = [&](int k0, int stage) {
        uint32_t st = sbase + stage * STAGE_B;
        #pragma unroll
        for (int i = 0; i < 4; i++) {
            int idx = tid + i * 256;
            int t = idx >> 9;
            int r = (idx >> 2) & 127;
            int u = idx & 3;
            const __half* src = (t ? B + (size_t)(n0 + r) * K
                                   : A + (size_t)(m0 + r) * K) + k0 + u * 8;
            cp16(st + t * TILE_B + r * 80 + u * 16, src);
        }
    };

    const uint32_t aOff = (uint32_t)(wm * 64 + (lane & 15)) * 80 + ((lane >> 4) << 4);
    const uint32_t bOff = (uint32_t)(wn * 32 + (lane & 7) + ((lane >> 4) << 3)) * 80
                        + (((lane >> 3) & 1) << 4);

    float acc[4][4][4];
    #pragma unroll
    for (int i = 0; i < 4; i++)
        #pragma unroll
        for (int j = 0; j < 4; j++)
            #pragma unroll
            for (int q = 0; q < 4; q++) acc[i][j][q] = 0.f;

    load_chunk(0, 0);
    CP_COMMIT();

    const int NCH = K / 32;
    for (int c = 0; c < NCH; c++) {
        CP_WAIT0();
        __syncthreads();
        if (c + 1 < NCH) { load_chunk((c + 1) * 32, (c + 1) & 1); CP_COMMIT(); }

        const uint32_t st = sbase + (c & 1) * STAGE_B;
        #pragma unroll
        for (int kk = 0; kk < 2; kk++) {
            const uint32_t kb = kk * 32;
            uint32_t bf[2][4];
            ldm4(bf[0], st + TILE_B + bOff + kb);
            ldm4(bf[1], st + TILE_B + bOff + 16 * 80 + kb);
            #pragma unroll
            for (int mt = 0; mt < 4; mt++) {
                uint32_t a4[4];
                ldm4(a4, st + aOff + mt * 16 * 80 + kb);
                #pragma unroll
                for (int nt = 0; nt < 4; nt++)
                    mma16816h(acc[mt][nt], a4, bf[nt >> 1] + (nt & 1) * 2);
            }
        }
        __syncthreads();
    }

    #pragma unroll
    for (int mt = 0; mt < 4; mt++) {
        int r0 = m0 + wm * 64 + mt * 16 + g;
        int r1 = r0 + 8;
        float bv0 = bias[r0], bv1 = bias[r1];
        #pragma unroll
        for (int nt = 0; nt < 4; nt++) {
            int col = n0 + wn * 32 + nt * 8 + tg * 2;
            size_t off0 = ((size_t)b * M + r0) * LL + col;
            size_t off1 = ((size_t)b * M + r1) * LL + col;
            float2 q0 = *(const float2*)(res + off0);
            float2 q1 = *(const float2*)(res + off1);
            float2 o0 = make_float2(acc[mt][nt][0] + bv0 + q0.x, acc[mt][nt][1] + bv0 + q0.y);
            float2 o1 = make_float2(acc[mt][nt][2] + bv1 + q1.x, acc[mt][nt][3] + bv1 + q1.y);
            *(float2*)(out + off0) = o0;
            *(float2*)(out + off1) = o1;
        }
    }
}

// ---------------------------------------------------------------------------
// Flash attention, fp16 single-term MMAs, register softmax, ldmatrix.
// CTA = (128 q-rows, h, b), 256 threads; warp owns 16 q-rows (full k-range).
// ---------------------------------------------------------------------------
#define QSTR 272     // 256B row + 16 pad
#define VSTR 144     // 128B row + 16 pad
#define AQ_OFF 0                    // Q 128x272 = 34816
#define AK_OFF 34816                // stage: 17408  x2
#define AV_OFF 69632                // stage: 18432  x2
#define ATTN_SMEM 106496

__global__ void __launch_bounds__(256) attn_mma_kernel() {
    extern __shared__ char smc[];
    const uint32_t sbase = smem_u32(smc);
    const int tid = threadIdx.x;
    const int wid = tid >> 5;
    const int lane = tid & 31;
    const int g  = lane >> 2;
    const int tg = lane & 3;
    const int lq0 = blockIdx.x * 128;
    const int h   = blockIdx.y;
    const int b   = blockIdx.z;
    const int wq0 = wid * 16;

    const size_t bh_ld = (size_t)(b * NH + h) * LL * HD;
    const __half* qt = g_qt + bh_ld + (size_t)lq0 * HD;
    const __half* kt = g_kt + bh_ld;
    const __half* vp = g_v + bh_ld;              // [d][l]

    auto load_kv = [&](int lk0, int s) {
        uint32_t kb = sbase + AK_OFF + s * 17408;
        uint32_t vb = sbase + AV_OFF + s * 18432;
        #pragma unroll
        for (int i = 0; i < 4; i++) {
            int idx = tid + i * 256;                 // 0..1023
            int r = idx >> 4, u = idx & 15;
            cp16(kb + r * QSTR + u * 16, kt + (size_t)(lk0 + r) * HD + u * 8);
        }
        #pragma unroll
        for (int i = 0; i < 4; i++) {
            int idx = tid + i * 256;
            int r = idx >> 3, u = idx & 7;
            cp16(vb + r * VSTR + u * 16, vp + (size_t)r * LL + lk0 + u * 8);
        }
    };

    // initial group: Q + K/V stage 0
    #pragma unroll
    for (int i = 0; i < 8; i++) {
        int idx = tid + i * 256;                     // 0..2047
        int r = idx >> 4, u = idx & 15;
        cp16(sbase + AQ_OFF + r * QSTR + u * 16, qt + (size_t)r * HD + u * 8);
    }
    load_kv(0, 0);
    CP_COMMIT();

    float rm0 = -1e30f, rm1 = -1e30f, rs0 = 0.f, rs1 = 0.f;
    float accO[16][4];
    #pragma unroll
    for (int i = 0; i < 16; i++)
        #pragma unroll
        for (int q = 0; q < 4; q++) accO[i][q] = 0.f;

    const uint32_t qOff = (uint32_t)(wq0 + (lane & 15)) * QSTR + ((lane >> 4) << 4);
    const uint32_t kOff = (uint32_t)((lane & 7) + ((lane >> 4) << 3)) * QSTR
                        + (((lane >> 3) & 1) << 4);
    const uint32_t vOff = (uint32_t)((lane & 7) + ((lane >> 4) << 3)) * VSTR
                        + (((lane >> 3) & 1) << 4);

    for (int it = 0; it < 16; it++) {
        const int st = it & 1;
        CP_WAIT0();
        __syncthreads();
        if (it + 1 < 16) { load_kv((it + 1) * 64, st ^ 1); CP_COMMIT(); }

        // ---- S = Q K^T (fp16), warp tile 16q x 64k ----
        float accS[8][4];
        #pragma unroll
        for (int i = 0; i < 8; i++)
            #pragma unroll
            for (int q = 0; q < 4; q++) accS[i][q] = 0.f;
        {
            const uint32_t KA = sbase + AK_OFF + st * 17408;
            #pragma unroll
            for (int ks = 0; ks < 8; ks++) {
                const uint32_t kb = ks * 32;
                uint32_t a4[4];
                ldm4(a4, sbase + AQ_OFF + qOff + kb);
                #pragma unroll
                for (int p = 0; p < 4; p++) {
                    uint32_t k4[4];
                    ldm4(k4, KA + kOff + p * 16 * QSTR + kb);
                    mma16816h(accS[p*2+0], a4, k4);
                    mma16816h(accS[p*2+1], a4, k4 + 2);
                }
            }
        }

        // ---- online softmax, fully in registers (rows g, g+8) ----
        float m0 = -1e30f, m1 = -1e30f;
        #pragma unroll
        for (int nt = 0; nt < 8; nt++) {
            m0 = fmaxf(m0, fmaxf(accS[nt][0], accS[nt][1]));
            m1 = fmaxf(m1, fmaxf(accS[nt][2], accS[nt][3]));
        }
        m0 = fmaxf(m0, __shfl_xor_sync(0xffffffff, m0, 1));
        m0 = fmaxf(m0, __shfl_xor_sync(0xffffffff, m0, 2));
        m1 = fmaxf(m1, __shfl_xor_sync(0xffffffff, m1, 1));
        m1 = fmaxf(m1, __shfl_xor_sync(0xffffffff, m1, 2));
        float nm0 = fmaxf(rm0, m0), nm1 = fmaxf(rm1, m1);
        float al0 = __expf(rm0 - nm0), al1 = __expf(rm1 - nm1);
        rm0 = nm0; rm1 = nm1;

        uint32_t pa[4][4];
        float s0 = 0.f, s1 = 0.f;
        #pragma unroll
        for (int kk = 0; kk < 4; kk++) {
            float p00 = __expf(accS[2*kk][0] - nm0);
            float p01 = __expf(accS[2*kk][1] - nm0);
            float p10 = __expf(accS[2*kk][2] - nm1);
            float p11 = __expf(accS[2*kk][3] - nm1);
            float q00 = __expf(accS[2*kk+1][0] - nm0);
            float q01 = __expf(accS[2*kk+1][1] - nm0);
            float q10 = __expf(accS[2*kk+1][2] - nm1);
            float q11 = __expf(accS[2*kk+1][3] - nm1);
            s0 += p00 + p01 + q00 + q01;
            s1 += p10 + p11 + q10 + q11;
            pa[kk][0] = packh2(p00, p01);
            pa[kk][1] = packh2(p10, p11);
            pa[kk][2] = packh2(q00, q01);
            pa[kk][3] = packh2(q10, q11);
        }
        s0 += __shfl_xor_sync(0xffffffff, s0, 1);
        s0 += __shfl_xor_sync(0xffffffff, s0, 2);
        s1 += __shfl_xor_sync(0xffffffff, s1, 1);
        s1 += __shfl_xor_sync(0xffffffff, s1, 2);
        rs0 = rs0 * al0 + s0;
        rs1 = rs1 * al1 + s1;

        #pragma unroll
        for (int nt = 0; nt < 16; nt++) {
            accO[nt][0] *= al0; accO[nt][1] *= al0;
            accO[nt][2] *= al1; accO[nt][3] *= al1;
        }

        // ---- O += P V (fp16), warp tile 16q x 128d ----
        {
            const uint32_t VA = sbase + AV_OFF + st * 18432;
            #pragma unroll
            for (int kk = 0; kk < 4; kk++) {
                const uint32_t kb = kk * 32;
                #pragma unroll
                for (int p = 0; p < 8; p++) {
                    uint32_t v4[4];
                    ldm4(v4, VA + vOff + p * 16 * VSTR + kb);
                    mma16816h(accO[p*2+0], pa[kk], v4);
                    mma16816h(accO[p*2+1], pa[kk], v4 + 2);
                }
            }
        }
    }

    // ---- epilogue: normalize, store att^T[b][l][c] fp16 ----
    float inv0 = 1.0f / rs0, inv1 = 1.0f / rs1;
    int ra = lq0 + wq0 + g, rb = ra + 8;
    #pragma unroll
    for (int nt = 0; nt < 16; nt++) {
        int dcol = h * HD + nt * 8 + tg * 2;
        size_t oa = ((size_t)b * LL + ra) * CC + dcol;
        *(uint32_t*)(g_attT + oa) = packh2(accO[nt][0] * inv0, accO[nt][1] * inv0);
        size_t ob = ((size_t)b * LL + rb) * CC + dcol;
        *(uint32_t*)(g_attT + ob) = packh2(accO[nt][2] * inv1, accO[nt][3] * inv1);
    }
}

// ---------------------------------------------------------------------------
extern "C" void kernel_launch(void* const* d_in, const int* in_sizes, int n_in,
                              void* d_out, int out_size) {
    const float* x      = (const float*)d_in[0];
    const float* gamma  = (const float*)d_in[1];
    const float* beta   = (const float*)d_in[2];
    const float* w_qkv  = (const float*)d_in[3];
    const float* b_qkv  = (const float*)d_in[4];
    const float* w_proj = (const float*)d_in[5];
    const float* b_proj = (const float*)d_in[6];
    float* out = (float*)d_out;

    __half *xnT, *attT, *wq, *wp;
    cudaGetSymbolAddress((void**)&xnT, g_xnT);
    cudaGetSymbolAddress((void**)&attT, g_attT);
    cudaGetSymbolAddress((void**)&wq, g_wq);
    cudaGetSymbolAddress((void**)&wp, g_wp);

    // weight converts + GN
    convert_kernel<<<(3*CC*CC + 255)/256, 256>>>(w_qkv, wq, 3*CC*CC);
    convert_kernel<<<(CC*CC + 255)/256, 256>>>(w_proj, wp, CC*CC);
    gn_stats_kernel<<<BB*GG, 256>>>(x);
    gn_norm_t_kernel<<<dim3(LL/64, CC/64, BB), 256>>>(x, gamma, beta);

    // Fused QKV projection + conversion epilogue (needs smem for transpose)
    const int qkv_smem = 132 * 128 * 4;     // 67584 > 2*STAGE_B
    cudaFuncSetAttribute(gemm_qkv_kernel, cudaFuncAttributeMaxDynamicSharedMemorySize, qkv_smem);
    gemm_qkv_kernel<<<dim3(LL/128, 12, BB), 256, qkv_smem>>>(wq, xnT, b_qkv);

    // attention (fp16 mma.sync, register softmax)
    cudaFuncSetAttribute(attn_mma_kernel, cudaFuncAttributeMaxDynamicSharedMemorySize, ATTN_SMEM);
    attn_mma_kernel<<<dim3(LL/128, NH, BB), 256, ATTN_SMEM>>>();

    // Output projection + residual
    const int proj_smem = 2 * STAGE_B;
    cudaFuncSetAttribute(gemm_proj_kernel, cudaFuncAttributeMaxDynamicSharedMemorySize, proj_smem);
    gemm_proj_kernel<<<dim3(LL/128, CC/128, BB), 256, proj_smem>>>(
        wp, attT, b_proj, x, out);
}